// round 1
// baseline (speedup 1.0000x reference)
#include <cuda_runtime.h>

#define TOKENS 8192
#define EDIM 1024
#define NHEAD 16
#define HDIM 64
#define SEQ 2048
#define MBATCH 4
#define KDIM 3072

// scratch: Q,K,V in (m,h,s,d) layout, plus gates
__device__ float g_qkv[3ull * TOKENS * EDIM];   // 96 MB
__device__ float g_gate[3 * TOKENS * 3];

typedef unsigned long long u64;

__device__ __forceinline__ u64 pk2(float a) {
    u64 r; asm("mov.b64 %0, {%1, %1};" : "=l"(r) : "f"(a)); return r;
}
__device__ __forceinline__ void up2(u64 v, float& lo, float& hi) {
    asm("mov.b64 {%0, %1}, %2;" : "=f"(lo), "=f"(hi) : "l"(v));
}
__device__ __forceinline__ u64 ffma2(u64 a, u64 b, u64 c) {
    u64 d; asm("fma.rn.f32x2 %0, %1, %2, %3;" : "=l"(d) : "l"(a), "l"(b), "l"(c)); return d;
}
__device__ __forceinline__ u64 fmul2(u64 a, u64 b) {
    u64 d; asm("mul.rn.f32x2 %0, %1, %2;" : "=l"(d) : "l"(a), "l"(b)); return d;
}

__device__ __forceinline__ float rmax16(float v) {
    v = fmaxf(v, __shfl_xor_sync(0xffffffffu, v, 1));
    v = fmaxf(v, __shfl_xor_sync(0xffffffffu, v, 2));
    v = fmaxf(v, __shfl_xor_sync(0xffffffffu, v, 4));
    v = fmaxf(v, __shfl_xor_sync(0xffffffffu, v, 8));
    return v;
}
__device__ __forceinline__ float rsum16(float v) {
    v += __shfl_xor_sync(0xffffffffu, v, 1);
    v += __shfl_xor_sync(0xffffffffu, v, 2);
    v += __shfl_xor_sync(0xffffffffu, v, 4);
    v += __shfl_xor_sync(0xffffffffu, v, 8);
    return v;
}

// ---------------------------------------------------------------------------
// Kernel 1: gates. One block per token (128 threads); warp p computes the
// 3-way softmax gate for projection p.
// ---------------------------------------------------------------------------
__global__ void gates_kernel(const float* __restrict__ x,
                             const float* __restrict__ Wg0, const float* __restrict__ bg0,
                             const float* __restrict__ Wg1, const float* __restrict__ bg1,
                             const float* __restrict__ Wg2, const float* __restrict__ bg2)
{
    __shared__ float xs[EDIM];
    int t = blockIdx.x;
    int tid = threadIdx.x;
    const float4* xrow = (const float4*)(x + (size_t)t * EDIM);
    ((float4*)xs)[tid]       = xrow[tid];
    ((float4*)xs)[tid + 128] = xrow[tid + 128];
    __syncthreads();

    int w = tid >> 5;
    if (w < 3) {
        const float* Wg = (w == 0) ? Wg0 : (w == 1) ? Wg1 : Wg2;
        const float* bg = (w == 0) ? bg0 : (w == 1) ? bg1 : bg2;
        int lane = tid & 31;
        float a0 = 0.f, a1 = 0.f, a2 = 0.f;
        for (int e = lane; e < EDIM; e += 32) {
            float xv = xs[e];
            a0 += xv * Wg[e * 3 + 0];
            a1 += xv * Wg[e * 3 + 1];
            a2 += xv * Wg[e * 3 + 2];
        }
        #pragma unroll
        for (int o = 16; o; o >>= 1) {
            a0 += __shfl_xor_sync(0xffffffffu, a0, o);
            a1 += __shfl_xor_sync(0xffffffffu, a1, o);
            a2 += __shfl_xor_sync(0xffffffffu, a2, o);
        }
        if (lane == 0) {
            a0 += bg[0]; a1 += bg[1]; a2 += bg[2];
            float mx = fmaxf(a0, fmaxf(a1, a2));
            float e0 = __expf(a0 - mx), e1 = __expf(a1 - mx), e2 = __expf(a2 - mx);
            float inv = 1.0f / (e0 + e1 + e2);
            float* gp = g_gate + ((size_t)w * TOKENS + t) * 3;
            gp[0] = e0 * inv; gp[1] = e1 * inv; gp[2] = e2 * inv;
        }
    }
}

// ---------------------------------------------------------------------------
// Kernel 2: MoE GEMM with gate folded into A.
//   C[t,o] = sum_{k<3072} (gate[t,k>>10] * x[t,k&1023]) * W[k,o]  + gate.b
// 128x128 tile, BK=8, 256 threads, 8x8 per thread, f32x2 FMAs,
// double-buffered smem with register-staged global prefetch.
// Output stored directly in (m,h,s,d) layout.
// ---------------------------------------------------------------------------
__global__ void __launch_bounds__(256, 2) moe_gemm_kernel(
    const float* __restrict__ x,
    const float* __restrict__ Wq, const float* __restrict__ bq,
    const float* __restrict__ Wk, const float* __restrict__ bk,
    const float* __restrict__ Wv, const float* __restrict__ bv)
{
    int z = blockIdx.z;
    const float* W    = (z == 0) ? Wq : (z == 1) ? Wk : Wv;
    const float* Bv   = (z == 0) ? bq : (z == 1) ? bk : bv;
    const float* gate = g_gate + (size_t)z * TOKENS * 3;
    float* out        = g_qkv + (size_t)z * TOKENS * EDIM;

    __shared__ float As[2][8][128];
    __shared__ float Bs[2][8][128];

    int tid = threadIdx.x;
    int tx = tid & 15, ty = tid >> 4;
    int row0 = blockIdx.y * 128;
    int col0 = blockIdx.x * 128;

    // A loader: row = tid/2, 4 k-elements at aseg
    int ar = tid >> 1;
    int aseg = (tid & 1) * 4;
    const float* xrow = x + (size_t)(row0 + ar) * EDIM;
    float ag0 = gate[(row0 + ar) * 3 + 0];
    float ag1 = gate[(row0 + ar) * 3 + 1];
    float ag2 = gate[(row0 + ar) * 3 + 2];

    // B loader: row = tid/32, 4 cols at bc
    int br = tid >> 5;
    int bc = (tid & 31) * 4;
    const float* wcol = W + col0 + bc;

    float4 av, bv4;
    // preload tile 0
    av  = *(const float4*)(xrow + aseg);
    bv4 = *(const float4*)(wcol + (size_t)br * EDIM);
    {
        float g = ag0;
        As[0][aseg + 0][ar] = av.x * g;
        As[0][aseg + 1][ar] = av.y * g;
        As[0][aseg + 2][ar] = av.z * g;
        As[0][aseg + 3][ar] = av.w * g;
        *(float4*)&Bs[0][br][bc] = bv4;
    }
    __syncthreads();

    u64 acc[8][4];
    #pragma unroll
    for (int i = 0; i < 8; i++)
        #pragma unroll
        for (int j = 0; j < 4; j++) acc[i][j] = 0ull;

    const int KT = KDIM / 8;   // 384
    float g = 0.f;
    for (int kt = 0; kt < KT; kt++) {
        int cur = kt & 1;
        if (kt + 1 < KT) {
            int kb = (kt + 1) * 8;
            av  = *(const float4*)(xrow + (kb & 1023) + aseg);
            bv4 = *(const float4*)(wcol + (size_t)(kb + br) * EDIM);
            g = (kb >> 10) == 0 ? ag0 : ((kb >> 10) == 1 ? ag1 : ag2);
        }
        #pragma unroll
        for (int k = 0; k < 8; k++) {
            float4 alo = *(const float4*)&As[cur][k][ty * 8];
            float4 ahi = *(const float4*)&As[cur][k][ty * 8 + 4];
            ulonglong2 blo = *(const ulonglong2*)&Bs[cur][k][tx * 4];
            ulonglong2 bhi = *(const ulonglong2*)&Bs[cur][k][tx * 4 + 64];
            float a[8] = {alo.x, alo.y, alo.z, alo.w, ahi.x, ahi.y, ahi.z, ahi.w};
            #pragma unroll
            for (int i = 0; i < 8; i++) {
                u64 a2 = pk2(a[i]);
                acc[i][0] = ffma2(a2, blo.x, acc[i][0]);
                acc[i][1] = ffma2(a2, blo.y, acc[i][1]);
                acc[i][2] = ffma2(a2, bhi.x, acc[i][2]);
                acc[i][3] = ffma2(a2, bhi.y, acc[i][3]);
            }
        }
        if (kt + 1 < KT) {
            int nxt = cur ^ 1;
            As[nxt][aseg + 0][ar] = av.x * g;
            As[nxt][aseg + 1][ar] = av.y * g;
            As[nxt][aseg + 2][ar] = av.z * g;
            As[nxt][aseg + 3][ar] = av.w * g;
            *(float4*)&Bs[nxt][br][bc] = bv4;
        }
        __syncthreads();
    }

    // epilogue: add gate-weighted bias, store to (m,h,s,d)
    #pragma unroll
    for (int i = 0; i < 8; i++) {
        int t = row0 + ty * 8 + i;
        float g0 = gate[t * 3 + 0], g1 = gate[t * 3 + 1], g2 = gate[t * 3 + 2];
        int mb = t >> 11;
        int sr = t & 2047;
        #pragma unroll
        for (int half = 0; half < 2; half++) {
            int c = col0 + (tx << 2) + (half << 6);
            float4 b0 = *(const float4*)&Bv[c];
            float4 b1 = *(const float4*)&Bv[EDIM + c];
            float4 b2 = *(const float4*)&Bv[2 * EDIM + c];
            float v0, v1, v2, v3;
            up2(acc[i][half * 2 + 0], v0, v1);
            up2(acc[i][half * 2 + 1], v2, v3);
            v0 += g0 * b0.x + g1 * b1.x + g2 * b2.x;
            v1 += g0 * b0.y + g1 * b1.y + g2 * b2.y;
            v2 += g0 * b0.z + g1 * b1.z + g2 * b2.z;
            v3 += g0 * b0.w + g1 * b1.w + g2 * b2.w;
            int h = c >> 6, d = c & 63;
            *(float4*)&out[(((size_t)mb * NHEAD + h) * SEQ + sr) * HDIM + d] =
                make_float4(v0, v1, v2, v3);
        }
    }
}

// ---------------------------------------------------------------------------
// Kernel 3: flash attention, fp32, 64x64 tiles, f32x2 FMAs.
// One block per (head, 64-query tile). K transposed in smem for
// conflict-free column access; P stored row-major (broadcast reads).
// ---------------------------------------------------------------------------
__global__ void __launch_bounds__(256, 2) attn_kernel(float* __restrict__ out)
{
    extern __shared__ float sm[];
    float* Qs  = sm;                   // 64*64
    float* Ps  = sm + 4096;            // 64*64 (also K-raw staging)
    float* Kst = sm + 8192;            // 64*68 (transposed K, padded)
    float* Vs  = sm + 8192 + 64 * 68;  // 64*64

    int bh = blockIdx.y;               // m*16 + h
    int q0 = blockIdx.x * 64;
    const float* Q = g_qkv + (size_t)bh * SEQ * HDIM + (size_t)q0 * HDIM;
    const float* K = g_qkv + (size_t)TOKENS * EDIM + (size_t)bh * SEQ * HDIM;
    const float* V = g_qkv + 2ull * TOKENS * EDIM + (size_t)bh * SEQ * HDIM;

    int tid = threadIdx.x;
    int tx = tid & 15, ty = tid >> 4;

    #pragma unroll
    for (int ii = 0; ii < 4; ii++) {
        int fi = ii * 256 + tid;
        ((float4*)Qs)[fi] = ((const float4*)Q)[fi];
    }

    u64 o2[4][2];
    float mrow[4], lrow[4];
    #pragma unroll
    for (int i = 0; i < 4; i++) {
        o2[i][0] = 0ull; o2[i][1] = 0ull;
        mrow[i] = -1e30f; lrow[i] = 0.f;
    }

    const float sc = 0.125f;   // 1/sqrt(64)

    for (int kt = 0; kt < SEQ / 64; kt++) {
        const float* Kt = K + (size_t)kt * 64 * HDIM;
        const float* Vt = V + (size_t)kt * 64 * HDIM;
        __syncthreads();   // prior-tile Ps/Vs reads done before overwrite
        #pragma unroll
        for (int ii = 0; ii < 4; ii++) {
            int fi = ii * 256 + tid;
            ((float4*)Ps)[fi] = ((const float4*)Kt)[fi];   // K raw
            ((float4*)Vs)[fi] = ((const float4*)Vt)[fi];
        }
        __syncthreads();
        // transpose K raw -> Kst[d][k]
        {
            int r0 = (tid & 15) << 2;
            int c0 = (tid >> 4) << 2;
            float4 a0 = *(const float4*)&Ps[(r0 + 0) * 64 + c0];
            float4 a1 = *(const float4*)&Ps[(r0 + 1) * 64 + c0];
            float4 a2 = *(const float4*)&Ps[(r0 + 2) * 64 + c0];
            float4 a3 = *(const float4*)&Ps[(r0 + 3) * 64 + c0];
            *(float4*)&Kst[(c0 + 0) * 68 + r0] = make_float4(a0.x, a1.x, a2.x, a3.x);
            *(float4*)&Kst[(c0 + 1) * 68 + r0] = make_float4(a0.y, a1.y, a2.y, a3.y);
            *(float4*)&Kst[(c0 + 2) * 68 + r0] = make_float4(a0.z, a1.z, a2.z, a3.z);
            *(float4*)&Kst[(c0 + 3) * 68 + r0] = make_float4(a0.w, a1.w, a2.w, a3.w);
        }
        __syncthreads();

        // S = Q K^T : s2[i][jp] pairs over columns (4tx+2jp, 4tx+2jp+1)
        u64 s2[4][2];
        #pragma unroll
        for (int i = 0; i < 4; i++) { s2[i][0] = 0ull; s2[i][1] = 0ull; }
        #pragma unroll
        for (int d4 = 0; d4 < 16; d4++) {
            float4 q[4];
            #pragma unroll
            for (int i = 0; i < 4; i++)
                q[i] = *(const float4*)&Qs[(4 * ty + i) * 64 + d4 * 4];
            #pragma unroll
            for (int dd = 0; dd < 4; dd++) {
                ulonglong2 kk = *(const ulonglong2*)&Kst[(d4 * 4 + dd) * 68 + 4 * tx];
                #pragma unroll
                for (int i = 0; i < 4; i++) {
                    float qv = (dd == 0) ? q[i].x : (dd == 1) ? q[i].y : (dd == 2) ? q[i].z : q[i].w;
                    u64 a2 = pk2(qv);
                    s2[i][0] = ffma2(a2, kk.x, s2[i][0]);
                    s2[i][1] = ffma2(a2, kk.y, s2[i][1]);
                }
            }
        }

        // online softmax
        float p[4][4];
        #pragma unroll
        for (int i = 0; i < 4; i++) {
            float s0, s1, s2f, s3;
            up2(s2[i][0], s0, s1);
            up2(s2[i][1], s2f, s3);
            float rm = fmaxf(fmaxf(s0, s1), fmaxf(s2f, s3));
            rm = rmax16(rm) * sc;
            float mnew = fmaxf(mrow[i], rm);
            float c = __expf(mrow[i] - mnew);
            mrow[i] = mnew;
            p[i][0] = __expf(s0 * sc - mnew);
            p[i][1] = __expf(s1 * sc - mnew);
            p[i][2] = __expf(s2f * sc - mnew);
            p[i][3] = __expf(s3 * sc - mnew);
            float rs = p[i][0] + p[i][1] + p[i][2] + p[i][3];
            rs = rsum16(rs);
            lrow[i] = lrow[i] * c + rs;
            u64 c2 = pk2(c);
            o2[i][0] = fmul2(o2[i][0], c2);
            o2[i][1] = fmul2(o2[i][1], c2);
        }
        #pragma unroll
        for (int i = 0; i < 4; i++)
            *(float4*)&Ps[(4 * ty + i) * 64 + 4 * tx] =
                make_float4(p[i][0], p[i][1], p[i][2], p[i][3]);
        __syncthreads();

        // O += P V
        #pragma unroll 8
        for (int k = 0; k < 64; k++) {
            ulonglong2 v2 = *(const ulonglong2*)&Vs[k * 64 + 4 * tx];
            #pragma unroll
            for (int i = 0; i < 4; i++) {
                u64 a2 = pk2(Ps[(4 * ty + i) * 64 + k]);
                o2[i][0] = ffma2(a2, v2.x, o2[i][0]);
                o2[i][1] = ffma2(a2, v2.y, o2[i][1]);
            }
        }
    }

    int m = bh >> 4, h = bh & 15;
    #pragma unroll
    for (int i = 0; i < 4; i++) {
        float inv = 1.0f / lrow[i];
        float v0, v1, v2, v3;
        up2(o2[i][0], v0, v1);
        up2(o2[i][1], v2, v3);
        size_t off = ((size_t)m * SEQ + q0 + 4 * ty + i) * EDIM + h * HDIM + 4 * tx;
        *(float4*)&out[off] = make_float4(v0 * inv, v1 * inv, v2 * inv, v3 * inv);
    }
}

// ---------------------------------------------------------------------------
extern "C" void kernel_launch(void* const* d_in, const int* in_sizes, int n_in,
                              void* d_out, int out_size)
{
    (void)in_sizes; (void)n_in; (void)out_size;
    const float* x   = (const float*)d_in[0];
    const float* Wq  = (const float*)d_in[1];
    const float* bq  = (const float*)d_in[2];
    const float* Wgq = (const float*)d_in[3];
    const float* bgq = (const float*)d_in[4];
    const float* Wk  = (const float*)d_in[5];
    const float* bk  = (const float*)d_in[6];
    const float* Wgk = (const float*)d_in[7];
    const float* bgk = (const float*)d_in[8];
    const float* Wv  = (const float*)d_in[9];
    const float* bv  = (const float*)d_in[10];
    const float* Wgv = (const float*)d_in[11];
    const float* bgv = (const float*)d_in[12];
    float* out = (float*)d_out;

    gates_kernel<<<TOKENS, 128>>>(x, Wgq, bgq, Wgk, bgk, Wgv, bgv);

    dim3 g2(EDIM / 128, TOKENS / 128, 3);
    moe_gemm_kernel<<<g2, 256>>>(x, Wq, bq, Wk, bk, Wv, bv);

    const int attn_smem = (4096 + 4096 + 64 * 68 + 4096) * 4;   // 66560 B
    cudaFuncSetAttribute(attn_kernel, cudaFuncAttributeMaxDynamicSharedMemorySize, attn_smem);
    attn_kernel<<<dim3(SEQ / 64, MBATCH * NHEAD), 256, attn_smem>>>(out);
}

// round 3
// speedup vs baseline: 1.2049x; 1.2049x over previous
#include <cuda_runtime.h>
#include <cuda_bf16.h>
#include <cstdint>

#define TOKENS 8192
#define EDIM 1024
#define NHEAD 16
#define HDIM 64
#define SEQ 2048
#define MBATCH 4
#define KDIM 3072

// scratch
__device__ float g_qkv[3ull * TOKENS * EDIM];            // 96 MB  (m,h,s,d) QKV
__device__ float g_gate[3 * TOKENS * 3];
__device__ __nv_bfloat16 g_Ahi[3ull * TOKENS * KDIM];    // 144 MB gate-folded x, hi
__device__ __nv_bfloat16 g_Alo[3ull * TOKENS * KDIM];    // 144 MB lo
__device__ __nv_bfloat16 g_Bhi[3ull * EDIM * KDIM];      // 18 MB  W^T hi  [z][o][k]
__device__ __nv_bfloat16 g_Blo[3ull * EDIM * KDIM];      // 18 MB  W^T lo

typedef unsigned long long u64;

// ---------------- helpers ----------------
__device__ __forceinline__ uint32_t smem_u32(const void* p) {
    uint32_t a;
    asm("{ .reg .u64 t; cvta.to.shared.u64 t, %1; cvt.u32.u64 %0, t; }" : "=r"(a) : "l"(p));
    return a;
}
__device__ __forceinline__ void cp_async16(uint32_t dst, const void* src) {
    asm volatile("cp.async.cg.shared.global [%0], [%1], 16;" :: "r"(dst), "l"(src) : "memory");
}
__device__ __forceinline__ void cp_commit() {
    asm volatile("cp.async.commit_group;" ::: "memory");
}
__device__ __forceinline__ void ldsm_x4(uint32_t& r0, uint32_t& r1, uint32_t& r2, uint32_t& r3,
                                        uint32_t addr) {
    asm volatile("ldmatrix.sync.aligned.m8n8.x4.shared.b16 {%0,%1,%2,%3}, [%4];"
                 : "=r"(r0), "=r"(r1), "=r"(r2), "=r"(r3) : "r"(addr));
}
__device__ __forceinline__ void mma_bf16(float* d, const uint32_t* a, const uint32_t* b) {
    asm volatile("mma.sync.aligned.m16n8k16.row.col.f32.bf16.bf16.f32 "
                 "{%0,%1,%2,%3},{%4,%5,%6,%7},{%8,%9},{%0,%1,%2,%3};"
                 : "+f"(d[0]), "+f"(d[1]), "+f"(d[2]), "+f"(d[3])
                 : "r"(a[0]), "r"(a[1]), "r"(a[2]), "r"(a[3]), "r"(b[0]), "r"(b[1]));
}

// f32x2 helpers for attention
__device__ __forceinline__ u64 pk2(float a) {
    u64 r; asm("mov.b64 %0, {%1, %1};" : "=l"(r) : "f"(a)); return r;
}
__device__ __forceinline__ void up2(u64 v, float& lo, float& hi) {
    asm("mov.b64 {%0, %1}, %2;" : "=f"(lo), "=f"(hi) : "l"(v));
}
__device__ __forceinline__ u64 ffma2(u64 a, u64 b, u64 c) {
    u64 d; asm("fma.rn.f32x2 %0, %1, %2, %3;" : "=l"(d) : "l"(a), "l"(b), "l"(c)); return d;
}
__device__ __forceinline__ u64 fmul2(u64 a, u64 b) {
    u64 d; asm("mul.rn.f32x2 %0, %1, %2;" : "=l"(d) : "l"(a), "l"(b)); return d;
}
__device__ __forceinline__ float rmax16(float v) {
    v = fmaxf(v, __shfl_xor_sync(0xffffffffu, v, 1));
    v = fmaxf(v, __shfl_xor_sync(0xffffffffu, v, 2));
    v = fmaxf(v, __shfl_xor_sync(0xffffffffu, v, 4));
    v = fmaxf(v, __shfl_xor_sync(0xffffffffu, v, 8));
    return v;
}
__device__ __forceinline__ float rsum16(float v) {
    v += __shfl_xor_sync(0xffffffffu, v, 1);
    v += __shfl_xor_sync(0xffffffffu, v, 2);
    v += __shfl_xor_sync(0xffffffffu, v, 4);
    v += __shfl_xor_sync(0xffffffffu, v, 8);
    return v;
}

// ---------------------------------------------------------------------------
// Kernel 1: gates
// ---------------------------------------------------------------------------
__global__ void gates_kernel(const float* __restrict__ x,
                             const float* __restrict__ Wg0, const float* __restrict__ bg0,
                             const float* __restrict__ Wg1, const float* __restrict__ bg1,
                             const float* __restrict__ Wg2, const float* __restrict__ bg2)
{
    __shared__ float xs[EDIM];
    int t = blockIdx.x;
    int tid = threadIdx.x;
    const float4* xrow = (const float4*)(x + (size_t)t * EDIM);
    ((float4*)xs)[tid]       = xrow[tid];
    ((float4*)xs)[tid + 128] = xrow[tid + 128];
    __syncthreads();

    int w = tid >> 5;
    if (w < 3) {
        const float* Wg = (w == 0) ? Wg0 : (w == 1) ? Wg1 : Wg2;
        const float* bg = (w == 0) ? bg0 : (w == 1) ? bg1 : bg2;
        int lane = tid & 31;
        float a0 = 0.f, a1 = 0.f, a2 = 0.f;
        for (int e = lane; e < EDIM; e += 32) {
            float xv = xs[e];
            a0 += xv * Wg[e * 3 + 0];
            a1 += xv * Wg[e * 3 + 1];
            a2 += xv * Wg[e * 3 + 2];
        }
        #pragma unroll
        for (int o = 16; o; o >>= 1) {
            a0 += __shfl_xor_sync(0xffffffffu, a0, o);
            a1 += __shfl_xor_sync(0xffffffffu, a1, o);
            a2 += __shfl_xor_sync(0xffffffffu, a2, o);
        }
        if (lane == 0) {
            a0 += bg[0]; a1 += bg[1]; a2 += bg[2];
            float mx = fmaxf(a0, fmaxf(a1, a2));
            float e0 = __expf(a0 - mx), e1 = __expf(a1 - mx), e2 = __expf(a2 - mx);
            float inv = 1.0f / (e0 + e1 + e2);
            float* gp = g_gate + ((size_t)w * TOKENS + t) * 3;
            gp[0] = e0 * inv; gp[1] = e1 * inv; gp[2] = e2 * inv;
        }
    }
}

// ---------------------------------------------------------------------------
// Kernel 2a: A conversion — gate-folded x split into bf16 hi/lo.
// ---------------------------------------------------------------------------
__global__ void convertA_kernel(const float* __restrict__ x)
{
    int t = blockIdx.x;
    int e = threadIdx.x * 4;
    float4 xv = *(const float4*)(x + (size_t)t * EDIM + e);
    #pragma unroll
    for (int z = 0; z < 3; z++) {
        const float* g = g_gate + ((size_t)z * TOKENS + t) * 3;
        float g3[3] = {g[0], g[1], g[2]};
        #pragma unroll
        for (int n = 0; n < 3; n++) {
            float gv = g3[n];
            float v[4] = {xv.x * gv, xv.y * gv, xv.z * gv, xv.w * gv};
            size_t idx = ((size_t)z * TOKENS + t) * KDIM + n * EDIM + e;
            #pragma unroll
            for (int i = 0; i < 4; i++) {
                __nv_bfloat16 hi = __float2bfloat16(v[i]);
                __nv_bfloat16 lo = __float2bfloat16(v[i] - __bfloat162float(hi));
                g_Ahi[idx + i] = hi;
                g_Alo[idx + i] = lo;
            }
        }
    }
}

// ---------------------------------------------------------------------------
// Kernel 2b: W conversion — transpose to [z][o][k] and split hi/lo.
// ---------------------------------------------------------------------------
__global__ void convertW_kernel(const float* __restrict__ Wq,
                                const float* __restrict__ Wk,
                                const float* __restrict__ Wv)
{
    __shared__ float ts[32][33];
    int zn = blockIdx.z;
    int z = zn / 3, n = zn % 3;
    const float* W = ((z == 0) ? Wq : (z == 1) ? Wk : Wv) + (size_t)n * EDIM * EDIM;
    int e0 = blockIdx.y * 32, o0 = blockIdx.x * 32;
    int tx = threadIdx.x, ty = threadIdx.y;   // (32, 8)
    #pragma unroll
    for (int i = 0; i < 4; i++) {
        int e = e0 + ty + i * 8;
        ts[ty + i * 8][tx] = W[(size_t)e * EDIM + o0 + tx];
    }
    __syncthreads();
    #pragma unroll
    for (int i = 0; i < 4; i++) {
        int o = o0 + ty + i * 8;
        float v = ts[tx][ty + i * 8];
        __nv_bfloat16 hi = __float2bfloat16(v);
        __nv_bfloat16 lo = __float2bfloat16(v - __bfloat162float(hi));
        size_t idx = ((size_t)z * EDIM + o) * KDIM + n * EDIM + e0 + tx;
        g_Bhi[idx] = hi;
        g_Blo[idx] = lo;
    }
}

// ---------------------------------------------------------------------------
// Kernel 3: bf16x3 MoE GEMM via mma.sync m16n8k16 (HMMA).
// BM=128, BN=128, BK=64. 8 warps: warp_m in 0..3 (32 rows), warp_n in 0..1
// (64 cols). 2-stage cp.async double buffer. Smem rows padded to 72 bf16
// (144 B) for conflict-free ldmatrix. Epilogue fuses gate-weighted bias and
// scatters fp32 to (m,h,s,d).
// ---------------------------------------------------------------------------
#define BM 128
#define BN 128
#define BK 64
#define NSTG (KDIM / BK)           // 48
#define ROWB 144                   // padded row bytes (72 bf16)
#define MATB (128 * ROWB)          // 18432 bytes per matrix
#define STGB (4 * MATB)            // Ah, Al, Bh, Bl per stage = 73728

__global__ void __launch_bounds__(256, 1) moe_gemm_mma(
    const float* __restrict__ bq, const float* __restrict__ bk, const float* __restrict__ bv)
{
    extern __shared__ char smem[];
    const uint32_t sb = smem_u32(smem);
    const int tid = threadIdx.x;
    const int lane = tid & 31, wid = tid >> 5;
    const int warpM = wid & 3, warpN = wid >> 2;
    const int z  = blockIdx.z;
    const int n0 = blockIdx.x * BN;
    const int t0 = blockIdx.y * BM;

    const __nv_bfloat16* Ah = g_Ahi + ((size_t)z * TOKENS + t0) * KDIM;
    const __nv_bfloat16* Al = g_Alo + ((size_t)z * TOKENS + t0) * KDIM;
    const __nv_bfloat16* Bh = g_Bhi + ((size_t)z * EDIM + n0) * KDIM;
    const __nv_bfloat16* Bl = g_Blo + ((size_t)z * EDIM + n0) * KDIM;

    // loader mapping: thread covers row r = tid/2, chunks (tid&1)*4 + j (j<4)
    const int lr = tid >> 1;
    const int lc0 = (tid & 1) * 4;
    const size_t grow = (size_t)lr * KDIM;
    const uint32_t srow = (uint32_t)lr * ROWB;

    float acc[2][8][4];
    #pragma unroll
    for (int mt = 0; mt < 2; mt++)
        #pragma unroll
        for (int nt = 0; nt < 8; nt++)
            #pragma unroll
            for (int q = 0; q < 4; q++) acc[mt][nt][q] = 0.f;

    // prologue: stage 0
    {
        uint32_t stg = sb;
        #pragma unroll
        for (int j = 0; j < 4; j++) {
            int c = lc0 + j;
            uint32_t d = stg + srow + c * 16;
            size_t go = grow + c * 8;
            cp_async16(d,            Ah + go);
            cp_async16(d + MATB,     Al + go);
            cp_async16(d + 2 * MATB, Bh + go);
            cp_async16(d + 3 * MATB, Bl + go);
        }
        cp_commit();
    }

    // ldmatrix lane addressing (within a stage/matrix):
    const uint32_t a_row = (uint32_t)(warpM * 32 + (lane & 7) + ((lane >> 3) & 1) * 8);
    const uint32_t a_chk = (uint32_t)((lane >> 4) * 16);
    const uint32_t b_row = (uint32_t)(warpN * 64 + (lane & 7) + (lane >> 4) * 8);
    const uint32_t b_chk = (uint32_t)(((lane >> 3) & 1) * 16);

    for (int s = 0; s < NSTG; s++) {
        uint32_t stg = sb + (uint32_t)(s & 1) * STGB;
        if (s + 1 < NSTG) {
            uint32_t nstg = sb + (uint32_t)((s + 1) & 1) * STGB;
            size_t k0 = (size_t)(s + 1) * BK;
            #pragma unroll
            for (int j = 0; j < 4; j++) {
                int c = lc0 + j;
                uint32_t d = nstg + srow + c * 16;
                size_t go = grow + k0 + c * 8;
                cp_async16(d,            Ah + go);
                cp_async16(d + MATB,     Al + go);
                cp_async16(d + 2 * MATB, Bh + go);
                cp_async16(d + 3 * MATB, Bl + go);
            }
            cp_commit();
            asm volatile("cp.async.wait_group 1;" ::: "memory");
        } else {
            asm volatile("cp.async.wait_group 0;" ::: "memory");
        }
        __syncthreads();

        #pragma unroll
        for (int ks = 0; ks < 4; ks++) {
            uint32_t koff = (uint32_t)(ks * 32);
            uint32_t ah[2][4], al[2][4];
            #pragma unroll
            for (int mt = 0; mt < 2; mt++) {
                uint32_t aaddr = stg + (a_row + mt * 16) * ROWB + koff + a_chk;
                ldsm_x4(ah[mt][0], ah[mt][1], ah[mt][2], ah[mt][3], aaddr);
                ldsm_x4(al[mt][0], al[mt][1], al[mt][2], al[mt][3], aaddr + MATB);
            }
            uint32_t bh[8][2], bl[8][2];
            #pragma unroll
            for (int p = 0; p < 4; p++) {
                uint32_t baddr = stg + 2 * MATB + (b_row + p * 16) * ROWB + koff + b_chk;
                ldsm_x4(bh[2 * p][0], bh[2 * p][1], bh[2 * p + 1][0], bh[2 * p + 1][1], baddr);
                ldsm_x4(bl[2 * p][0], bl[2 * p][1], bl[2 * p + 1][0], bl[2 * p + 1][1], baddr + MATB);
            }
            #pragma unroll
            for (int mt = 0; mt < 2; mt++)
                #pragma unroll
                for (int nt = 0; nt < 8; nt++) {
                    mma_bf16(acc[mt][nt], ah[mt], bh[nt]);
                    mma_bf16(acc[mt][nt], ah[mt], bl[nt]);
                    mma_bf16(acc[mt][nt], al[mt], bh[nt]);
                }
        }
        __syncthreads();
    }

    // epilogue
    const float* bias = (z == 0) ? bq : (z == 1) ? bk : bv;
    float* outp = g_qkv + (size_t)z * TOKENS * EDIM;
    #pragma unroll
    for (int mt = 0; mt < 2; mt++) {
        #pragma unroll
        for (int half = 0; half < 2; half++) {
            int t = t0 + warpM * 32 + mt * 16 + (lane >> 2) + half * 8;
            const float* g = g_gate + ((size_t)z * TOKENS + t) * 3;
            float g0 = g[0], g1 = g[1], g2 = g[2];
            int mb = t >> 11, sr = t & 2047;
            #pragma unroll
            for (int nt = 0; nt < 8; nt++) {
                int o = n0 + warpN * 64 + nt * 8 + 2 * (lane & 3);
                float2 b0 = *(const float2*)&bias[o];
                float2 b1 = *(const float2*)&bias[EDIM + o];
                float2 b2 = *(const float2*)&bias[2 * EDIM + o];
                float v0 = acc[mt][nt][half * 2 + 0] + g0 * b0.x + g1 * b1.x + g2 * b2.x;
                float v1 = acc[mt][nt][half * 2 + 1] + g0 * b0.y + g1 * b1.y + g2 * b2.y;
                int h = o >> 6, d = o & 63;
                *(float2*)&outp[(((size_t)mb * NHEAD + h) * SEQ + sr) * HDIM + d] =
                    make_float2(v0, v1);
            }
        }
    }
}

// ---------------------------------------------------------------------------
// Kernel 4: flash attention, fp32 SIMT, 64x64 tiles, f32x2 FMAs
// ---------------------------------------------------------------------------
__global__ void __launch_bounds__(256, 2) attn_kernel(float* __restrict__ out)
{
    extern __shared__ float sm[];
    float* Qs  = sm;
    float* Ps  = sm + 4096;
    float* Kst = sm + 8192;
    float* Vs  = sm + 8192 + 64 * 68;

    int bh = blockIdx.y;
    int q0 = blockIdx.x * 64;
    const float* Q = g_qkv + (size_t)bh * SEQ * HDIM + (size_t)q0 * HDIM;
    const float* K = g_qkv + (size_t)TOKENS * EDIM + (size_t)bh * SEQ * HDIM;
    const float* V = g_qkv + 2ull * TOKENS * EDIM + (size_t)bh * SEQ * HDIM;

    int tid = threadIdx.x;
    int tx = tid & 15, ty = tid >> 4;

    #pragma unroll
    for (int ii = 0; ii < 4; ii++) {
        int fi = ii * 256 + tid;
        ((float4*)Qs)[fi] = ((const float4*)Q)[fi];
    }

    u64 o2[4][2];
    float mrow[4], lrow[4];
    #pragma unroll
    for (int i = 0; i < 4; i++) {
        o2[i][0] = 0ull; o2[i][1] = 0ull;
        mrow[i] = -1e30f; lrow[i] = 0.f;
    }

    const float sc = 0.125f;

    for (int kt = 0; kt < SEQ / 64; kt++) {
        const float* Kt = K + (size_t)kt * 64 * HDIM;
        const float* Vt = V + (size_t)kt * 64 * HDIM;
        __syncthreads();
        #pragma unroll
        for (int ii = 0; ii < 4; ii++) {
            int fi = ii * 256 + tid;
            ((float4*)Ps)[fi] = ((const float4*)Kt)[fi];
            ((float4*)Vs)[fi] = ((const float4*)Vt)[fi];
        }
        __syncthreads();
        {
            int r0 = (tid & 15) << 2;
            int c0 = (tid >> 4) << 2;
            float4 a0 = *(const float4*)&Ps[(r0 + 0) * 64 + c0];
            float4 a1 = *(const float4*)&Ps[(r0 + 1) * 64 + c0];
            float4 a2 = *(const float4*)&Ps[(r0 + 2) * 64 + c0];
            float4 a3 = *(const float4*)&Ps[(r0 + 3) * 64 + c0];
            *(float4*)&Kst[(c0 + 0) * 68 + r0] = make_float4(a0.x, a1.x, a2.x, a3.x);
            *(float4*)&Kst[(c0 + 1) * 68 + r0] = make_float4(a0.y, a1.y, a2.y, a3.y);
            *(float4*)&Kst[(c0 + 2) * 68 + r0] = make_float4(a0.z, a1.z, a2.z, a3.z);
            *(float4*)&Kst[(c0 + 3) * 68 + r0] = make_float4(a0.w, a1.w, a2.w, a3.w);
        }
        __syncthreads();

        u64 s2[4][2];
        #pragma unroll
        for (int i = 0; i < 4; i++) { s2[i][0] = 0ull; s2[i][1] = 0ull; }
        #pragma unroll
        for (int d4 = 0; d4 < 16; d4++) {
            float4 q[4];
            #pragma unroll
            for (int i = 0; i < 4; i++)
                q[i] = *(const float4*)&Qs[(4 * ty + i) * 64 + d4 * 4];
            #pragma unroll
            for (int dd = 0; dd < 4; dd++) {
                ulonglong2 kk = *(const ulonglong2*)&Kst[(d4 * 4 + dd) * 68 + 4 * tx];
                #pragma unroll
                for (int i = 0; i < 4; i++) {
                    float qv = (dd == 0) ? q[i].x : (dd == 1) ? q[i].y : (dd == 2) ? q[i].z : q[i].w;
                    u64 a2 = pk2(qv);
                    s2[i][0] = ffma2(a2, kk.x, s2[i][0]);
                    s2[i][1] = ffma2(a2, kk.y, s2[i][1]);
                }
            }
        }

        float p[4][4];
        #pragma unroll
        for (int i = 0; i < 4; i++) {
            float s0, s1, s2f, s3;
            up2(s2[i][0], s0, s1);
            up2(s2[i][1], s2f, s3);
            float rm = fmaxf(fmaxf(s0, s1), fmaxf(s2f, s3));
            rm = rmax16(rm) * sc;
            float mnew = fmaxf(mrow[i], rm);
            float c = __expf(mrow[i] - mnew);
            mrow[i] = mnew;
            p[i][0] = __expf(s0 * sc - mnew);
            p[i][1] = __expf(s1 * sc - mnew);
            p[i][2] = __expf(s2f * sc - mnew);
            p[i][3] = __expf(s3 * sc - mnew);
            float rs = p[i][0] + p[i][1] + p[i][2] + p[i][3];
            rs = rsum16(rs);
            lrow[i] = lrow[i] * c + rs;
            u64 c2 = pk2(c);
            o2[i][0] = fmul2(o2[i][0], c2);
            o2[i][1] = fmul2(o2[i][1], c2);
        }
        #pragma unroll
        for (int i = 0; i < 4; i++)
            *(float4*)&Ps[(4 * ty + i) * 64 + 4 * tx] =
                make_float4(p[i][0], p[i][1], p[i][2], p[i][3]);
        __syncthreads();

        #pragma unroll 8
        for (int k = 0; k < 64; k++) {
            ulonglong2 v2 = *(const ulonglong2*)&Vs[k * 64 + 4 * tx];
            #pragma unroll
            for (int i = 0; i < 4; i++) {
                u64 a2 = pk2(Ps[(4 * ty + i) * 64 + k]);
                o2[i][0] = ffma2(a2, v2.x, o2[i][0]);
                o2[i][1] = ffma2(a2, v2.y, o2[i][1]);
            }
        }
    }

    int m = bh >> 4, h = bh & 15;
    #pragma unroll
    for (int i = 0; i < 4; i++) {
        float inv = 1.0f / lrow[i];
        float v0, v1, v2, v3;
        up2(o2[i][0], v0, v1);
        up2(o2[i][1], v2, v3);
        size_t off = ((size_t)m * SEQ + q0 + 4 * ty + i) * EDIM + h * HDIM + 4 * tx;
        *(float4*)&out[off] = make_float4(v0 * inv, v1 * inv, v2 * inv, v3 * inv);
    }
}

// ---------------------------------------------------------------------------
extern "C" void kernel_launch(void* const* d_in, const int* in_sizes, int n_in,
                              void* d_out, int out_size)
{
    (void)in_sizes; (void)n_in; (void)out_size;
    const float* x   = (const float*)d_in[0];
    const float* Wq  = (const float*)d_in[1];
    const float* bq  = (const float*)d_in[2];
    const float* Wgq = (const float*)d_in[3];
    const float* bgq = (const float*)d_in[4];
    const float* Wk  = (const float*)d_in[5];
    const float* bk  = (const float*)d_in[6];
    const float* Wgk = (const float*)d_in[7];
    const float* bgk = (const float*)d_in[8];
    const float* Wv  = (const float*)d_in[9];
    const float* bv  = (const float*)d_in[10];
    const float* Wgv = (const float*)d_in[11];
    const float* bgv = (const float*)d_in[12];
    float* out = (float*)d_out;

    gates_kernel<<<TOKENS, 128>>>(x, Wgq, bgq, Wgk, bgk, Wgv, bgv);

    convertW_kernel<<<dim3(32, 32, 9), dim3(32, 8)>>>(Wq, Wk, Wv);
    convertA_kernel<<<TOKENS, 256>>>(x);

    const int gemm_smem = 2 * STGB;   // 147456
    cudaFuncSetAttribute(moe_gemm_mma, cudaFuncAttributeMaxDynamicSharedMemorySize, gemm_smem);
    moe_gemm_mma<<<dim3(EDIM / BN, TOKENS / BM, 3), 256, gemm_smem>>>(bq, bk, bv);

    const int attn_smem = (4096 + 4096 + 64 * 68 + 4096) * 4;
    cudaFuncSetAttribute(attn_kernel, cudaFuncAttributeMaxDynamicSharedMemorySize, attn_smem);
    attn_kernel<<<dim3(SEQ / 64, MBATCH * NHEAD), 256, attn_smem>>>(out);
}

// round 4
// speedup vs baseline: 1.9830x; 1.6458x over previous
#include <cuda_runtime.h>
#include <cuda_bf16.h>
#include <cstdint>

#define TOKENS 8192
#define EDIM 1024
#define NHEAD 16
#define HDIM 64
#define SEQ 2048
#define MBATCH 4
#define KDIM 3072

// scratch
__device__ float g_gate[3 * TOKENS * 3];
__device__ __nv_bfloat16 g_Ahi[3ull * TOKENS * KDIM];
__device__ __nv_bfloat16 g_Alo[3ull * TOKENS * KDIM];
__device__ __nv_bfloat16 g_Bhi[3ull * EDIM * KDIM];
__device__ __nv_bfloat16 g_Blo[3ull * EDIM * KDIM];
// QKV in (z, m*h, s, d) bf16 hi/lo
__device__ __nv_bfloat16 g_Qhi[(size_t)TOKENS * EDIM];
__device__ __nv_bfloat16 g_Qlo[(size_t)TOKENS * EDIM];
__device__ __nv_bfloat16 g_Khi[(size_t)TOKENS * EDIM];
__device__ __nv_bfloat16 g_Klo[(size_t)TOKENS * EDIM];
__device__ __nv_bfloat16 g_Vhi[(size_t)TOKENS * EDIM];
__device__ __nv_bfloat16 g_Vlo[(size_t)TOKENS * EDIM];

// ---------------- helpers ----------------
__device__ __forceinline__ uint32_t smem_u32(const void* p) {
    uint32_t a;
    asm("{ .reg .u64 t; cvta.to.shared.u64 t, %1; cvt.u32.u64 %0, t; }" : "=r"(a) : "l"(p));
    return a;
}
__device__ __forceinline__ void cp_async16(uint32_t dst, const void* src) {
    asm volatile("cp.async.cg.shared.global [%0], [%1], 16;" :: "r"(dst), "l"(src) : "memory");
}
__device__ __forceinline__ void cp_commit() {
    asm volatile("cp.async.commit_group;" ::: "memory");
}
__device__ __forceinline__ void cp_wait0() {
    asm volatile("cp.async.wait_group 0;" ::: "memory");
}
__device__ __forceinline__ void cp_wait1() {
    asm volatile("cp.async.wait_group 1;" ::: "memory");
}
__device__ __forceinline__ void ldsm_x4(uint32_t& r0, uint32_t& r1, uint32_t& r2, uint32_t& r3,
                                        uint32_t addr) {
    asm volatile("ldmatrix.sync.aligned.m8n8.x4.shared.b16 {%0,%1,%2,%3}, [%4];"
                 : "=r"(r0), "=r"(r1), "=r"(r2), "=r"(r3) : "r"(addr));
}
__device__ __forceinline__ void ldsm_x4t(uint32_t& r0, uint32_t& r1, uint32_t& r2, uint32_t& r3,
                                         uint32_t addr) {
    asm volatile("ldmatrix.sync.aligned.m8n8.x4.trans.shared.b16 {%0,%1,%2,%3}, [%4];"
                 : "=r"(r0), "=r"(r1), "=r"(r2), "=r"(r3) : "r"(addr));
}
__device__ __forceinline__ void mma_bf16(float* d, const uint32_t* a, const uint32_t* b) {
    asm volatile("mma.sync.aligned.m16n8k16.row.col.f32.bf16.bf16.f32 "
                 "{%0,%1,%2,%3},{%4,%5,%6,%7},{%8,%9},{%0,%1,%2,%3};"
                 : "+f"(d[0]), "+f"(d[1]), "+f"(d[2]), "+f"(d[3])
                 : "r"(a[0]), "r"(a[1]), "r"(a[2]), "r"(a[3]), "r"(b[0]), "r"(b[1]));
}
__device__ __forceinline__ uint32_t pack_bf16x2(float lo, float hi) {
    __nv_bfloat162 h = __float22bfloat162_rn(make_float2(lo, hi));
    return *(uint32_t*)&h;
}

// ---------------------------------------------------------------------------
// Kernel 1: gates
// ---------------------------------------------------------------------------
__global__ void gates_kernel(const float* __restrict__ x,
                             const float* __restrict__ Wg0, const float* __restrict__ bg0,
                             const float* __restrict__ Wg1, const float* __restrict__ bg1,
                             const float* __restrict__ Wg2, const float* __restrict__ bg2)
{
    __shared__ float xs[EDIM];
    int t = blockIdx.x;
    int tid = threadIdx.x;
    const float4* xrow = (const float4*)(x + (size_t)t * EDIM);
    ((float4*)xs)[tid]       = xrow[tid];
    ((float4*)xs)[tid + 128] = xrow[tid + 128];
    __syncthreads();

    int w = tid >> 5;
    if (w < 3) {
        const float* Wg = (w == 0) ? Wg0 : (w == 1) ? Wg1 : Wg2;
        const float* bg = (w == 0) ? bg0 : (w == 1) ? bg1 : bg2;
        int lane = tid & 31;
        float a0 = 0.f, a1 = 0.f, a2 = 0.f;
        for (int e = lane; e < EDIM; e += 32) {
            float xv = xs[e];
            a0 += xv * Wg[e * 3 + 0];
            a1 += xv * Wg[e * 3 + 1];
            a2 += xv * Wg[e * 3 + 2];
        }
        #pragma unroll
        for (int o = 16; o; o >>= 1) {
            a0 += __shfl_xor_sync(0xffffffffu, a0, o);
            a1 += __shfl_xor_sync(0xffffffffu, a1, o);
            a2 += __shfl_xor_sync(0xffffffffu, a2, o);
        }
        if (lane == 0) {
            a0 += bg[0]; a1 += bg[1]; a2 += bg[2];
            float mx = fmaxf(a0, fmaxf(a1, a2));
            float e0 = __expf(a0 - mx), e1 = __expf(a1 - mx), e2 = __expf(a2 - mx);
            float inv = 1.0f / (e0 + e1 + e2);
            float* gp = g_gate + ((size_t)w * TOKENS + t) * 3;
            gp[0] = e0 * inv; gp[1] = e1 * inv; gp[2] = e2 * inv;
        }
    }
}

// ---------------------------------------------------------------------------
// Kernel 2a: A conversion — gate-folded x split into bf16 hi/lo.
// ---------------------------------------------------------------------------
__global__ void convertA_kernel(const float* __restrict__ x)
{
    int t = blockIdx.x;
    int e = threadIdx.x * 4;
    float4 xv = *(const float4*)(x + (size_t)t * EDIM + e);
    #pragma unroll
    for (int z = 0; z < 3; z++) {
        const float* g = g_gate + ((size_t)z * TOKENS + t) * 3;
        float g3[3] = {g[0], g[1], g[2]};
        #pragma unroll
        for (int n = 0; n < 3; n++) {
            float gv = g3[n];
            float v[4] = {xv.x * gv, xv.y * gv, xv.z * gv, xv.w * gv};
            size_t idx = ((size_t)z * TOKENS + t) * KDIM + n * EDIM + e;
            #pragma unroll
            for (int i = 0; i < 4; i++) {
                __nv_bfloat16 hi = __float2bfloat16(v[i]);
                __nv_bfloat16 lo = __float2bfloat16(v[i] - __bfloat162float(hi));
                g_Ahi[idx + i] = hi;
                g_Alo[idx + i] = lo;
            }
        }
    }
}

// ---------------------------------------------------------------------------
// Kernel 2b: W conversion — transpose to [z][o][k] and split hi/lo.
// ---------------------------------------------------------------------------
__global__ void convertW_kernel(const float* __restrict__ Wq,
                                const float* __restrict__ Wk,
                                const float* __restrict__ Wv)
{
    __shared__ float ts[32][33];
    int zn = blockIdx.z;
    int z = zn / 3, n = zn % 3;
    const float* W = ((z == 0) ? Wq : (z == 1) ? Wk : Wv) + (size_t)n * EDIM * EDIM;
    int e0 = blockIdx.y * 32, o0 = blockIdx.x * 32;
    int tx = threadIdx.x, ty = threadIdx.y;   // (32, 8)
    #pragma unroll
    for (int i = 0; i < 4; i++) {
        int e = e0 + ty + i * 8;
        ts[ty + i * 8][tx] = W[(size_t)e * EDIM + o0 + tx];
    }
    __syncthreads();
    #pragma unroll
    for (int i = 0; i < 4; i++) {
        int o = o0 + ty + i * 8;
        float v = ts[tx][ty + i * 8];
        __nv_bfloat16 hi = __float2bfloat16(v);
        __nv_bfloat16 lo = __float2bfloat16(v - __bfloat162float(hi));
        size_t idx = ((size_t)z * EDIM + o) * KDIM + n * EDIM + e0 + tx;
        g_Bhi[idx] = hi;
        g_Blo[idx] = lo;
    }
}

// ---------------------------------------------------------------------------
// Kernel 3: bf16x3 MoE GEMM, BM=128 BN=256 BK=32, 3-stage cp.async,
// 8 warps (2x4), warp tile 64x64. Epilogue writes bf16 hi/lo QKV.
// ---------------------------------------------------------------------------
#define GBN 256
#define GP 80
#define MAT_A 10240              // 128*80
#define MAT_B 20480              // 256*80
#define GSTG (2*MAT_A + 2*MAT_B) // 61440
#define GNST (KDIM / 32)         // 96

__global__ void __launch_bounds__(256, 1) moe_gemm_mma(
    const float* __restrict__ bq, const float* __restrict__ bk, const float* __restrict__ bv)
{
    extern __shared__ char smem[];
    const uint32_t sb = smem_u32(smem);
    const int tid = threadIdx.x;
    const int lane = tid & 31, wid = tid >> 5;
    const int warpM = wid >> 2, warpN = wid & 3;
    const int z  = blockIdx.z;
    const int n0 = blockIdx.x * GBN;
    const int t0 = blockIdx.y * 128;

    const __nv_bfloat16* Ah = g_Ahi + ((size_t)z * TOKENS + t0) * KDIM;
    const __nv_bfloat16* Al = g_Alo + ((size_t)z * TOKENS + t0) * KDIM;
    const __nv_bfloat16* Bh = g_Bhi + ((size_t)z * EDIM + n0) * KDIM;
    const __nv_bfloat16* Bl = g_Blo + ((size_t)z * EDIM + n0) * KDIM;

    const int lr = tid >> 1;          // 0..127
    const int lc = (tid & 1) * 2;     // chunk base 0 or 2

    float acc[4][8][4];
    #pragma unroll
    for (int mt = 0; mt < 4; mt++)
        #pragma unroll
        for (int nt = 0; nt < 8; nt++)
            #pragma unroll
            for (int q = 0; q < 4; q++) acc[mt][nt][q] = 0.f;

    #define GEMM_ISSUE(S) do {                                                  \
        int _k0 = (S) * 32;                                                     \
        uint32_t _st = sb + (uint32_t)((S) % 3) * GSTG;                         \
        _Pragma("unroll")                                                       \
        for (int j = 0; j < 2; j++) {                                           \
            int c = lc + j;                                                     \
            uint32_t d = _st + (uint32_t)lr * GP + c * 16;                      \
            size_t go = (size_t)lr * KDIM + _k0 + c * 8;                        \
            cp_async16(d,         Ah + go);                                     \
            cp_async16(d + MAT_A, Al + go);                                     \
        }                                                                       \
        _Pragma("unroll")                                                       \
        for (int rr = 0; rr < 2; rr++) {                                        \
            int r = lr + rr * 128;                                              \
            _Pragma("unroll")                                                   \
            for (int j = 0; j < 2; j++) {                                       \
                int c = lc + j;                                                 \
                uint32_t d = _st + 2 * MAT_A + (uint32_t)r * GP + c * 16;       \
                size_t go = (size_t)r * KDIM + _k0 + c * 8;                     \
                cp_async16(d,         Bh + go);                                 \
                cp_async16(d + MAT_B, Bl + go);                                 \
            }                                                                   \
        }                                                                       \
        cp_commit();                                                            \
    } while (0)

    GEMM_ISSUE(0);
    GEMM_ISSUE(1);

    const uint32_t a_off = (uint32_t)(warpM * 64 + (lane & 15)) * GP + ((lane >> 4) << 4);
    const uint32_t b_off = (uint32_t)(warpN * 64 + (lane & 7) + ((lane >> 4) << 3)) * GP
                         + (((lane >> 3) & 1) << 4);

    for (int s = 0; s < GNST; s++) {
        if (s == GNST - 1) cp_wait0(); else cp_wait1();
        __syncthreads();
        if (s + 2 < GNST) GEMM_ISSUE(s + 2);
        uint32_t stg = sb + (uint32_t)(s % 3) * GSTG;
        #pragma unroll
        for (int kc = 0; kc < 2; kc++) {
            uint32_t ko = kc * 32;
            uint32_t ah[4][4], al[4][4];
            #pragma unroll
            for (int mt = 0; mt < 4; mt++) {
                uint32_t ad = stg + a_off + (uint32_t)(mt * 16) * GP + ko;
                ldsm_x4(ah[mt][0], ah[mt][1], ah[mt][2], ah[mt][3], ad);
                ldsm_x4(al[mt][0], al[mt][1], al[mt][2], al[mt][3], ad + MAT_A);
            }
            uint32_t bh_[8][2], bl_[8][2];
            #pragma unroll
            for (int p = 0; p < 4; p++) {
                uint32_t bd = stg + 2 * MAT_A + b_off + (uint32_t)(p * 16) * GP + ko;
                ldsm_x4(bh_[2*p][0], bh_[2*p][1], bh_[2*p+1][0], bh_[2*p+1][1], bd);
                ldsm_x4(bl_[2*p][0], bl_[2*p][1], bl_[2*p+1][0], bl_[2*p+1][1], bd + MAT_B);
            }
            #pragma unroll
            for (int mt = 0; mt < 4; mt++)
                #pragma unroll
                for (int nt = 0; nt < 8; nt++) {
                    mma_bf16(acc[mt][nt], ah[mt], bh_[nt]);
                    mma_bf16(acc[mt][nt], ah[mt], bl_[nt]);
                    mma_bf16(acc[mt][nt], al[mt], bh_[nt]);
                }
        }
    }

    // epilogue: gate-weighted bias, split to bf16 hi/lo, scatter to (m,h,s,d)
    const float* bias = (z == 0) ? bq : (z == 1) ? bk : bv;
    __nv_bfloat16* ohi = (z == 0) ? g_Qhi : (z == 1) ? g_Khi : g_Vhi;
    __nv_bfloat16* olo = (z == 0) ? g_Qlo : (z == 1) ? g_Klo : g_Vlo;
    #pragma unroll
    for (int mt = 0; mt < 4; mt++) {
        #pragma unroll
        for (int half = 0; half < 2; half++) {
            int t = t0 + warpM * 64 + mt * 16 + (lane >> 2) + half * 8;
            const float* g = g_gate + ((size_t)z * TOKENS + t) * 3;
            float g0 = g[0], g1 = g[1], g2 = g[2];
            int mb = t >> 11, sr = t & 2047;
            #pragma unroll
            for (int nt = 0; nt < 8; nt++) {
                int co = n0 + warpN * 64 + nt * 8 + 2 * (lane & 3);
                float2 b0 = *(const float2*)&bias[co];
                float2 b1 = *(const float2*)&bias[EDIM + co];
                float2 b2 = *(const float2*)&bias[2 * EDIM + co];
                float v0 = acc[mt][nt][half*2+0] + g0*b0.x + g1*b1.x + g2*b2.x;
                float v1 = acc[mt][nt][half*2+1] + g0*b0.y + g1*b1.y + g2*b2.y;
                __nv_bfloat16 h0 = __float2bfloat16(v0);
                __nv_bfloat16 h1 = __float2bfloat16(v1);
                float l0 = v0 - __bfloat162float(h0);
                float l1 = v1 - __bfloat162float(h1);
                __nv_bfloat162 hp; hp.x = h0; hp.y = h1;
                __nv_bfloat162 lp; lp.x = __float2bfloat16(l0); lp.y = __float2bfloat16(l1);
                int h = co >> 6, d = co & 63;
                size_t off = (((size_t)mb * NHEAD + h) * SEQ + sr) * HDIM + d;
                *(__nv_bfloat162*)&ohi[off] = hp;
                *(__nv_bfloat162*)&olo[off] = lp;
            }
        }
    }
    #undef GEMM_ISSUE
}

// ---------------------------------------------------------------------------
// Kernel 4: flash attention via HMMA bf16x3.
// 128 queries per CTA, 4 warps (32 q each: 2 m16 tiles x 64 d).
// 64-key kv tiles, 2-stage cp.async double buffer. Q resident in smem.
// ---------------------------------------------------------------------------
#define AP 144                    // smem row pitch bytes (64 bf16 + pad)
#define AQMAT (128 * AP)          // 18432: one Q matrix (hi or lo)
#define AKMAT (64 * AP)           // 9216: one K/V matrix
#define KVSTG (4 * AKMAT)         // 36864 per stage
#define KVOFF (2 * AQMAT)         // 36864: Q hi+lo before stages

__global__ void __launch_bounds__(128, 2) attn_mma(float* __restrict__ out)
{
    extern __shared__ char smem[];
    const uint32_t su = smem_u32(smem);
    const int tid = threadIdx.x;
    const int lane = tid & 31, wid = tid >> 5;
    const int bh = blockIdx.y;
    const int q0 = blockIdx.x * 128;

    const __nv_bfloat16* Qh = g_Qhi + ((size_t)bh * SEQ + q0) * HDIM;
    const __nv_bfloat16* Ql = g_Qlo + ((size_t)bh * SEQ + q0) * HDIM;
    const __nv_bfloat16* Khb = g_Khi + (size_t)bh * SEQ * HDIM;
    const __nv_bfloat16* Klb = g_Klo + (size_t)bh * SEQ * HDIM;
    const __nv_bfloat16* Vhb = g_Vhi + (size_t)bh * SEQ * HDIM;
    const __nv_bfloat16* Vlb = g_Vlo + (size_t)bh * SEQ * HDIM;

    const int lr = tid >> 1;          // 0..63
    const int lc = (tid & 1) * 4;     // chunk base

    // stage Q (hi/lo)
    #pragma unroll
    for (int rr = 0; rr < 2; rr++) {
        int r = lr + rr * 64;
        #pragma unroll
        for (int j = 0; j < 4; j++) {
            int c = lc + j;
            uint32_t d = su + (uint32_t)r * AP + c * 16;
            size_t go = (size_t)r * HDIM + c * 8;
            cp_async16(d,         Qh + go);
            cp_async16(d + AQMAT, Ql + go);
        }
    }
    cp_commit();

    #define ATTN_ISSUE(T) do {                                                  \
        uint32_t _st = su + KVOFF + (uint32_t)((T) & 1) * KVSTG;                \
        size_t _gb = (size_t)(T) * 64 * HDIM;                                   \
        _Pragma("unroll")                                                       \
        for (int j = 0; j < 4; j++) {                                           \
            int c = lc + j;                                                     \
            uint32_t d = _st + (uint32_t)lr * AP + c * 16;                      \
            size_t go = _gb + (size_t)lr * HDIM + c * 8;                        \
            cp_async16(d,             Khb + go);                                \
            cp_async16(d + AKMAT,     Klb + go);                                \
            cp_async16(d + 2*AKMAT,   Vhb + go);                                \
            cp_async16(d + 3*AKMAT,   Vlb + go);                                \
        }                                                                       \
        cp_commit();                                                            \
    } while (0)

    ATTN_ISSUE(0);

    float o_[2][8][4];
    float mrow[2][2], lrow[2][2];
    #pragma unroll
    for (int mt = 0; mt < 2; mt++) {
        #pragma unroll
        for (int nt = 0; nt < 8; nt++)
            #pragma unroll
            for (int q = 0; q < 4; q++) o_[mt][nt][q] = 0.f;
        mrow[mt][0] = -1e30f; mrow[mt][1] = -1e30f;
        lrow[mt][0] = 0.f;    lrow[mt][1] = 0.f;
    }

    const float sc = 0.125f;
    const uint32_t qa_off = (uint32_t)(wid * 32 + (lane & 15)) * AP + ((lane >> 4) << 4);
    const uint32_t kb_off = (uint32_t)((lane & 7) + ((lane >> 4) << 3)) * AP
                          + (((lane >> 3) & 1) << 4);
    const uint32_t vb_off = (uint32_t)((lane & 7) + (((lane >> 3) & 1) << 3)) * AP
                          + ((lane >> 4) << 4);

    for (int t = 0; t < SEQ / 64; t++) {
        cp_wait0();
        __syncthreads();
        if (t + 1 < SEQ / 64) ATTN_ISSUE(t + 1);
        uint32_t stg = su + KVOFF + (uint32_t)(t & 1) * KVSTG;

        // S = Qhi*Khi + Qhi*Klo + Qlo*Khi
        float s_[2][8][4];
        #pragma unroll
        for (int mt = 0; mt < 2; mt++)
            #pragma unroll
            for (int nt = 0; nt < 8; nt++)
                #pragma unroll
                for (int q = 0; q < 4; q++) s_[mt][nt][q] = 0.f;

        #pragma unroll
        for (int c = 0; c < 4; c++) {
            uint32_t qh[2][4], ql[2][4];
            #pragma unroll
            for (int mt = 0; mt < 2; mt++) {
                uint32_t ad = su + qa_off + (uint32_t)(mt * 16) * AP + c * 32;
                ldsm_x4(qh[mt][0], qh[mt][1], qh[mt][2], qh[mt][3], ad);
                ldsm_x4(ql[mt][0], ql[mt][1], ql[mt][2], ql[mt][3], ad + AQMAT);
            }
            uint32_t kh[8][2], kl[8][2];
            #pragma unroll
            for (int p = 0; p < 4; p++) {
                uint32_t bd = stg + kb_off + (uint32_t)(p * 16) * AP + c * 32;
                ldsm_x4(kh[2*p][0], kh[2*p][1], kh[2*p+1][0], kh[2*p+1][1], bd);
                ldsm_x4(kl[2*p][0], kl[2*p][1], kl[2*p+1][0], kl[2*p+1][1], bd + AKMAT);
            }
            #pragma unroll
            for (int mt = 0; mt < 2; mt++)
                #pragma unroll
                for (int nt = 0; nt < 8; nt++) {
                    mma_bf16(s_[mt][nt], qh[mt], kh[nt]);
                    mma_bf16(s_[mt][nt], qh[mt], kl[nt]);
                    mma_bf16(s_[mt][nt], ql[mt], kh[nt]);
                }
        }

        // online softmax + pack P hi/lo
        uint32_t phi[2][8][2], plo[2][8][2];
        #pragma unroll
        for (int mt = 0; mt < 2; mt++) {
            float r0 = -1e30f, r1 = -1e30f;
            #pragma unroll
            for (int j = 0; j < 8; j++) {
                r0 = fmaxf(r0, fmaxf(s_[mt][j][0], s_[mt][j][1]));
                r1 = fmaxf(r1, fmaxf(s_[mt][j][2], s_[mt][j][3]));
            }
            r0 = fmaxf(r0, __shfl_xor_sync(0xffffffffu, r0, 1));
            r0 = fmaxf(r0, __shfl_xor_sync(0xffffffffu, r0, 2));
            r1 = fmaxf(r1, __shfl_xor_sync(0xffffffffu, r1, 1));
            r1 = fmaxf(r1, __shfl_xor_sync(0xffffffffu, r1, 2));
            float m0 = fmaxf(mrow[mt][0], r0 * sc);
            float m1 = fmaxf(mrow[mt][1], r1 * sc);
            float f0 = __expf(mrow[mt][0] - m0);
            float f1 = __expf(mrow[mt][1] - m1);
            mrow[mt][0] = m0; mrow[mt][1] = m1;
            float s0 = 0.f, s1 = 0.f;
            #pragma unroll
            for (int j = 0; j < 8; j++) {
                float p00 = __expf(__fmaf_rn(s_[mt][j][0], sc, -m0));
                float p01 = __expf(__fmaf_rn(s_[mt][j][1], sc, -m0));
                float p10 = __expf(__fmaf_rn(s_[mt][j][2], sc, -m1));
                float p11 = __expf(__fmaf_rn(s_[mt][j][3], sc, -m1));
                s0 += p00 + p01; s1 += p10 + p11;
                uint32_t h0 = pack_bf16x2(p00, p01);
                uint32_t h1 = pack_bf16x2(p10, p11);
                phi[mt][j][0] = h0; phi[mt][j][1] = h1;
                float2 hf0 = __bfloat1622float2(*(__nv_bfloat162*)&h0);
                float2 hf1 = __bfloat1622float2(*(__nv_bfloat162*)&h1);
                plo[mt][j][0] = pack_bf16x2(p00 - hf0.x, p01 - hf0.y);
                plo[mt][j][1] = pack_bf16x2(p10 - hf1.x, p11 - hf1.y);
            }
            s0 += __shfl_xor_sync(0xffffffffu, s0, 1);
            s0 += __shfl_xor_sync(0xffffffffu, s0, 2);
            s1 += __shfl_xor_sync(0xffffffffu, s1, 1);
            s1 += __shfl_xor_sync(0xffffffffu, s1, 2);
            lrow[mt][0] = lrow[mt][0] * f0 + s0;
            lrow[mt][1] = lrow[mt][1] * f1 + s1;
            #pragma unroll
            for (int j = 0; j < 8; j++) {
                o_[mt][j][0] *= f0; o_[mt][j][1] *= f0;
                o_[mt][j][2] *= f1; o_[mt][j][3] *= f1;
            }
        }

        // O += Phi*Vhi + Phi*Vlo + Plo*Vhi
        #pragma unroll
        for (int kc = 0; kc < 4; kc++) {
            uint32_t vh[8][2], vl[8][2];
            #pragma unroll
            for (int dj = 0; dj < 4; dj++) {
                uint32_t vd = stg + 2 * AKMAT + vb_off
                            + (uint32_t)(kc * 16) * AP + dj * 32;
                ldsm_x4t(vh[2*dj][0], vh[2*dj][1], vh[2*dj+1][0], vh[2*dj+1][1], vd);
                ldsm_x4t(vl[2*dj][0], vl[2*dj][1], vl[2*dj+1][0], vl[2*dj+1][1], vd + AKMAT);
            }
            #pragma unroll
            for (int mt = 0; mt < 2; mt++) {
                uint32_t ah[4] = {phi[mt][2*kc][0], phi[mt][2*kc][1],
                                  phi[mt][2*kc+1][0], phi[mt][2*kc+1][1]};
                uint32_t al[4] = {plo[mt][2*kc][0], plo[mt][2*kc][1],
                                  plo[mt][2*kc+1][0], plo[mt][2*kc+1][1]};
                #pragma unroll
                for (int nt = 0; nt < 8; nt++) {
                    mma_bf16(o_[mt][nt], ah, vh[nt]);
                    mma_bf16(o_[mt][nt], ah, vl[nt]);
                    mma_bf16(o_[mt][nt], al, vh[nt]);
                }
            }
        }
    }

    // normalize and store
    int m = bh >> 4, h = bh & 15;
    #pragma unroll
    for (int mt = 0; mt < 2; mt++) {
        float inv0 = 1.0f / lrow[mt][0];
        float inv1 = 1.0f / lrow[mt][1];
        int r0 = q0 + wid * 32 + mt * 16 + (lane >> 2);
        int r1 = r0 + 8;
        #pragma unroll
        for (int j = 0; j < 8; j++) {
            int col = h * HDIM + j * 8 + 2 * (lane & 3);
            *(float2*)&out[((size_t)m * SEQ + r0) * EDIM + col] =
                make_float2(o_[mt][j][0] * inv0, o_[mt][j][1] * inv0);
            *(float2*)&out[((size_t)m * SEQ + r1) * EDIM + col] =
                make_float2(o_[mt][j][2] * inv1, o_[mt][j][3] * inv1);
        }
    }
    #undef ATTN_ISSUE
}

// ---------------------------------------------------------------------------
extern "C" void kernel_launch(void* const* d_in, const int* in_sizes, int n_in,
                              void* d_out, int out_size)
{
    (void)in_sizes; (void)n_in; (void)out_size;
    const float* x   = (const float*)d_in[0];
    const float* Wq  = (const float*)d_in[1];
    const float* bq  = (const float*)d_in[2];
    const float* Wgq = (const float*)d_in[3];
    const float* bgq = (const float*)d_in[4];
    const float* Wk  = (const float*)d_in[5];
    const float* bk  = (const float*)d_in[6];
    const float* Wgk = (const float*)d_in[7];
    const float* bgk = (const float*)d_in[8];
    const float* Wv  = (const float*)d_in[9];
    const float* bv  = (const float*)d_in[10];
    const float* Wgv = (const float*)d_in[11];
    const float* bgv = (const float*)d_in[12];
    float* out = (float*)d_out;

    gates_kernel<<<TOKENS, 128>>>(x, Wgq, bgq, Wgk, bgk, Wgv, bgv);
    convertW_kernel<<<dim3(32, 32, 9), dim3(32, 8)>>>(Wq, Wk, Wv);
    convertA_kernel<<<TOKENS, 256>>>(x);

    const int gemm_smem = 3 * GSTG;   // 184320
    cudaFuncSetAttribute(moe_gemm_mma, cudaFuncAttributeMaxDynamicSharedMemorySize, gemm_smem);
    moe_gemm_mma<<<dim3(EDIM / GBN, TOKENS / 128, 3), 256, gemm_smem>>>(bq, bk, bv);

    const int attn_smem = KVOFF + 2 * KVSTG;  // 110592
    cudaFuncSetAttribute(attn_mma, cudaFuncAttributeMaxDynamicSharedMemorySize, attn_smem);
    attn_mma<<<dim3(SEQ / 128, MBATCH * NHEAD), 128, attn_smem>>>(out);
}

// round 5
// speedup vs baseline: 2.0358x; 1.0266x over previous
#include <cuda_runtime.h>
#include <cuda_bf16.h>
#include <cstdint>

#define TOKENS 8192
#define EDIM 1024
#define NHEAD 16
#define HDIM 64
#define SEQ 2048
#define MBATCH 4
#define KDIM 3072

// scratch
__device__ float g_gate[3 * TOKENS * 3];
__device__ __nv_bfloat16 g_Xhi[(size_t)TOKENS * EDIM];   // split x (shared across z)
__device__ __nv_bfloat16 g_Xlo[(size_t)TOKENS * EDIM];
__device__ __nv_bfloat16 g_Bhi[3ull * EDIM * KDIM];      // W^T hi [z][o][k]
__device__ __nv_bfloat16 g_Blo[3ull * EDIM * KDIM];
// QKV in (z, m*h, s, d) bf16 hi/lo
__device__ __nv_bfloat16 g_Qhi[(size_t)TOKENS * EDIM];
__device__ __nv_bfloat16 g_Qlo[(size_t)TOKENS * EDIM];
__device__ __nv_bfloat16 g_Khi[(size_t)TOKENS * EDIM];
__device__ __nv_bfloat16 g_Klo[(size_t)TOKENS * EDIM];
__device__ __nv_bfloat16 g_Vhi[(size_t)TOKENS * EDIM];
__device__ __nv_bfloat16 g_Vlo[(size_t)TOKENS * EDIM];

// ---------------- helpers ----------------
__device__ __forceinline__ uint32_t smem_u32(const void* p) {
    uint32_t a;
    asm("{ .reg .u64 t; cvta.to.shared.u64 t, %1; cvt.u32.u64 %0, t; }" : "=r"(a) : "l"(p));
    return a;
}
__device__ __forceinline__ void cp_async16(uint32_t dst, const void* src) {
    asm volatile("cp.async.cg.shared.global [%0], [%1], 16;" :: "r"(dst), "l"(src) : "memory");
}
__device__ __forceinline__ void cp_commit() {
    asm volatile("cp.async.commit_group;" ::: "memory");
}
__device__ __forceinline__ void cp_wait0() {
    asm volatile("cp.async.wait_group 0;" ::: "memory");
}
__device__ __forceinline__ void cp_wait1() {
    asm volatile("cp.async.wait_group 1;" ::: "memory");
}
__device__ __forceinline__ void ldsm_x4(uint32_t& r0, uint32_t& r1, uint32_t& r2, uint32_t& r3,
                                        uint32_t addr) {
    asm volatile("ldmatrix.sync.aligned.m8n8.x4.shared.b16 {%0,%1,%2,%3}, [%4];"
                 : "=r"(r0), "=r"(r1), "=r"(r2), "=r"(r3) : "r"(addr));
}
__device__ __forceinline__ void ldsm_x4t(uint32_t& r0, uint32_t& r1, uint32_t& r2, uint32_t& r3,
                                         uint32_t addr) {
    asm volatile("ldmatrix.sync.aligned.m8n8.x4.trans.shared.b16 {%0,%1,%2,%3}, [%4];"
                 : "=r"(r0), "=r"(r1), "=r"(r2), "=r"(r3) : "r"(addr));
}
__device__ __forceinline__ void mma_bf16(float* d, const uint32_t* a, const uint32_t* b) {
    asm volatile("mma.sync.aligned.m16n8k16.row.col.f32.bf16.bf16.f32 "
                 "{%0,%1,%2,%3},{%4,%5,%6,%7},{%8,%9},{%0,%1,%2,%3};"
                 : "+f"(d[0]), "+f"(d[1]), "+f"(d[2]), "+f"(d[3])
                 : "r"(a[0]), "r"(a[1]), "r"(a[2]), "r"(a[3]), "r"(b[0]), "r"(b[1]));
}
__device__ __forceinline__ uint32_t pack_bf16x2(float lo, float hi) {
    __nv_bfloat162 h = __float22bfloat162_rn(make_float2(lo, hi));
    return *(uint32_t*)&h;
}

// ---------------------------------------------------------------------------
// Kernel 1: gates
// ---------------------------------------------------------------------------
__global__ void gates_kernel(const float* __restrict__ x,
                             const float* __restrict__ Wg0, const float* __restrict__ bg0,
                             const float* __restrict__ Wg1, const float* __restrict__ bg1,
                             const float* __restrict__ Wg2, const float* __restrict__ bg2)
{
    __shared__ float xs[EDIM];
    int t = blockIdx.x;
    int tid = threadIdx.x;
    const float4* xrow = (const float4*)(x + (size_t)t * EDIM);
    ((float4*)xs)[tid]       = xrow[tid];
    ((float4*)xs)[tid + 128] = xrow[tid + 128];
    __syncthreads();

    int w = tid >> 5;
    if (w < 3) {
        const float* Wg = (w == 0) ? Wg0 : (w == 1) ? Wg1 : Wg2;
        const float* bg = (w == 0) ? bg0 : (w == 1) ? bg1 : bg2;
        int lane = tid & 31;
        float a0 = 0.f, a1 = 0.f, a2 = 0.f;
        for (int e = lane; e < EDIM; e += 32) {
            float xv = xs[e];
            a0 += xv * Wg[e * 3 + 0];
            a1 += xv * Wg[e * 3 + 1];
            a2 += xv * Wg[e * 3 + 2];
        }
        #pragma unroll
        for (int o = 16; o; o >>= 1) {
            a0 += __shfl_xor_sync(0xffffffffu, a0, o);
            a1 += __shfl_xor_sync(0xffffffffu, a1, o);
            a2 += __shfl_xor_sync(0xffffffffu, a2, o);
        }
        if (lane == 0) {
            a0 += bg[0]; a1 += bg[1]; a2 += bg[2];
            float mx = fmaxf(a0, fmaxf(a1, a2));
            float e0 = __expf(a0 - mx), e1 = __expf(a1 - mx), e2 = __expf(a2 - mx);
            float inv = 1.0f / (e0 + e1 + e2);
            float* gp = g_gate + ((size_t)w * TOKENS + t) * 3;
            gp[0] = e0 * inv; gp[1] = e1 * inv; gp[2] = e2 * inv;
        }
    }
}

// ---------------------------------------------------------------------------
// Kernel 2a: X conversion — split x into bf16 hi/lo (no gate; shared by z)
// ---------------------------------------------------------------------------
__global__ void convertX_kernel(const float* __restrict__ x)
{
    size_t i = ((size_t)blockIdx.x * 256 + threadIdx.x) * 4;
    float4 v = *(const float4*)(x + i);
    float vv[4] = {v.x, v.y, v.z, v.w};
    #pragma unroll
    for (int j = 0; j < 4; j++) {
        __nv_bfloat16 hi = __float2bfloat16(vv[j]);
        g_Xhi[i + j] = hi;
        g_Xlo[i + j] = __float2bfloat16(vv[j] - __bfloat162float(hi));
    }
}

// ---------------------------------------------------------------------------
// Kernel 2b: W conversion — transpose to [z][o][k] and split hi/lo.
// ---------------------------------------------------------------------------
__global__ void convertW_kernel(const float* __restrict__ Wq,
                                const float* __restrict__ Wk,
                                const float* __restrict__ Wv)
{
    __shared__ float ts[32][33];
    int zn = blockIdx.z;
    int z = zn / 3, n = zn % 3;
    const float* W = ((z == 0) ? Wq : (z == 1) ? Wk : Wv) + (size_t)n * EDIM * EDIM;
    int e0 = blockIdx.y * 32, o0 = blockIdx.x * 32;
    int tx = threadIdx.x, ty = threadIdx.y;   // (32, 8)
    #pragma unroll
    for (int i = 0; i < 4; i++) {
        int e = e0 + ty + i * 8;
        ts[ty + i * 8][tx] = W[(size_t)e * EDIM + o0 + tx];
    }
    __syncthreads();
    #pragma unroll
    for (int i = 0; i < 4; i++) {
        int o = o0 + ty + i * 8;
        float v = ts[tx][ty + i * 8];
        __nv_bfloat16 hi = __float2bfloat16(v);
        __nv_bfloat16 lo = __float2bfloat16(v - __bfloat162float(hi));
        size_t idx = ((size_t)z * EDIM + o) * KDIM + n * EDIM + e0 + tx;
        g_Bhi[idx] = hi;
        g_Blo[idx] = lo;
    }
}

// ---------------------------------------------------------------------------
// Kernel 3: bf16x3 MoE GEMM, BM=128 BN=256 BK=64, 2-stage cp.async,
// Horner gate factorization across the 3 K-segments of 1024.
// 8 warps (2x4), warp tile 64x64. Epilogue writes bf16 hi/lo QKV.
// ---------------------------------------------------------------------------
#define GBN 256
#define GP 144                    // row pitch bytes (64 bf16 + 16 pad)
#define AXM (128 * GP)            // 18432 per A matrix
#define BXM (256 * GP)            // 36864 per B matrix
#define GSTG (2 * AXM + 2 * BXM)  // 110592 per stage
#define GNST (KDIM / 64)          // 48
#define SEGST 16                  // stages per gate segment

__global__ void __launch_bounds__(256, 1) moe_gemm_mma(
    const float* __restrict__ bq, const float* __restrict__ bk, const float* __restrict__ bv)
{
    extern __shared__ char smem[];
    const uint32_t sb = smem_u32(smem);
    const int tid = threadIdx.x;
    const int lane = tid & 31, wid = tid >> 5;
    const int warpM = wid >> 2, warpN = wid & 3;
    const int z  = blockIdx.z;
    const int n0 = blockIdx.x * GBN;
    const int t0 = blockIdx.y * 128;

    const __nv_bfloat16* Xh = g_Xhi + (size_t)t0 * EDIM;
    const __nv_bfloat16* Xl = g_Xlo + (size_t)t0 * EDIM;
    const __nv_bfloat16* Bh = g_Bhi + ((size_t)z * EDIM + n0) * KDIM;
    const __nv_bfloat16* Bl = g_Blo + ((size_t)z * EDIM + n0) * KDIM;
    const float* gate = g_gate + (size_t)z * TOKENS * 3;

    const int lr = tid >> 1;          // 0..127
    const int lc = (tid & 1) * 4;     // chunk base 0 or 4

    float acc[4][8][4];
    #pragma unroll
    for (int mt = 0; mt < 4; mt++)
        #pragma unroll
        for (int nt = 0; nt < 8; nt++)
            #pragma unroll
            for (int q = 0; q < 4; q++) acc[mt][nt][q] = 0.f;

    #define GEMM_ISSUE(S) do {                                                  \
        int _k0 = (S) * 64;                                                     \
        int _e0 = _k0 & 1023;                                                   \
        uint32_t _st = sb + (uint32_t)((S) & 1) * GSTG;                         \
        _Pragma("unroll")                                                       \
        for (int j = 0; j < 4; j++) {                                           \
            int c = lc + j;                                                     \
            uint32_t d = _st + (uint32_t)lr * GP + c * 16;                      \
            size_t go = (size_t)lr * EDIM + _e0 + c * 8;                        \
            cp_async16(d,       Xh + go);                                       \
            cp_async16(d + AXM, Xl + go);                                       \
        }                                                                       \
        _Pragma("unroll")                                                       \
        for (int rr = 0; rr < 2; rr++) {                                        \
            int r = lr + rr * 128;                                              \
            _Pragma("unroll")                                                   \
            for (int j = 0; j < 4; j++) {                                       \
                int c = lc + j;                                                 \
                uint32_t d = _st + 2 * AXM + (uint32_t)r * GP + c * 16;         \
                size_t go = (size_t)r * KDIM + _k0 + c * 8;                     \
                cp_async16(d,       Bh + go);                                   \
                cp_async16(d + BXM, Bl + go);                                   \
            }                                                                   \
        }                                                                       \
        cp_commit();                                                            \
    } while (0)

    GEMM_ISSUE(0);

    const uint32_t a_off = (uint32_t)(warpM * 64 + (lane & 15)) * GP + ((lane >> 4) << 4);
    const uint32_t b_off = (uint32_t)(warpN * 64 + (lane & 7) + ((lane >> 4) << 3)) * GP
                         + (((lane >> 3) & 1) << 4);

    for (int s = 0; s < GNST; s++) {
        if (s + 1 < GNST) cp_wait1(); else cp_wait0();
        __syncthreads();
        if (s + 1 < GNST) GEMM_ISSUE(s + 1);
        uint32_t stg = sb + (uint32_t)(s & 1) * GSTG;
        #pragma unroll
        for (int kc = 0; kc < 4; kc++) {
            uint32_t ko = kc * 32;
            uint32_t ah[4][4], al[4][4];
            #pragma unroll
            for (int mt = 0; mt < 4; mt++) {
                uint32_t ad = stg + a_off + (uint32_t)(mt * 16) * GP + ko;
                ldsm_x4(ah[mt][0], ah[mt][1], ah[mt][2], ah[mt][3], ad);
                ldsm_x4(al[mt][0], al[mt][1], al[mt][2], al[mt][3], ad + AXM);
            }
            uint32_t bh_[8][2], bl_[8][2];
            #pragma unroll
            for (int p = 0; p < 4; p++) {
                uint32_t bd = stg + 2 * AXM + b_off + (uint32_t)(p * 16) * GP + ko;
                ldsm_x4(bh_[2*p][0], bh_[2*p][1], bh_[2*p+1][0], bh_[2*p+1][1], bd);
                ldsm_x4(bl_[2*p][0], bl_[2*p][1], bl_[2*p+1][0], bl_[2*p+1][1], bd + BXM);
            }
            #pragma unroll
            for (int mt = 0; mt < 4; mt++)
                #pragma unroll
                for (int nt = 0; nt < 8; nt++) {
                    mma_bf16(acc[mt][nt], ah[mt], bh_[nt]);
                    mma_bf16(acc[mt][nt], ah[mt], bl_[nt]);
                    mma_bf16(acc[mt][nt], al[mt], bh_[nt]);
                }
        }
        // Horner gate-segment boundary: acc *= g[n]/g[n+1]
        if (s == SEGST - 1 || s == 2 * SEGST - 1) {
            int n = (s == SEGST - 1) ? 0 : 1;
            #pragma unroll
            for (int mt = 0; mt < 4; mt++) {
                #pragma unroll
                for (int half = 0; half < 2; half++) {
                    int t = t0 + warpM * 64 + mt * 16 + (lane >> 2) + half * 8;
                    float r = __ldg(&gate[t * 3 + n]) / __ldg(&gate[t * 3 + n + 1]);
                    #pragma unroll
                    for (int nt = 0; nt < 8; nt++) {
                        acc[mt][nt][half * 2 + 0] *= r;
                        acc[mt][nt][half * 2 + 1] *= r;
                    }
                }
            }
        }
    }

    // epilogue: v = acc*g2 + sum g_i b_i; split to bf16 hi/lo; scatter (m,h,s,d)
    const float* bias = (z == 0) ? bq : (z == 1) ? bk : bv;
    __nv_bfloat16* ohi = (z == 0) ? g_Qhi : (z == 1) ? g_Khi : g_Vhi;
    __nv_bfloat16* olo = (z == 0) ? g_Qlo : (z == 1) ? g_Klo : g_Vlo;
    #pragma unroll
    for (int mt = 0; mt < 4; mt++) {
        #pragma unroll
        for (int half = 0; half < 2; half++) {
            int t = t0 + warpM * 64 + mt * 16 + (lane >> 2) + half * 8;
            float g0 = gate[t * 3 + 0], g1 = gate[t * 3 + 1], g2 = gate[t * 3 + 2];
            int mb = t >> 11, sr = t & 2047;
            #pragma unroll
            for (int nt = 0; nt < 8; nt++) {
                int co = n0 + warpN * 64 + nt * 8 + 2 * (lane & 3);
                float2 b0 = *(const float2*)&bias[co];
                float2 b1 = *(const float2*)&bias[EDIM + co];
                float2 b2 = *(const float2*)&bias[2 * EDIM + co];
                float v0 = acc[mt][nt][half*2+0] * g2 + g0*b0.x + g1*b1.x + g2*b2.x;
                float v1 = acc[mt][nt][half*2+1] * g2 + g0*b0.y + g1*b1.y + g2*b2.y;
                __nv_bfloat16 h0 = __float2bfloat16(v0);
                __nv_bfloat16 h1 = __float2bfloat16(v1);
                float l0 = v0 - __bfloat162float(h0);
                float l1 = v1 - __bfloat162float(h1);
                __nv_bfloat162 hp; hp.x = h0; hp.y = h1;
                __nv_bfloat162 lp; lp.x = __float2bfloat16(l0); lp.y = __float2bfloat16(l1);
                int h = co >> 6, d = co & 63;
                size_t off = (((size_t)mb * NHEAD + h) * SEQ + sr) * HDIM + d;
                *(__nv_bfloat162*)&ohi[off] = hp;
                *(__nv_bfloat162*)&olo[off] = lp;
            }
        }
    }
    #undef GEMM_ISSUE
}

// ---------------------------------------------------------------------------
// Kernel 4: flash attention via HMMA bf16x3 (unchanged from R4).
// ---------------------------------------------------------------------------
#define AP 144
#define AQMAT (128 * AP)
#define AKMAT (64 * AP)
#define KVSTG (4 * AKMAT)
#define KVOFF (2 * AQMAT)

__global__ void __launch_bounds__(128, 2) attn_mma(float* __restrict__ out)
{
    extern __shared__ char smem[];
    const uint32_t su = smem_u32(smem);
    const int tid = threadIdx.x;
    const int lane = tid & 31, wid = tid >> 5;
    const int bh = blockIdx.y;
    const int q0 = blockIdx.x * 128;

    const __nv_bfloat16* Qh = g_Qhi + ((size_t)bh * SEQ + q0) * HDIM;
    const __nv_bfloat16* Ql = g_Qlo + ((size_t)bh * SEQ + q0) * HDIM;
    const __nv_bfloat16* Khb = g_Khi + (size_t)bh * SEQ * HDIM;
    const __nv_bfloat16* Klb = g_Klo + (size_t)bh * SEQ * HDIM;
    const __nv_bfloat16* Vhb = g_Vhi + (size_t)bh * SEQ * HDIM;
    const __nv_bfloat16* Vlb = g_Vlo + (size_t)bh * SEQ * HDIM;

    const int lr = tid >> 1;
    const int lc = (tid & 1) * 4;

    #pragma unroll
    for (int rr = 0; rr < 2; rr++) {
        int r = lr + rr * 64;
        #pragma unroll
        for (int j = 0; j < 4; j++) {
            int c = lc + j;
            uint32_t d = su + (uint32_t)r * AP + c * 16;
            size_t go = (size_t)r * HDIM + c * 8;
            cp_async16(d,         Qh + go);
            cp_async16(d + AQMAT, Ql + go);
        }
    }
    cp_commit();

    #define ATTN_ISSUE(T) do {                                                  \
        uint32_t _st = su + KVOFF + (uint32_t)((T) & 1) * KVSTG;                \
        size_t _gb = (size_t)(T) * 64 * HDIM;                                   \
        _Pragma("unroll")                                                       \
        for (int j = 0; j < 4; j++) {                                           \
            int c = lc + j;                                                     \
            uint32_t d = _st + (uint32_t)lr * AP + c * 16;                      \
            size_t go = _gb + (size_t)lr * HDIM + c * 8;                        \
            cp_async16(d,             Khb + go);                                \
            cp_async16(d + AKMAT,     Klb + go);                                \
            cp_async16(d + 2*AKMAT,   Vhb + go);                                \
            cp_async16(d + 3*AKMAT,   Vlb + go);                                \
        }                                                                       \
        cp_commit();                                                            \
    } while (0)

    ATTN_ISSUE(0);

    float o_[2][8][4];
    float mrow[2][2], lrow[2][2];
    #pragma unroll
    for (int mt = 0; mt < 2; mt++) {
        #pragma unroll
        for (int nt = 0; nt < 8; nt++)
            #pragma unroll
            for (int q = 0; q < 4; q++) o_[mt][nt][q] = 0.f;
        mrow[mt][0] = -1e30f; mrow[mt][1] = -1e30f;
        lrow[mt][0] = 0.f;    lrow[mt][1] = 0.f;
    }

    const float sc = 0.125f;
    const uint32_t qa_off = (uint32_t)(wid * 32 + (lane & 15)) * AP + ((lane >> 4) << 4);
    const uint32_t kb_off = (uint32_t)((lane & 7) + ((lane >> 4) << 3)) * AP
                          + (((lane >> 3) & 1) << 4);
    const uint32_t vb_off = (uint32_t)((lane & 7) + (((lane >> 3) & 1) << 3)) * AP
                          + ((lane >> 4) << 4);

    for (int t = 0; t < SEQ / 64; t++) {
        cp_wait0();
        __syncthreads();
        if (t + 1 < SEQ / 64) ATTN_ISSUE(t + 1);
        uint32_t stg = su + KVOFF + (uint32_t)(t & 1) * KVSTG;

        float s_[2][8][4];
        #pragma unroll
        for (int mt = 0; mt < 2; mt++)
            #pragma unroll
            for (int nt = 0; nt < 8; nt++)
                #pragma unroll
                for (int q = 0; q < 4; q++) s_[mt][nt][q] = 0.f;

        #pragma unroll
        for (int c = 0; c < 4; c++) {
            uint32_t qh[2][4], ql[2][4];
            #pragma unroll
            for (int mt = 0; mt < 2; mt++) {
                uint32_t ad = su + qa_off + (uint32_t)(mt * 16) * AP + c * 32;
                ldsm_x4(qh[mt][0], qh[mt][1], qh[mt][2], qh[mt][3], ad);
                ldsm_x4(ql[mt][0], ql[mt][1], ql[mt][2], ql[mt][3], ad + AQMAT);
            }
            uint32_t kh[8][2], kl[8][2];
            #pragma unroll
            for (int p = 0; p < 4; p++) {
                uint32_t bd = stg + kb_off + (uint32_t)(p * 16) * AP + c * 32;
                ldsm_x4(kh[2*p][0], kh[2*p][1], kh[2*p+1][0], kh[2*p+1][1], bd);
                ldsm_x4(kl[2*p][0], kl[2*p][1], kl[2*p+1][0], kl[2*p+1][1], bd + AKMAT);
            }
            #pragma unroll
            for (int mt = 0; mt < 2; mt++)
                #pragma unroll
                for (int nt = 0; nt < 8; nt++) {
                    mma_bf16(s_[mt][nt], qh[mt], kh[nt]);
                    mma_bf16(s_[mt][nt], qh[mt], kl[nt]);
                    mma_bf16(s_[mt][nt], ql[mt], kh[nt]);
                }
        }

        uint32_t phi[2][8][2], plo[2][8][2];
        #pragma unroll
        for (int mt = 0; mt < 2; mt++) {
            float r0 = -1e30f, r1 = -1e30f;
            #pragma unroll
            for (int j = 0; j < 8; j++) {
                r0 = fmaxf(r0, fmaxf(s_[mt][j][0], s_[mt][j][1]));
                r1 = fmaxf(r1, fmaxf(s_[mt][j][2], s_[mt][j][3]));
            }
            r0 = fmaxf(r0, __shfl_xor_sync(0xffffffffu, r0, 1));
            r0 = fmaxf(r0, __shfl_xor_sync(0xffffffffu, r0, 2));
            r1 = fmaxf(r1, __shfl_xor_sync(0xffffffffu, r1, 1));
            r1 = fmaxf(r1, __shfl_xor_sync(0xffffffffu, r1, 2));
            float m0 = fmaxf(mrow[mt][0], r0 * sc);
            float m1 = fmaxf(mrow[mt][1], r1 * sc);
            float f0 = __expf(mrow[mt][0] - m0);
            float f1 = __expf(mrow[mt][1] - m1);
            mrow[mt][0] = m0; mrow[mt][1] = m1;
            float s0 = 0.f, s1 = 0.f;
            #pragma unroll
            for (int j = 0; j < 8; j++) {
                float p00 = __expf(__fmaf_rn(s_[mt][j][0], sc, -m0));
                float p01 = __expf(__fmaf_rn(s_[mt][j][1], sc, -m0));
                float p10 = __expf(__fmaf_rn(s_[mt][j][2], sc, -m1));
                float p11 = __expf(__fmaf_rn(s_[mt][j][3], sc, -m1));
                s0 += p00 + p01; s1 += p10 + p11;
                uint32_t h0 = pack_bf16x2(p00, p01);
                uint32_t h1 = pack_bf16x2(p10, p11);
                phi[mt][j][0] = h0; phi[mt][j][1] = h1;
                float2 hf0 = __bfloat1622float2(*(__nv_bfloat162*)&h0);
                float2 hf1 = __bfloat1622float2(*(__nv_bfloat162*)&h1);
                plo[mt][j][0] = pack_bf16x2(p00 - hf0.x, p01 - hf0.y);
                plo[mt][j][1] = pack_bf16x2(p10 - hf1.x, p11 - hf1.y);
            }
            s0 += __shfl_xor_sync(0xffffffffu, s0, 1);
            s0 += __shfl_xor_sync(0xffffffffu, s0, 2);
            s1 += __shfl_xor_sync(0xffffffffu, s1, 1);
            s1 += __shfl_xor_sync(0xffffffffu, s1, 2);
            lrow[mt][0] = lrow[mt][0] * f0 + s0;
            lrow[mt][1] = lrow[mt][1] * f1 + s1;
            #pragma unroll
            for (int j = 0; j < 8; j++) {
                o_[mt][j][0] *= f0; o_[mt][j][1] *= f0;
                o_[mt][j][2] *= f1; o_[mt][j][3] *= f1;
            }
        }

        #pragma unroll
        for (int kc = 0; kc < 4; kc++) {
            uint32_t vh[8][2], vl[8][2];
            #pragma unroll
            for (int dj = 0; dj < 4; dj++) {
                uint32_t vd = stg + 2 * AKMAT + vb_off
                            + (uint32_t)(kc * 16) * AP + dj * 32;
                ldsm_x4t(vh[2*dj][0], vh[2*dj][1], vh[2*dj+1][0], vh[2*dj+1][1], vd);
                ldsm_x4t(vl[2*dj][0], vl[2*dj][1], vl[2*dj+1][0], vl[2*dj+1][1], vd + AKMAT);
            }
            #pragma unroll
            for (int mt = 0; mt < 2; mt++) {
                uint32_t ah[4] = {phi[mt][2*kc][0], phi[mt][2*kc][1],
                                  phi[mt][2*kc+1][0], phi[mt][2*kc+1][1]};
                uint32_t al[4] = {plo[mt][2*kc][0], plo[mt][2*kc][1],
                                  plo[mt][2*kc+1][0], plo[mt][2*kc+1][1]};
                #pragma unroll
                for (int nt = 0; nt < 8; nt++) {
                    mma_bf16(o_[mt][nt], ah, vh[nt]);
                    mma_bf16(o_[mt][nt], ah, vl[nt]);
                    mma_bf16(o_[mt][nt], al, vh[nt]);
                }
            }
        }
    }

    int m = bh >> 4, h = bh & 15;
    #pragma unroll
    for (int mt = 0; mt < 2; mt++) {
        float inv0 = 1.0f / lrow[mt][0];
        float inv1 = 1.0f / lrow[mt][1];
        int r0 = q0 + wid * 32 + mt * 16 + (lane >> 2);
        int r1 = r0 + 8;
        #pragma unroll
        for (int j = 0; j < 8; j++) {
            int col = h * HDIM + j * 8 + 2 * (lane & 3);
            *(float2*)&out[((size_t)m * SEQ + r0) * EDIM + col] =
                make_float2(o_[mt][j][0] * inv0, o_[mt][j][1] * inv0);
            *(float2*)&out[((size_t)m * SEQ + r1) * EDIM + col] =
                make_float2(o_[mt][j][2] * inv1, o_[mt][j][3] * inv1);
        }
    }
    #undef ATTN_ISSUE
}

// ---------------------------------------------------------------------------
extern "C" void kernel_launch(void* const* d_in, const int* in_sizes, int n_in,
                              void* d_out, int out_size)
{
    (void)in_sizes; (void)n_in; (void)out_size;
    const float* x   = (const float*)d_in[0];
    const float* Wq  = (const float*)d_in[1];
    const float* bq  = (const float*)d_in[2];
    const float* Wgq = (const float*)d_in[3];
    const float* bgq = (const float*)d_in[4];
    const float* Wk  = (const float*)d_in[5];
    const float* bk  = (const float*)d_in[6];
    const float* Wgk = (const float*)d_in[7];
    const float* bgk = (const float*)d_in[8];
    const float* Wv  = (const float*)d_in[9];
    const float* bv  = (const float*)d_in[10];
    const float* Wgv = (const float*)d_in[11];
    const float* bgv = (const float*)d_in[12];
    float* out = (float*)d_out;

    gates_kernel<<<TOKENS, 128>>>(x, Wgq, bgq, Wgk, bgk, Wgv, bgv);
    convertW_kernel<<<dim3(32, 32, 9), dim3(32, 8)>>>(Wq, Wk, Wv);
    convertX_kernel<<<TOKENS * EDIM / 1024, 256>>>(x);

    const int gemm_smem = 2 * GSTG;   // 221184
    cudaFuncSetAttribute(moe_gemm_mma, cudaFuncAttributeMaxDynamicSharedMemorySize, gemm_smem);
    moe_gemm_mma<<<dim3(EDIM / GBN, TOKENS / 128, 3), 256, gemm_smem>>>(bq, bk, bv);

    const int attn_smem = KVOFF + 2 * KVSTG;  // 110592
    cudaFuncSetAttribute(attn_mma, cudaFuncAttributeMaxDynamicSharedMemorySize, attn_smem);
    attn_mma<<<dim3(SEQ / 128, MBATCH * NHEAD), 128, attn_smem>>>(out);
}

// round 6
// speedup vs baseline: 2.0431x; 1.0036x over previous
#include <cuda_runtime.h>
#include <cuda_bf16.h>
#include <cstdint>

#define TOKENS 8192
#define EDIM 1024
#define NHEAD 16
#define HDIM 64
#define SEQ 2048
#define MBATCH 4
#define KDIM 3072

// scratch
__device__ float g_gate[3 * TOKENS * 3];
__device__ __nv_bfloat16 g_Xhi[(size_t)TOKENS * EDIM];   // split x (shared across z)
__device__ __nv_bfloat16 g_Xlo[(size_t)TOKENS * EDIM];
__device__ __nv_bfloat16 g_Bhi[3ull * EDIM * KDIM];      // W^T hi [z][o][k]
__device__ __nv_bfloat16 g_Blo[3ull * EDIM * KDIM];
// QKV in (z, m*h, s, d) bf16 hi/lo
__device__ __nv_bfloat16 g_Qhi[(size_t)TOKENS * EDIM];
__device__ __nv_bfloat16 g_Qlo[(size_t)TOKENS * EDIM];
__device__ __nv_bfloat16 g_Khi[(size_t)TOKENS * EDIM];
__device__ __nv_bfloat16 g_Klo[(size_t)TOKENS * EDIM];
__device__ __nv_bfloat16 g_Vhi[(size_t)TOKENS * EDIM];
__device__ __nv_bfloat16 g_Vlo[(size_t)TOKENS * EDIM];

// ---------------- helpers ----------------
__device__ __forceinline__ uint32_t smem_u32(const void* p) {
    uint32_t a;
    asm("{ .reg .u64 t; cvta.to.shared.u64 t, %1; cvt.u32.u64 %0, t; }" : "=r"(a) : "l"(p));
    return a;
}
__device__ __forceinline__ void cp_async16(uint32_t dst, const void* src) {
    asm volatile("cp.async.cg.shared.global [%0], [%1], 16;" :: "r"(dst), "l"(src) : "memory");
}
__device__ __forceinline__ void cp_commit() {
    asm volatile("cp.async.commit_group;" ::: "memory");
}
__device__ __forceinline__ void cp_wait0() {
    asm volatile("cp.async.wait_group 0;" ::: "memory");
}
__device__ __forceinline__ void ldsm_x4(uint32_t& r0, uint32_t& r1, uint32_t& r2, uint32_t& r3,
                                        uint32_t addr) {
    asm volatile("ldmatrix.sync.aligned.m8n8.x4.shared.b16 {%0,%1,%2,%3}, [%4];"
                 : "=r"(r0), "=r"(r1), "=r"(r2), "=r"(r3) : "r"(addr));
}
__device__ __forceinline__ void ldsm_x4t(uint32_t& r0, uint32_t& r1, uint32_t& r2, uint32_t& r3,
                                         uint32_t addr) {
    asm volatile("ldmatrix.sync.aligned.m8n8.x4.trans.shared.b16 {%0,%1,%2,%3}, [%4];"
                 : "=r"(r0), "=r"(r1), "=r"(r2), "=r"(r3) : "r"(addr));
}
__device__ __forceinline__ void mma_bf16(float* d, const uint32_t* a, const uint32_t* b) {
    asm volatile("mma.sync.aligned.m16n8k16.row.col.f32.bf16.bf16.f32 "
                 "{%0,%1,%2,%3},{%4,%5,%6,%7},{%8,%9},{%0,%1,%2,%3};"
                 : "+f"(d[0]), "+f"(d[1]), "+f"(d[2]), "+f"(d[3])
                 : "r"(a[0]), "r"(a[1]), "r"(a[2]), "r"(a[3]), "r"(b[0]), "r"(b[1]));
}
__device__ __forceinline__ uint32_t pack_bf16x2(float lo, float hi) {
    __nv_bfloat162 h = __float22bfloat162_rn(make_float2(lo, hi));
    return *(uint32_t*)&h;
}

// ---------------------------------------------------------------------------
// Kernel 1: gates
// ---------------------------------------------------------------------------
__global__ void gates_kernel(const float* __restrict__ x,
                             const float* __restrict__ Wg0, const float* __restrict__ bg0,
                             const float* __restrict__ Wg1, const float* __restrict__ bg1,
                             const float* __restrict__ Wg2, const float* __restrict__ bg2)
{
    __shared__ float xs[EDIM];
    int t = blockIdx.x;
    int tid = threadIdx.x;
    const float4* xrow = (const float4*)(x + (size_t)t * EDIM);
    ((float4*)xs)[tid]       = xrow[tid];
    ((float4*)xs)[tid + 128] = xrow[tid + 128];
    __syncthreads();

    int w = tid >> 5;
    if (w < 3) {
        const float* Wg = (w == 0) ? Wg0 : (w == 1) ? Wg1 : Wg2;
        const float* bg = (w == 0) ? bg0 : (w == 1) ? bg1 : bg2;
        int lane = tid & 31;
        float a0 = 0.f, a1 = 0.f, a2 = 0.f;
        for (int e = lane; e < EDIM; e += 32) {
            float xv = xs[e];
            a0 += xv * Wg[e * 3 + 0];
            a1 += xv * Wg[e * 3 + 1];
            a2 += xv * Wg[e * 3 + 2];
        }
        #pragma unroll
        for (int o = 16; o; o >>= 1) {
            a0 += __shfl_xor_sync(0xffffffffu, a0, o);
            a1 += __shfl_xor_sync(0xffffffffu, a1, o);
            a2 += __shfl_xor_sync(0xffffffffu, a2, o);
        }
        if (lane == 0) {
            a0 += bg[0]; a1 += bg[1]; a2 += bg[2];
            float mx = fmaxf(a0, fmaxf(a1, a2));
            float e0 = __expf(a0 - mx), e1 = __expf(a1 - mx), e2 = __expf(a2 - mx);
            float inv = 1.0f / (e0 + e1 + e2);
            float* gp = g_gate + ((size_t)w * TOKENS + t) * 3;
            gp[0] = e0 * inv; gp[1] = e1 * inv; gp[2] = e2 * inv;
        }
    }
}

// ---------------------------------------------------------------------------
// Kernel 2a: X conversion — split x into bf16 hi/lo (no gate; shared by z)
// ---------------------------------------------------------------------------
__global__ void convertX_kernel(const float* __restrict__ x)
{
    size_t i = ((size_t)blockIdx.x * 256 + threadIdx.x) * 4;
    float4 v = *(const float4*)(x + i);
    float vv[4] = {v.x, v.y, v.z, v.w};
    #pragma unroll
    for (int j = 0; j < 4; j++) {
        __nv_bfloat16 hi = __float2bfloat16(vv[j]);
        g_Xhi[i + j] = hi;
        g_Xlo[i + j] = __float2bfloat16(vv[j] - __bfloat162float(hi));
    }
}

// ---------------------------------------------------------------------------
// Kernel 2b: W conversion — transpose to [z][o][k] and split hi/lo.
// ---------------------------------------------------------------------------
__global__ void convertW_kernel(const float* __restrict__ Wq,
                                const float* __restrict__ Wk,
                                const float* __restrict__ Wv)
{
    __shared__ float ts[32][33];
    int zn = blockIdx.z;
    int z = zn / 3, n = zn % 3;
    const float* W = ((z == 0) ? Wq : (z == 1) ? Wk : Wv) + (size_t)n * EDIM * EDIM;
    int e0 = blockIdx.y * 32, o0 = blockIdx.x * 32;
    int tx = threadIdx.x, ty = threadIdx.y;   // (32, 8)
    #pragma unroll
    for (int i = 0; i < 4; i++) {
        int e = e0 + ty + i * 8;
        ts[ty + i * 8][tx] = W[(size_t)e * EDIM + o0 + tx];
    }
    __syncthreads();
    #pragma unroll
    for (int i = 0; i < 4; i++) {
        int o = o0 + ty + i * 8;
        float v = ts[tx][ty + i * 8];
        __nv_bfloat16 hi = __float2bfloat16(v);
        __nv_bfloat16 lo = __float2bfloat16(v - __bfloat162float(hi));
        size_t idx = ((size_t)z * EDIM + o) * KDIM + n * EDIM + e0 + tx;
        g_Bhi[idx] = hi;
        g_Blo[idx] = lo;
    }
}

// ---------------------------------------------------------------------------
// Kernel 3: bf16x3 MoE GEMM, BM=128 BN=256 BK=64, 2-stage cp.async,
// Horner gate factorization. MMA emission in 3 dependency-free passes.
// ---------------------------------------------------------------------------
#define GBN 256
#define GP 144                    // row pitch bytes (64 bf16 + 16 pad)
#define AXM (128 * GP)            // 18432 per A matrix
#define BXM (256 * GP)            // 36864 per B matrix
#define GSTG (2 * AXM + 2 * BXM)  // 110592 per stage
#define GNST (KDIM / 64)          // 48
#define SEGST 16                  // stages per gate segment

__global__ void __launch_bounds__(256, 1) moe_gemm_mma(
    const float* __restrict__ bq, const float* __restrict__ bk, const float* __restrict__ bv)
{
    extern __shared__ char smem[];
    const uint32_t sb = smem_u32(smem);
    const int tid = threadIdx.x;
    const int lane = tid & 31, wid = tid >> 5;
    const int warpM = wid >> 2, warpN = wid & 3;
    const int z  = blockIdx.z;
    const int n0 = blockIdx.x * GBN;
    const int t0 = blockIdx.y * 128;

    const __nv_bfloat16* Xh = g_Xhi + (size_t)t0 * EDIM;
    const __nv_bfloat16* Xl = g_Xlo + (size_t)t0 * EDIM;
    const __nv_bfloat16* Bh = g_Bhi + ((size_t)z * EDIM + n0) * KDIM;
    const __nv_bfloat16* Bl = g_Blo + ((size_t)z * EDIM + n0) * KDIM;
    const float* gate = g_gate + (size_t)z * TOKENS * 3;

    const int lr = tid >> 1;          // 0..127
    const int lc = (tid & 1) * 4;     // chunk base 0 or 4

    float acc[4][8][4];
    #pragma unroll
    for (int mt = 0; mt < 4; mt++)
        #pragma unroll
        for (int nt = 0; nt < 8; nt++)
            #pragma unroll
            for (int q = 0; q < 4; q++) acc[mt][nt][q] = 0.f;

    #define GEMM_ISSUE(S) do {                                                  \
        int _k0 = (S) * 64;                                                     \
        int _e0 = _k0 & 1023;                                                   \
        uint32_t _st = sb + (uint32_t)((S) & 1) * GSTG;                         \
        _Pragma("unroll")                                                       \
        for (int j = 0; j < 4; j++) {                                           \
            int c = lc + j;                                                     \
            uint32_t d = _st + (uint32_t)lr * GP + c * 16;                      \
            size_t go = (size_t)lr * EDIM + _e0 + c * 8;                        \
            cp_async16(d,       Xh + go);                                       \
            cp_async16(d + AXM, Xl + go);                                       \
        }                                                                       \
        _Pragma("unroll")                                                       \
        for (int rr = 0; rr < 2; rr++) {                                        \
            int r = lr + rr * 128;                                              \
            _Pragma("unroll")                                                   \
            for (int j = 0; j < 4; j++) {                                       \
                int c = lc + j;                                                 \
                uint32_t d = _st + 2 * AXM + (uint32_t)r * GP + c * 16;         \
                size_t go = (size_t)r * KDIM + _k0 + c * 8;                     \
                cp_async16(d,       Bh + go);                                   \
                cp_async16(d + BXM, Bl + go);                                   \
            }                                                                   \
        }                                                                       \
        cp_commit();                                                            \
    } while (0)

    GEMM_ISSUE(0);

    const uint32_t a_off = (uint32_t)(warpM * 64 + (lane & 15)) * GP + ((lane >> 4) << 4);
    const uint32_t b_off = (uint32_t)(warpN * 64 + (lane & 7) + ((lane >> 4) << 3)) * GP
                         + (((lane >> 3) & 1) << 4);

    for (int s = 0; s < GNST; s++) {
        cp_wait0();                         // single group in flight: stage s
        __syncthreads();
        if (s + 1 < GNST) GEMM_ISSUE(s + 1);
        uint32_t stg = sb + (uint32_t)(s & 1) * GSTG;
        #pragma unroll
        for (int kc = 0; kc < 4; kc++) {
            uint32_t ko = kc * 32;
            uint32_t ah[4][4], al[4][4];
            #pragma unroll
            for (int mt = 0; mt < 4; mt++) {
                uint32_t ad = stg + a_off + (uint32_t)(mt * 16) * GP + ko;
                ldsm_x4(ah[mt][0], ah[mt][1], ah[mt][2], ah[mt][3], ad);
                ldsm_x4(al[mt][0], al[mt][1], al[mt][2], al[mt][3], ad + AXM);
            }
            uint32_t bh_[8][2], bl_[8][2];
            #pragma unroll
            for (int p = 0; p < 4; p++) {
                uint32_t bd = stg + 2 * AXM + b_off + (uint32_t)(p * 16) * GP + ko;
                ldsm_x4(bh_[2*p][0], bh_[2*p][1], bh_[2*p+1][0], bh_[2*p+1][1], bd);
                ldsm_x4(bl_[2*p][0], bl_[2*p][1], bl_[2*p+1][0], bl_[2*p+1][1], bd + BXM);
            }
            // 3 dependency-free passes: accumulator reuse distance = 32 MMAs
            #pragma unroll
            for (int mt = 0; mt < 4; mt++)
                #pragma unroll
                for (int nt = 0; nt < 8; nt++)
                    mma_bf16(acc[mt][nt], ah[mt], bh_[nt]);
            #pragma unroll
            for (int mt = 0; mt < 4; mt++)
                #pragma unroll
                for (int nt = 0; nt < 8; nt++)
                    mma_bf16(acc[mt][nt], ah[mt], bl_[nt]);
            #pragma unroll
            for (int mt = 0; mt < 4; mt++)
                #pragma unroll
                for (int nt = 0; nt < 8; nt++)
                    mma_bf16(acc[mt][nt], al[mt], bh_[nt]);
        }
        // Horner gate-segment boundary: acc *= g[n]/g[n+1]
        if (s == SEGST - 1 || s == 2 * SEGST - 1) {
            int n = (s == SEGST - 1) ? 0 : 1;
            #pragma unroll
            for (int mt = 0; mt < 4; mt++) {
                #pragma unroll
                for (int half = 0; half < 2; half++) {
                    int t = t0 + warpM * 64 + mt * 16 + (lane >> 2) + half * 8;
                    float r = __ldg(&gate[t * 3 + n]) / __ldg(&gate[t * 3 + n + 1]);
                    #pragma unroll
                    for (int nt = 0; nt < 8; nt++) {
                        acc[mt][nt][half * 2 + 0] *= r;
                        acc[mt][nt][half * 2 + 1] *= r;
                    }
                }
            }
        }
    }

    // epilogue: v = acc*g2 + sum g_i b_i; split to bf16 hi/lo; scatter (m,h,s,d)
    const float* bias = (z == 0) ? bq : (z == 1) ? bk : bv;
    __nv_bfloat16* ohi = (z == 0) ? g_Qhi : (z == 1) ? g_Khi : g_Vhi;
    __nv_bfloat16* olo = (z == 0) ? g_Qlo : (z == 1) ? g_Klo : g_Vlo;
    #pragma unroll
    for (int mt = 0; mt < 4; mt++) {
        #pragma unroll
        for (int half = 0; half < 2; half++) {
            int t = t0 + warpM * 64 + mt * 16 + (lane >> 2) + half * 8;
            float g0 = gate[t * 3 + 0], g1 = gate[t * 3 + 1], g2 = gate[t * 3 + 2];
            int mb = t >> 11, sr = t & 2047;
            #pragma unroll
            for (int nt = 0; nt < 8; nt++) {
                int co = n0 + warpN * 64 + nt * 8 + 2 * (lane & 3);
                float2 b0 = *(const float2*)&bias[co];
                float2 b1 = *(const float2*)&bias[EDIM + co];
                float2 b2 = *(const float2*)&bias[2 * EDIM + co];
                float v0 = acc[mt][nt][half*2+0] * g2 + g0*b0.x + g1*b1.x + g2*b2.x;
                float v1 = acc[mt][nt][half*2+1] * g2 + g0*b0.y + g1*b1.y + g2*b2.y;
                __nv_bfloat16 h0 = __float2bfloat16(v0);
                __nv_bfloat16 h1 = __float2bfloat16(v1);
                float l0 = v0 - __bfloat162float(h0);
                float l1 = v1 - __bfloat162float(h1);
                __nv_bfloat162 hp; hp.x = h0; hp.y = h1;
                __nv_bfloat162 lp; lp.x = __float2bfloat16(l0); lp.y = __float2bfloat16(l1);
                int h = co >> 6, d = co & 63;
                size_t off = (((size_t)mb * NHEAD + h) * SEQ + sr) * HDIM + d;
                *(__nv_bfloat162*)&ohi[off] = hp;
                *(__nv_bfloat162*)&olo[off] = lp;
            }
        }
    }
    #undef GEMM_ISSUE
}

// ---------------------------------------------------------------------------
// Kernel 4: flash attention via HMMA bf16x3, dependency-free MMA passes.
// ---------------------------------------------------------------------------
#define AP 144
#define AQMAT (128 * AP)
#define AKMAT (64 * AP)
#define KVSTG (4 * AKMAT)
#define KVOFF (2 * AQMAT)

__global__ void __launch_bounds__(128, 2) attn_mma(float* __restrict__ out)
{
    extern __shared__ char smem[];
    const uint32_t su = smem_u32(smem);
    const int tid = threadIdx.x;
    const int lane = tid & 31, wid = tid >> 5;
    const int bh = blockIdx.y;
    const int q0 = blockIdx.x * 128;

    const __nv_bfloat16* Qh = g_Qhi + ((size_t)bh * SEQ + q0) * HDIM;
    const __nv_bfloat16* Ql = g_Qlo + ((size_t)bh * SEQ + q0) * HDIM;
    const __nv_bfloat16* Khb = g_Khi + (size_t)bh * SEQ * HDIM;
    const __nv_bfloat16* Klb = g_Klo + (size_t)bh * SEQ * HDIM;
    const __nv_bfloat16* Vhb = g_Vhi + (size_t)bh * SEQ * HDIM;
    const __nv_bfloat16* Vlb = g_Vlo + (size_t)bh * SEQ * HDIM;

    const int lr = tid >> 1;
    const int lc = (tid & 1) * 4;

    #pragma unroll
    for (int rr = 0; rr < 2; rr++) {
        int r = lr + rr * 64;
        #pragma unroll
        for (int j = 0; j < 4; j++) {
            int c = lc + j;
            uint32_t d = su + (uint32_t)r * AP + c * 16;
            size_t go = (size_t)r * HDIM + c * 8;
            cp_async16(d,         Qh + go);
            cp_async16(d + AQMAT, Ql + go);
        }
    }
    cp_commit();

    #define ATTN_ISSUE(T) do {                                                  \
        uint32_t _st = su + KVOFF + (uint32_t)((T) & 1) * KVSTG;                \
        size_t _gb = (size_t)(T) * 64 * HDIM;                                   \
        _Pragma("unroll")                                                       \
        for (int j = 0; j < 4; j++) {                                           \
            int c = lc + j;                                                     \
            uint32_t d = _st + (uint32_t)lr * AP + c * 16;                      \
            size_t go = _gb + (size_t)lr * HDIM + c * 8;                        \
            cp_async16(d,             Khb + go);                                \
            cp_async16(d + AKMAT,     Klb + go);                                \
            cp_async16(d + 2*AKMAT,   Vhb + go);                                \
            cp_async16(d + 3*AKMAT,   Vlb + go);                                \
        }                                                                       \
        cp_commit();                                                            \
    } while (0)

    ATTN_ISSUE(0);

    float o_[2][8][4];
    float mrow[2][2], lrow[2][2];
    #pragma unroll
    for (int mt = 0; mt < 2; mt++) {
        #pragma unroll
        for (int nt = 0; nt < 8; nt++)
            #pragma unroll
            for (int q = 0; q < 4; q++) o_[mt][nt][q] = 0.f;
        mrow[mt][0] = -1e30f; mrow[mt][1] = -1e30f;
        lrow[mt][0] = 0.f;    lrow[mt][1] = 0.f;
    }

    const float sc = 0.125f;
    const uint32_t qa_off = (uint32_t)(wid * 32 + (lane & 15)) * AP + ((lane >> 4) << 4);
    const uint32_t kb_off = (uint32_t)((lane & 7) + ((lane >> 4) << 3)) * AP
                          + (((lane >> 3) & 1) << 4);
    const uint32_t vb_off = (uint32_t)((lane & 7) + (((lane >> 3) & 1) << 3)) * AP
                          + ((lane >> 4) << 4);

    for (int t = 0; t < SEQ / 64; t++) {
        cp_wait0();
        __syncthreads();
        if (t + 1 < SEQ / 64) ATTN_ISSUE(t + 1);
        uint32_t stg = su + KVOFF + (uint32_t)(t & 1) * KVSTG;

        float s_[2][8][4];
        #pragma unroll
        for (int mt = 0; mt < 2; mt++)
            #pragma unroll
            for (int nt = 0; nt < 8; nt++)
                #pragma unroll
                for (int q = 0; q < 4; q++) s_[mt][nt][q] = 0.f;

        #pragma unroll
        for (int c = 0; c < 4; c++) {
            uint32_t qh[2][4], ql[2][4];
            #pragma unroll
            for (int mt = 0; mt < 2; mt++) {
                uint32_t ad = su + qa_off + (uint32_t)(mt * 16) * AP + c * 32;
                ldsm_x4(qh[mt][0], qh[mt][1], qh[mt][2], qh[mt][3], ad);
                ldsm_x4(ql[mt][0], ql[mt][1], ql[mt][2], ql[mt][3], ad + AQMAT);
            }
            uint32_t kh[8][2], kl[8][2];
            #pragma unroll
            for (int p = 0; p < 4; p++) {
                uint32_t bd = stg + kb_off + (uint32_t)(p * 16) * AP + c * 32;
                ldsm_x4(kh[2*p][0], kh[2*p][1], kh[2*p+1][0], kh[2*p+1][1], bd);
                ldsm_x4(kl[2*p][0], kl[2*p][1], kl[2*p+1][0], kl[2*p+1][1], bd + AKMAT);
            }
            #pragma unroll
            for (int mt = 0; mt < 2; mt++)
                #pragma unroll
                for (int nt = 0; nt < 8; nt++)
                    mma_bf16(s_[mt][nt], qh[mt], kh[nt]);
            #pragma unroll
            for (int mt = 0; mt < 2; mt++)
                #pragma unroll
                for (int nt = 0; nt < 8; nt++)
                    mma_bf16(s_[mt][nt], qh[mt], kl[nt]);
            #pragma unroll
            for (int mt = 0; mt < 2; mt++)
                #pragma unroll
                for (int nt = 0; nt < 8; nt++)
                    mma_bf16(s_[mt][nt], ql[mt], kh[nt]);
        }

        uint32_t phi[2][8][2], plo[2][8][2];
        #pragma unroll
        for (int mt = 0; mt < 2; mt++) {
            float r0 = -1e30f, r1 = -1e30f;
            #pragma unroll
            for (int j = 0; j < 8; j++) {
                r0 = fmaxf(r0, fmaxf(s_[mt][j][0], s_[mt][j][1]));
                r1 = fmaxf(r1, fmaxf(s_[mt][j][2], s_[mt][j][3]));
            }
            r0 = fmaxf(r0, __shfl_xor_sync(0xffffffffu, r0, 1));
            r0 = fmaxf(r0, __shfl_xor_sync(0xffffffffu, r0, 2));
            r1 = fmaxf(r1, __shfl_xor_sync(0xffffffffu, r1, 1));
            r1 = fmaxf(r1, __shfl_xor_sync(0xffffffffu, r1, 2));
            float m0 = fmaxf(mrow[mt][0], r0 * sc);
            float m1 = fmaxf(mrow[mt][1], r1 * sc);
            float f0 = __expf(mrow[mt][0] - m0);
            float f1 = __expf(mrow[mt][1] - m1);
            mrow[mt][0] = m0; mrow[mt][1] = m1;
            float s0 = 0.f, s1 = 0.f;
            #pragma unroll
            for (int j = 0; j < 8; j++) {
                float p00 = __expf(__fmaf_rn(s_[mt][j][0], sc, -m0));
                float p01 = __expf(__fmaf_rn(s_[mt][j][1], sc, -m0));
                float p10 = __expf(__fmaf_rn(s_[mt][j][2], sc, -m1));
                float p11 = __expf(__fmaf_rn(s_[mt][j][3], sc, -m1));
                s0 += p00 + p01; s1 += p10 + p11;
                uint32_t h0 = pack_bf16x2(p00, p01);
                uint32_t h1 = pack_bf16x2(p10, p11);
                phi[mt][j][0] = h0; phi[mt][j][1] = h1;
                float2 hf0 = __bfloat1622float2(*(__nv_bfloat162*)&h0);
                float2 hf1 = __bfloat1622float2(*(__nv_bfloat162*)&h1);
                plo[mt][j][0] = pack_bf16x2(p00 - hf0.x, p01 - hf0.y);
                plo[mt][j][1] = pack_bf16x2(p10 - hf1.x, p11 - hf1.y);
            }
            s0 += __shfl_xor_sync(0xffffffffu, s0, 1);
            s0 += __shfl_xor_sync(0xffffffffu, s0, 2);
            s1 += __shfl_xor_sync(0xffffffffu, s1, 1);
            s1 += __shfl_xor_sync(0xffffffffu, s1, 2);
            lrow[mt][0] = lrow[mt][0] * f0 + s0;
            lrow[mt][1] = lrow[mt][1] * f1 + s1;
            #pragma unroll
            for (int j = 0; j < 8; j++) {
                o_[mt][j][0] *= f0; o_[mt][j][1] *= f0;
                o_[mt][j][2] *= f1; o_[mt][j][3] *= f1;
            }
        }

        #pragma unroll
        for (int kc = 0; kc < 4; kc++) {
            uint32_t vh[8][2], vl[8][2];
            #pragma unroll
            for (int dj = 0; dj < 4; dj++) {
                uint32_t vd = stg + 2 * AKMAT + vb_off
                            + (uint32_t)(kc * 16) * AP + dj * 32;
                ldsm_x4t(vh[2*dj][0], vh[2*dj][1], vh[2*dj+1][0], vh[2*dj+1][1], vd);
                ldsm_x4t(vl[2*dj][0], vl[2*dj][1], vl[2*dj+1][0], vl[2*dj+1][1], vd + AKMAT);
            }
            uint32_t pa[2][4], pb[2][4];
            #pragma unroll
            for (int mt = 0; mt < 2; mt++) {
                pa[mt][0] = phi[mt][2*kc][0]; pa[mt][1] = phi[mt][2*kc][1];
                pa[mt][2] = phi[mt][2*kc+1][0]; pa[mt][3] = phi[mt][2*kc+1][1];
                pb[mt][0] = plo[mt][2*kc][0]; pb[mt][1] = plo[mt][2*kc][1];
                pb[mt][2] = plo[mt][2*kc+1][0]; pb[mt][3] = plo[mt][2*kc+1][1];
            }
            #pragma unroll
            for (int mt = 0; mt < 2; mt++)
                #pragma unroll
                for (int nt = 0; nt < 8; nt++)
                    mma_bf16(o_[mt][nt], pa[mt], vh[nt]);
            #pragma unroll
            for (int mt = 0; mt < 2; mt++)
                #pragma unroll
                for (int nt = 0; nt < 8; nt++)
                    mma_bf16(o_[mt][nt], pa[mt], vl[nt]);
            #pragma unroll
            for (int mt = 0; mt < 2; mt++)
                #pragma unroll
                for (int nt = 0; nt < 8; nt++)
                    mma_bf16(o_[mt][nt], pb[mt], vh[nt]);
        }
    }

    int m = bh >> 4, h = bh & 15;
    #pragma unroll
    for (int mt = 0; mt < 2; mt++) {
        float inv0 = 1.0f / lrow[mt][0];
        float inv1 = 1.0f / lrow[mt][1];
        int r0 = q0 + wid * 32 + mt * 16 + (lane >> 2);
        int r1 = r0 + 8;
        #pragma unroll
        for (int j = 0; j < 8; j++) {
            int col = h * HDIM + j * 8 + 2 * (lane & 3);
            *(float2*)&out[((size_t)m * SEQ + r0) * EDIM + col] =
                make_float2(o_[mt][j][0] * inv0, o_[mt][j][1] * inv0);
            *(float2*)&out[((size_t)m * SEQ + r1) * EDIM + col] =
                make_float2(o_[mt][j][2] * inv1, o_[mt][j][3] * inv1);
        }
    }
    #undef ATTN_ISSUE
}

// ---------------------------------------------------------------------------
extern "C" void kernel_launch(void* const* d_in, const int* in_sizes, int n_in,
                              void* d_out, int out_size)
{
    (void)in_sizes; (void)n_in; (void)out_size;
    const float* x   = (const float*)d_in[0];
    const float* Wq  = (const float*)d_in[1];
    const float* bq  = (const float*)d_in[2];
    const float* Wgq = (const float*)d_in[3];
    const float* bgq = (const float*)d_in[4];
    const float* Wk  = (const float*)d_in[5];
    const float* bk  = (const float*)d_in[6];
    const float* Wgk = (const float*)d_in[7];
    const float* bgk = (const float*)d_in[8];
    const float* Wv  = (const float*)d_in[9];
    const float* bv  = (const float*)d_in[10];
    const float* Wgv = (const float*)d_in[11];
    const float* bgv = (const float*)d_in[12];
    float* out = (float*)d_out;

    gates_kernel<<<TOKENS, 128>>>(x, Wgq, bgq, Wgk, bgk, Wgv, bgv);
    convertW_kernel<<<dim3(32, 32, 9), dim3(32, 8)>>>(Wq, Wk, Wv);
    convertX_kernel<<<TOKENS * EDIM / 1024, 256>>>(x);

    const int gemm_smem = 2 * GSTG;   // 221184
    cudaFuncSetAttribute(moe_gemm_mma, cudaFuncAttributeMaxDynamicSharedMemorySize, gemm_smem);
    moe_gemm_mma<<<dim3(EDIM / GBN, TOKENS / 128, 3), 256, gemm_smem>>>(bq, bk, bv);

    const int attn_smem = KVOFF + 2 * KVSTG;  // 110592
    cudaFuncSetAttribute(attn_mma, cudaFuncAttributeMaxDynamicSharedMemorySize, attn_smem);
    attn_mma<<<dim3(SEQ / 128, MBATCH * NHEAD), 128, attn_smem>>>(out);
}

// round 7
// speedup vs baseline: 2.9647x; 1.4511x over previous
#include <cuda_runtime.h>
#include <cuda_fp16.h>
#include <cstdint>

#define TOKENS 8192
#define EDIM 1024
#define NHEAD 16
#define HDIM 64
#define SEQ 2048
#define MBATCH 4
#define KDIM 3072

// scratch
__device__ float g_gate[3 * TOKENS * 3];
__device__ __half g_Xh[(size_t)TOKENS * EDIM];      // x split hi (fp16)
__device__ __half g_Xl[(size_t)TOKENS * EDIM];      // x split lo
__device__ __half g_Wf[3ull * EDIM * KDIM];         // W^T single fp16 [z][o][k]
// QKV (m*h, s, d): Q split hi/lo, K/V single fp16
__device__ __half g_Qh[(size_t)TOKENS * EDIM];
__device__ __half g_Ql[(size_t)TOKENS * EDIM];
__device__ __half g_Kf[(size_t)TOKENS * EDIM];
__device__ __half g_Vf[(size_t)TOKENS * EDIM];

// ---------------- helpers ----------------
__device__ __forceinline__ uint32_t smem_u32(const void* p) {
    uint32_t a;
    asm("{ .reg .u64 t; cvta.to.shared.u64 t, %1; cvt.u32.u64 %0, t; }" : "=r"(a) : "l"(p));
    return a;
}
__device__ __forceinline__ void cp_async16(uint32_t dst, const void* src) {
    asm volatile("cp.async.cg.shared.global [%0], [%1], 16;" :: "r"(dst), "l"(src) : "memory");
}
__device__ __forceinline__ void cp_commit() {
    asm volatile("cp.async.commit_group;" ::: "memory");
}
__device__ __forceinline__ void cp_wait0() {
    asm volatile("cp.async.wait_group 0;" ::: "memory");
}
__device__ __forceinline__ void cp_wait1() {
    asm volatile("cp.async.wait_group 1;" ::: "memory");
}
__device__ __forceinline__ void ldsm_x4(uint32_t& r0, uint32_t& r1, uint32_t& r2, uint32_t& r3,
                                        uint32_t addr) {
    asm volatile("ldmatrix.sync.aligned.m8n8.x4.shared.b16 {%0,%1,%2,%3}, [%4];"
                 : "=r"(r0), "=r"(r1), "=r"(r2), "=r"(r3) : "r"(addr));
}
__device__ __forceinline__ void ldsm_x4t(uint32_t& r0, uint32_t& r1, uint32_t& r2, uint32_t& r3,
                                         uint32_t addr) {
    asm volatile("ldmatrix.sync.aligned.m8n8.x4.trans.shared.b16 {%0,%1,%2,%3}, [%4];"
                 : "=r"(r0), "=r"(r1), "=r"(r2), "=r"(r3) : "r"(addr));
}
__device__ __forceinline__ void mma_f16(float* d, const uint32_t* a, const uint32_t* b) {
    asm volatile("mma.sync.aligned.m16n8k16.row.col.f32.f16.f16.f32 "
                 "{%0,%1,%2,%3},{%4,%5,%6,%7},{%8,%9},{%0,%1,%2,%3};"
                 : "+f"(d[0]), "+f"(d[1]), "+f"(d[2]), "+f"(d[3])
                 : "r"(a[0]), "r"(a[1]), "r"(a[2]), "r"(a[3]), "r"(b[0]), "r"(b[1]));
}
__device__ __forceinline__ uint32_t pack_f16x2(float a, float b) {
    __half2 h = __float22half2_rn(make_float2(a, b));
    return *(uint32_t*)&h;
}

// ---------------------------------------------------------------------------
// Kernel 1: gates
// ---------------------------------------------------------------------------
__global__ void gates_kernel(const float* __restrict__ x,
                             const float* __restrict__ Wg0, const float* __restrict__ bg0,
                             const float* __restrict__ Wg1, const float* __restrict__ bg1,
                             const float* __restrict__ Wg2, const float* __restrict__ bg2)
{
    __shared__ float xs[EDIM];
    int t = blockIdx.x;
    int tid = threadIdx.x;
    const float4* xrow = (const float4*)(x + (size_t)t * EDIM);
    ((float4*)xs)[tid]       = xrow[tid];
    ((float4*)xs)[tid + 128] = xrow[tid + 128];
    __syncthreads();

    int w = tid >> 5;
    if (w < 3) {
        const float* Wg = (w == 0) ? Wg0 : (w == 1) ? Wg1 : Wg2;
        const float* bg = (w == 0) ? bg0 : (w == 1) ? bg1 : bg2;
        int lane = tid & 31;
        float a0 = 0.f, a1 = 0.f, a2 = 0.f;
        for (int e = lane; e < EDIM; e += 32) {
            float xv = xs[e];
            a0 += xv * Wg[e * 3 + 0];
            a1 += xv * Wg[e * 3 + 1];
            a2 += xv * Wg[e * 3 + 2];
        }
        #pragma unroll
        for (int o = 16; o; o >>= 1) {
            a0 += __shfl_xor_sync(0xffffffffu, a0, o);
            a1 += __shfl_xor_sync(0xffffffffu, a1, o);
            a2 += __shfl_xor_sync(0xffffffffu, a2, o);
        }
        if (lane == 0) {
            a0 += bg[0]; a1 += bg[1]; a2 += bg[2];
            float mx = fmaxf(a0, fmaxf(a1, a2));
            float e0 = __expf(a0 - mx), e1 = __expf(a1 - mx), e2 = __expf(a2 - mx);
            float inv = 1.0f / (e0 + e1 + e2);
            float* gp = g_gate + ((size_t)w * TOKENS + t) * 3;
            gp[0] = e0 * inv; gp[1] = e1 * inv; gp[2] = e2 * inv;
        }
    }
}

// ---------------------------------------------------------------------------
// Kernel 2a: X conversion — split x into fp16 hi/lo (exact to 2^-22)
// ---------------------------------------------------------------------------
__global__ void convertX_kernel(const float* __restrict__ x)
{
    size_t i = ((size_t)blockIdx.x * 256 + threadIdx.x) * 4;
    float4 v = *(const float4*)(x + i);
    float vv[4] = {v.x, v.y, v.z, v.w};
    #pragma unroll
    for (int j = 0; j < 4; j++) {
        __half hi = __float2half(vv[j]);
        g_Xh[i + j] = hi;
        g_Xl[i + j] = __float2half(vv[j] - __half2float(hi));
    }
}

// ---------------------------------------------------------------------------
// Kernel 2b: W conversion — transpose to [z][o][k], single fp16.
// ---------------------------------------------------------------------------
__global__ void convertW_kernel(const float* __restrict__ Wq,
                                const float* __restrict__ Wk,
                                const float* __restrict__ Wv)
{
    __shared__ float ts[32][33];
    int zn = blockIdx.z;
    int z = zn / 3, n = zn % 3;
    const float* W = ((z == 0) ? Wq : (z == 1) ? Wk : Wv) + (size_t)n * EDIM * EDIM;
    int e0 = blockIdx.y * 32, o0 = blockIdx.x * 32;
    int tx = threadIdx.x, ty = threadIdx.y;   // (32, 8)
    #pragma unroll
    for (int i = 0; i < 4; i++) {
        int e = e0 + ty + i * 8;
        ts[ty + i * 8][tx] = W[(size_t)e * EDIM + o0 + tx];
    }
    __syncthreads();
    #pragma unroll
    for (int i = 0; i < 4; i++) {
        int o = o0 + ty + i * 8;
        size_t idx = ((size_t)z * EDIM + o) * KDIM + n * EDIM + e0 + tx;
        g_Wf[idx] = __float2half(ts[tx][ty + i * 8]);
    }
}

// ---------------------------------------------------------------------------
// Kernel 3: fp16x2 MoE GEMM, BM=128 BN=256 BK=64, 3-stage cp.async,
// Horner gate factorization. C = (x_hi + x_lo) * fp16(W): 2 MMA passes.
// ---------------------------------------------------------------------------
#define GBN 256
#define GP 144                    // row pitch bytes (64 fp16 + 16 pad)
#define AXM (128 * GP)            // 18432 per A matrix
#define BXM (256 * GP)            // 36864 for B matrix
#define GSTG (2 * AXM + BXM)      // 73728 per stage
#define GNST (KDIM / 64)          // 48
#define SEGST 16                  // stages per gate segment

__global__ void __launch_bounds__(256, 1) moe_gemm_mma(
    const float* __restrict__ bq, const float* __restrict__ bk, const float* __restrict__ bv)
{
    extern __shared__ char smem[];
    const uint32_t sb = smem_u32(smem);
    const int tid = threadIdx.x;
    const int lane = tid & 31, wid = tid >> 5;
    const int warpM = wid >> 2, warpN = wid & 3;
    const int z  = blockIdx.z;
    const int n0 = blockIdx.x * GBN;
    const int t0 = blockIdx.y * 128;

    const __half* Xh = g_Xh + (size_t)t0 * EDIM;
    const __half* Xl = g_Xl + (size_t)t0 * EDIM;
    const __half* Wf = g_Wf + ((size_t)z * EDIM + n0) * KDIM;
    const float* gate = g_gate + (size_t)z * TOKENS * 3;

    const int lr = tid >> 1;          // 0..127
    const int lc = (tid & 1) * 4;     // chunk base 0 or 4

    float acc[4][8][4];
    #pragma unroll
    for (int mt = 0; mt < 4; mt++)
        #pragma unroll
        for (int nt = 0; nt < 8; nt++)
            #pragma unroll
            for (int q = 0; q < 4; q++) acc[mt][nt][q] = 0.f;

    #define GEMM_ISSUE(S) do {                                                  \
        int _k0 = (S) * 64;                                                     \
        int _e0 = _k0 & 1023;                                                   \
        uint32_t _st = sb + (uint32_t)((S) % 3) * GSTG;                         \
        _Pragma("unroll")                                                       \
        for (int j = 0; j < 4; j++) {                                           \
            int c = lc + j;                                                     \
            uint32_t d = _st + (uint32_t)lr * GP + c * 16;                      \
            size_t go = (size_t)lr * EDIM + _e0 + c * 8;                        \
            cp_async16(d,       Xh + go);                                       \
            cp_async16(d + AXM, Xl + go);                                       \
        }                                                                       \
        _Pragma("unroll")                                                       \
        for (int rr = 0; rr < 2; rr++) {                                        \
            int r = lr + rr * 128;                                              \
            _Pragma("unroll")                                                   \
            for (int j = 0; j < 4; j++) {                                       \
                int c = lc + j;                                                 \
                uint32_t d = _st + 2 * AXM + (uint32_t)r * GP + c * 16;         \
                size_t go = (size_t)r * KDIM + _k0 + c * 8;                     \
                cp_async16(d, Wf + go);                                         \
            }                                                                   \
        }                                                                       \
        cp_commit();                                                            \
    } while (0)

    GEMM_ISSUE(0);
    GEMM_ISSUE(1);

    const uint32_t a_off = (uint32_t)(warpM * 64 + (lane & 15)) * GP + ((lane >> 4) << 4);
    const uint32_t b_off = (uint32_t)(warpN * 64 + (lane & 7) + ((lane >> 4) << 3)) * GP
                         + (((lane >> 3) & 1) << 4);

    for (int s = 0; s < GNST; s++) {
        if (s + 1 < GNST) cp_wait1(); else cp_wait0();   // stage s complete
        __syncthreads();                                 // all warps done with buf (s+2)%3
        if (s + 2 < GNST) GEMM_ISSUE(s + 2);
        uint32_t stg = sb + (uint32_t)(s % 3) * GSTG;
        #pragma unroll
        for (int kc = 0; kc < 4; kc++) {
            uint32_t ko = kc * 32;
            uint32_t xh[4][4], xl[4][4];
            #pragma unroll
            for (int mt = 0; mt < 4; mt++) {
                uint32_t ad = stg + a_off + (uint32_t)(mt * 16) * GP + ko;
                ldsm_x4(xh[mt][0], xh[mt][1], xh[mt][2], xh[mt][3], ad);
                ldsm_x4(xl[mt][0], xl[mt][1], xl[mt][2], xl[mt][3], ad + AXM);
            }
            uint32_t bb[8][2];
            #pragma unroll
            for (int p = 0; p < 4; p++) {
                uint32_t bd = stg + 2 * AXM + b_off + (uint32_t)(p * 16) * GP + ko;
                ldsm_x4(bb[2*p][0], bb[2*p][1], bb[2*p+1][0], bb[2*p+1][1], bd);
            }
            #pragma unroll
            for (int mt = 0; mt < 4; mt++)
                #pragma unroll
                for (int nt = 0; nt < 8; nt++)
                    mma_f16(acc[mt][nt], xh[mt], bb[nt]);
            #pragma unroll
            for (int mt = 0; mt < 4; mt++)
                #pragma unroll
                for (int nt = 0; nt < 8; nt++)
                    mma_f16(acc[mt][nt], xl[mt], bb[nt]);
        }
        // Horner gate-segment boundary: acc *= g[n]/g[n+1]
        if (s == SEGST - 1 || s == 2 * SEGST - 1) {
            int n = (s == SEGST - 1) ? 0 : 1;
            #pragma unroll
            for (int mt = 0; mt < 4; mt++) {
                #pragma unroll
                for (int half = 0; half < 2; half++) {
                    int t = t0 + warpM * 64 + mt * 16 + (lane >> 2) + half * 8;
                    float r = __ldg(&gate[t * 3 + n]) / __ldg(&gate[t * 3 + n + 1]);
                    #pragma unroll
                    for (int nt = 0; nt < 8; nt++) {
                        acc[mt][nt][half * 2 + 0] *= r;
                        acc[mt][nt][half * 2 + 1] *= r;
                    }
                }
            }
        }
    }

    // epilogue: v = acc*g2 + sum g_i b_i; Q split hi/lo fp16, K/V single fp16
    const float* bias = (z == 0) ? bq : (z == 1) ? bk : bv;
    #pragma unroll
    for (int mt = 0; mt < 4; mt++) {
        #pragma unroll
        for (int half = 0; half < 2; half++) {
            int t = t0 + warpM * 64 + mt * 16 + (lane >> 2) + half * 8;
            float g0 = gate[t * 3 + 0], g1 = gate[t * 3 + 1], g2 = gate[t * 3 + 2];
            int mb = t >> 11, sr = t & 2047;
            #pragma unroll
            for (int nt = 0; nt < 8; nt++) {
                int co = n0 + warpN * 64 + nt * 8 + 2 * (lane & 3);
                float2 b0 = *(const float2*)&bias[co];
                float2 b1 = *(const float2*)&bias[EDIM + co];
                float2 b2 = *(const float2*)&bias[2 * EDIM + co];
                float v0 = acc[mt][nt][half*2+0] * g2 + g0*b0.x + g1*b1.x + g2*b2.x;
                float v1 = acc[mt][nt][half*2+1] * g2 + g0*b0.y + g1*b1.y + g2*b2.y;
                int h = co >> 6, d = co & 63;
                size_t off = (((size_t)mb * NHEAD + h) * SEQ + sr) * HDIM + d;
                if (z == 0) {
                    __half h0 = __float2half(v0);
                    __half h1 = __float2half(v1);
                    __half2 hp; hp.x = h0; hp.y = h1;
                    __half2 lp;
                    lp.x = __float2half(v0 - __half2float(h0));
                    lp.y = __float2half(v1 - __half2float(h1));
                    *(__half2*)&g_Qh[off] = hp;
                    *(__half2*)&g_Ql[off] = lp;
                } else {
                    __half2 hp = __float22half2_rn(make_float2(v0, v1));
                    __half* dst = (z == 1) ? g_Kf : g_Vf;
                    *(__half2*)&dst[off] = hp;
                }
            }
        }
    }
    #undef GEMM_ISSUE
}

// ---------------------------------------------------------------------------
// Kernel 4: flash attention fp16x2. S=(q_hi+q_lo)*k, O=(p_hi+p_lo)*v.
// K/V single fp16, 3-stage KV ring, 2 CTA/SM.
// ---------------------------------------------------------------------------
#define AP 144
#define AQMAT (128 * AP)          // 18432 per Q matrix
#define AKMAT (64 * AP)           // 9216 per K/V matrix
#define KVSTG (2 * AKMAT)         // 18432 per stage (K + V)
#define KVOFF (2 * AQMAT)         // 36864

__global__ void __launch_bounds__(128, 2) attn_mma(float* __restrict__ out)
{
    extern __shared__ char smem[];
    const uint32_t su = smem_u32(smem);
    const int tid = threadIdx.x;
    const int lane = tid & 31, wid = tid >> 5;
    const int bh = blockIdx.y;
    const int q0 = blockIdx.x * 128;

    const __half* Qh = g_Qh + ((size_t)bh * SEQ + q0) * HDIM;
    const __half* Ql = g_Ql + ((size_t)bh * SEQ + q0) * HDIM;
    const __half* Kb = g_Kf + (size_t)bh * SEQ * HDIM;
    const __half* Vb = g_Vf + (size_t)bh * SEQ * HDIM;

    const int lr = tid >> 1;          // 0..63
    const int lc = (tid & 1) * 4;

    // stage Q (hi/lo)
    #pragma unroll
    for (int rr = 0; rr < 2; rr++) {
        int r = lr + rr * 64;
        #pragma unroll
        for (int j = 0; j < 4; j++) {
            int c = lc + j;
            uint32_t d = su + (uint32_t)r * AP + c * 16;
            size_t go = (size_t)r * HDIM + c * 8;
            cp_async16(d,         Qh + go);
            cp_async16(d + AQMAT, Ql + go);
        }
    }
    cp_commit();      // group: Q (counts as one group before KV groups)

    #define ATTN_ISSUE(T) do {                                                  \
        uint32_t _st = su + KVOFF + (uint32_t)((T) % 3) * KVSTG;                \
        size_t _gb = (size_t)(T) * 64 * HDIM;                                   \
        _Pragma("unroll")                                                       \
        for (int j = 0; j < 4; j++) {                                           \
            int c = lc + j;                                                     \
            uint32_t d = _st + (uint32_t)lr * AP + c * 16;                      \
            size_t go = _gb + (size_t)lr * HDIM + c * 8;                        \
            cp_async16(d,         Kb + go);                                     \
            cp_async16(d + AKMAT, Vb + go);                                     \
        }                                                                       \
        cp_commit();                                                            \
    } while (0)

    ATTN_ISSUE(0);
    ATTN_ISSUE(1);

    float o_[2][8][4];
    float mrow[2][2], lrow[2][2];
    #pragma unroll
    for (int mt = 0; mt < 2; mt++) {
        #pragma unroll
        for (int nt = 0; nt < 8; nt++)
            #pragma unroll
            for (int q = 0; q < 4; q++) o_[mt][nt][q] = 0.f;
        mrow[mt][0] = -1e30f; mrow[mt][1] = -1e30f;
        lrow[mt][0] = 0.f;    lrow[mt][1] = 0.f;
    }

    const float sc = 0.125f;
    const uint32_t qa_off = (uint32_t)(wid * 32 + (lane & 15)) * AP + ((lane >> 4) << 4);
    const uint32_t kb_off = (uint32_t)((lane & 7) + ((lane >> 4) << 3)) * AP
                          + (((lane >> 3) & 1) << 4);
    const uint32_t vb_off = (uint32_t)((lane & 7) + (((lane >> 3) & 1) << 3)) * AP
                          + ((lane >> 4) << 4);

    const int NT = SEQ / 64;
    for (int t = 0; t < NT; t++) {
        if (t + 1 < NT) cp_wait1(); else cp_wait0();   // tile t (and Q) landed
        __syncthreads();
        if (t + 2 < NT) ATTN_ISSUE(t + 2);
        uint32_t stg = su + KVOFF + (uint32_t)(t % 3) * KVSTG;

        // S = (q_hi + q_lo) * k
        float s_[2][8][4];
        #pragma unroll
        for (int mt = 0; mt < 2; mt++)
            #pragma unroll
            for (int nt = 0; nt < 8; nt++)
                #pragma unroll
                for (int q = 0; q < 4; q++) s_[mt][nt][q] = 0.f;

        #pragma unroll
        for (int c = 0; c < 4; c++) {
            uint32_t qh[2][4], ql[2][4];
            #pragma unroll
            for (int mt = 0; mt < 2; mt++) {
                uint32_t ad = su + qa_off + (uint32_t)(mt * 16) * AP + c * 32;
                ldsm_x4(qh[mt][0], qh[mt][1], qh[mt][2], qh[mt][3], ad);
                ldsm_x4(ql[mt][0], ql[mt][1], ql[mt][2], ql[mt][3], ad + AQMAT);
            }
            uint32_t kk[8][2];
            #pragma unroll
            for (int p = 0; p < 4; p++) {
                uint32_t bd = stg + kb_off + (uint32_t)(p * 16) * AP + c * 32;
                ldsm_x4(kk[2*p][0], kk[2*p][1], kk[2*p+1][0], kk[2*p+1][1], bd);
            }
            #pragma unroll
            for (int mt = 0; mt < 2; mt++)
                #pragma unroll
                for (int nt = 0; nt < 8; nt++)
                    mma_f16(s_[mt][nt], qh[mt], kk[nt]);
            #pragma unroll
            for (int mt = 0; mt < 2; mt++)
                #pragma unroll
                for (int nt = 0; nt < 8; nt++)
                    mma_f16(s_[mt][nt], ql[mt], kk[nt]);
        }

        // online softmax + pack P hi/lo fp16
        uint32_t phi[2][8][2], plo[2][8][2];
        #pragma unroll
        for (int mt = 0; mt < 2; mt++) {
            float r0 = -1e30f, r1 = -1e30f;
            #pragma unroll
            for (int j = 0; j < 8; j++) {
                r0 = fmaxf(r0, fmaxf(s_[mt][j][0], s_[mt][j][1]));
                r1 = fmaxf(r1, fmaxf(s_[mt][j][2], s_[mt][j][3]));
            }
            r0 = fmaxf(r0, __shfl_xor_sync(0xffffffffu, r0, 1));
            r0 = fmaxf(r0, __shfl_xor_sync(0xffffffffu, r0, 2));
            r1 = fmaxf(r1, __shfl_xor_sync(0xffffffffu, r1, 1));
            r1 = fmaxf(r1, __shfl_xor_sync(0xffffffffu, r1, 2));
            float m0 = fmaxf(mrow[mt][0], r0 * sc);
            float m1 = fmaxf(mrow[mt][1], r1 * sc);
            float f0 = __expf(mrow[mt][0] - m0);
            float f1 = __expf(mrow[mt][1] - m1);
            mrow[mt][0] = m0; mrow[mt][1] = m1;
            float s0 = 0.f, s1 = 0.f;
            #pragma unroll
            for (int j = 0; j < 8; j++) {
                float p00 = __expf(__fmaf_rn(s_[mt][j][0], sc, -m0));
                float p01 = __expf(__fmaf_rn(s_[mt][j][1], sc, -m0));
                float p10 = __expf(__fmaf_rn(s_[mt][j][2], sc, -m1));
                float p11 = __expf(__fmaf_rn(s_[mt][j][3], sc, -m1));
                s0 += p00 + p01; s1 += p10 + p11;
                uint32_t h0 = pack_f16x2(p00, p01);
                uint32_t h1 = pack_f16x2(p10, p11);
                phi[mt][j][0] = h0; phi[mt][j][1] = h1;
                float2 hf0 = __half22float2(*(__half2*)&h0);
                float2 hf1 = __half22float2(*(__half2*)&h1);
                plo[mt][j][0] = pack_f16x2(p00 - hf0.x, p01 - hf0.y);
                plo[mt][j][1] = pack_f16x2(p10 - hf1.x, p11 - hf1.y);
            }
            s0 += __shfl_xor_sync(0xffffffffu, s0, 1);
            s0 += __shfl_xor_sync(0xffffffffu, s0, 2);
            s1 += __shfl_xor_sync(0xffffffffu, s1, 1);
            s1 += __shfl_xor_sync(0xffffffffu, s1, 2);
            lrow[mt][0] = lrow[mt][0] * f0 + s0;
            lrow[mt][1] = lrow[mt][1] * f1 + s1;
            #pragma unroll
            for (int j = 0; j < 8; j++) {
                o_[mt][j][0] *= f0; o_[mt][j][1] *= f0;
                o_[mt][j][2] *= f1; o_[mt][j][3] *= f1;
            }
        }

        // O += (p_hi + p_lo) * v
        #pragma unroll
        for (int kc = 0; kc < 4; kc++) {
            uint32_t vv[8][2];
            #pragma unroll
            for (int dj = 0; dj < 4; dj++) {
                uint32_t vd = stg + AKMAT + vb_off
                            + (uint32_t)(kc * 16) * AP + dj * 32;
                ldsm_x4t(vv[2*dj][0], vv[2*dj][1], vv[2*dj+1][0], vv[2*dj+1][1], vd);
            }
            uint32_t pa[2][4], pb[2][4];
            #pragma unroll
            for (int mt = 0; mt < 2; mt++) {
                pa[mt][0] = phi[mt][2*kc][0];   pa[mt][1] = phi[mt][2*kc][1];
                pa[mt][2] = phi[mt][2*kc+1][0]; pa[mt][3] = phi[mt][2*kc+1][1];
                pb[mt][0] = plo[mt][2*kc][0];   pb[mt][1] = plo[mt][2*kc][1];
                pb[mt][2] = plo[mt][2*kc+1][0]; pb[mt][3] = plo[mt][2*kc+1][1];
            }
            #pragma unroll
            for (int mt = 0; mt < 2; mt++)
                #pragma unroll
                for (int nt = 0; nt < 8; nt++)
                    mma_f16(o_[mt][nt], pa[mt], vv[nt]);
            #pragma unroll
            for (int mt = 0; mt < 2; mt++)
                #pragma unroll
                for (int nt = 0; nt < 8; nt++)
                    mma_f16(o_[mt][nt], pb[mt], vv[nt]);
        }
    }

    int m = bh >> 4, h = bh & 15;
    #pragma unroll
    for (int mt = 0; mt < 2; mt++) {
        float inv0 = 1.0f / lrow[mt][0];
        float inv1 = 1.0f / lrow[mt][1];
        int r0 = q0 + wid * 32 + mt * 16 + (lane >> 2);
        int r1 = r0 + 8;
        #pragma unroll
        for (int j = 0; j < 8; j++) {
            int col = h * HDIM + j * 8 + 2 * (lane & 3);
            *(float2*)&out[((size_t)m * SEQ + r0) * EDIM + col] =
                make_float2(o_[mt][j][0] * inv0, o_[mt][j][1] * inv0);
            *(float2*)&out[((size_t)m * SEQ + r1) * EDIM + col] =
                make_float2(o_[mt][j][2] * inv1, o_[mt][j][3] * inv1);
        }
    }
    #undef ATTN_ISSUE
}

// ---------------------------------------------------------------------------
extern "C" void kernel_launch(void* const* d_in, const int* in_sizes, int n_in,
                              void* d_out, int out_size)
{
    (void)in_sizes; (void)n_in; (void)out_size;
    const float* x   = (const float*)d_in[0];
    const float* Wq  = (const float*)d_in[1];
    const float* bq  = (const float*)d_in[2];
    const float* Wgq = (const float*)d_in[3];
    const float* bgq = (const float*)d_in[4];
    const float* Wk  = (const float*)d_in[5];
    const float* bk  = (const float*)d_in[6];
    const float* Wgk = (const float*)d_in[7];
    const float* bgk = (const float*)d_in[8];
    const float* Wv  = (const float*)d_in[9];
    const float* bv  = (const float*)d_in[10];
    const float* Wgv = (const float*)d_in[11];
    const float* bgv = (const float*)d_in[12];
    float* out = (float*)d_out;

    gates_kernel<<<TOKENS, 128>>>(x, Wgq, bgq, Wgk, bgk, Wgv, bgv);
    convertW_kernel<<<dim3(32, 32, 9), dim3(32, 8)>>>(Wq, Wk, Wv);
    convertX_kernel<<<TOKENS * EDIM / 1024, 256>>>(x);

    const int gemm_smem = 3 * GSTG;   // 221184
    cudaFuncSetAttribute(moe_gemm_mma, cudaFuncAttributeMaxDynamicSharedMemorySize, gemm_smem);
    moe_gemm_mma<<<dim3(EDIM / GBN, TOKENS / 128, 3), 256, gemm_smem>>>(bq, bk, bv);

    const int attn_smem = KVOFF + 3 * KVSTG;  // 92160
    cudaFuncSetAttribute(attn_mma, cudaFuncAttributeMaxDynamicSharedMemorySize, attn_smem);
    attn_mma<<<dim3(SEQ / 128, MBATCH * NHEAD), 128, attn_smem>>>(out);
}

// round 8
// speedup vs baseline: 3.1240x; 1.0537x over previous
#include <cuda_runtime.h>
#include <cuda_fp16.h>
#include <cstdint>

#define TOKENS 8192
#define EDIM 1024
#define NHEAD 16
#define HDIM 64
#define SEQ 2048
#define MBATCH 4
#define KDIM 3072

// scratch
__device__ float g_gate[3 * TOKENS * 3];
__device__ __half g_Xh[(size_t)TOKENS * EDIM];      // x split hi (fp16)
__device__ __half g_Xl[(size_t)TOKENS * EDIM];      // x split lo
__device__ __half g_Wf[3ull * EDIM * KDIM];         // W^T single fp16 [z][o][k]
// QKV (m*h, s, d): Q split hi/lo, K/V single fp16
__device__ __half g_Qh[(size_t)TOKENS * EDIM];
__device__ __half g_Ql[(size_t)TOKENS * EDIM];
__device__ __half g_Kf[(size_t)TOKENS * EDIM];
__device__ __half g_Vf[(size_t)TOKENS * EDIM];

// ---------------- helpers ----------------
__device__ __forceinline__ uint32_t smem_u32(const void* p) {
    uint32_t a;
    asm("{ .reg .u64 t; cvta.to.shared.u64 t, %1; cvt.u32.u64 %0, t; }" : "=r"(a) : "l"(p));
    return a;
}
__device__ __forceinline__ void cp_async16(uint32_t dst, const void* src) {
    asm volatile("cp.async.cg.shared.global [%0], [%1], 16;" :: "r"(dst), "l"(src) : "memory");
}
__device__ __forceinline__ void cp_commit() {
    asm volatile("cp.async.commit_group;" ::: "memory");
}
__device__ __forceinline__ void cp_wait0() {
    asm volatile("cp.async.wait_group 0;" ::: "memory");
}
__device__ __forceinline__ void ldsm_x4(uint32_t& r0, uint32_t& r1, uint32_t& r2, uint32_t& r3,
                                        uint32_t addr) {
    asm volatile("ldmatrix.sync.aligned.m8n8.x4.shared.b16 {%0,%1,%2,%3}, [%4];"
                 : "=r"(r0), "=r"(r1), "=r"(r2), "=r"(r3) : "r"(addr));
}
__device__ __forceinline__ void ldsm_x4t(uint32_t& r0, uint32_t& r1, uint32_t& r2, uint32_t& r3,
                                         uint32_t addr) {
    asm volatile("ldmatrix.sync.aligned.m8n8.x4.trans.shared.b16 {%0,%1,%2,%3}, [%4];"
                 : "=r"(r0), "=r"(r1), "=r"(r2), "=r"(r3) : "r"(addr));
}
__device__ __forceinline__ void mma_f16(float* d, const uint32_t* a, const uint32_t* b) {
    asm volatile("mma.sync.aligned.m16n8k16.row.col.f32.f16.f16.f32 "
                 "{%0,%1,%2,%3},{%4,%5,%6,%7},{%8,%9},{%0,%1,%2,%3};"
                 : "+f"(d[0]), "+f"(d[1]), "+f"(d[2]), "+f"(d[3])
                 : "r"(a[0]), "r"(a[1]), "r"(a[2]), "r"(a[3]), "r"(b[0]), "r"(b[1]));
}
__device__ __forceinline__ uint32_t pack_f16x2(float a, float b) {
    __half2 h = __float22half2_rn(make_float2(a, b));
    return *(uint32_t*)&h;
}

// ---------------------------------------------------------------------------
// Kernel 1: gates
// ---------------------------------------------------------------------------
__global__ void gates_kernel(const float* __restrict__ x,
                             const float* __restrict__ Wg0, const float* __restrict__ bg0,
                             const float* __restrict__ Wg1, const float* __restrict__ bg1,
                             const float* __restrict__ Wg2, const float* __restrict__ bg2)
{
    __shared__ float xs[EDIM];
    int t = blockIdx.x;
    int tid = threadIdx.x;
    const float4* xrow = (const float4*)(x + (size_t)t * EDIM);
    ((float4*)xs)[tid]       = xrow[tid];
    ((float4*)xs)[tid + 128] = xrow[tid + 128];
    __syncthreads();

    int w = tid >> 5;
    if (w < 3) {
        const float* Wg = (w == 0) ? Wg0 : (w == 1) ? Wg1 : Wg2;
        const float* bg = (w == 0) ? bg0 : (w == 1) ? bg1 : bg2;
        int lane = tid & 31;
        float a0 = 0.f, a1 = 0.f, a2 = 0.f;
        for (int e = lane; e < EDIM; e += 32) {
            float xv = xs[e];
            a0 += xv * Wg[e * 3 + 0];
            a1 += xv * Wg[e * 3 + 1];
            a2 += xv * Wg[e * 3 + 2];
        }
        #pragma unroll
        for (int o = 16; o; o >>= 1) {
            a0 += __shfl_xor_sync(0xffffffffu, a0, o);
            a1 += __shfl_xor_sync(0xffffffffu, a1, o);
            a2 += __shfl_xor_sync(0xffffffffu, a2, o);
        }
        if (lane == 0) {
            a0 += bg[0]; a1 += bg[1]; a2 += bg[2];
            float mx = fmaxf(a0, fmaxf(a1, a2));
            float e0 = __expf(a0 - mx), e1 = __expf(a1 - mx), e2 = __expf(a2 - mx);
            float inv = 1.0f / (e0 + e1 + e2);
            float* gp = g_gate + ((size_t)w * TOKENS + t) * 3;
            gp[0] = e0 * inv; gp[1] = e1 * inv; gp[2] = e2 * inv;
        }
    }
}

// ---------------------------------------------------------------------------
// Kernel 2a: X conversion — split x into fp16 hi/lo (exact to 2^-22)
// ---------------------------------------------------------------------------
__global__ void convertX_kernel(const float* __restrict__ x)
{
    size_t i = ((size_t)blockIdx.x * 256 + threadIdx.x) * 4;
    float4 v = *(const float4*)(x + i);
    float vv[4] = {v.x, v.y, v.z, v.w};
    #pragma unroll
    for (int j = 0; j < 4; j++) {
        __half hi = __float2half(vv[j]);
        g_Xh[i + j] = hi;
        g_Xl[i + j] = __float2half(vv[j] - __half2float(hi));
    }
}

// ---------------------------------------------------------------------------
// Kernel 2b: W conversion — transpose to [z][o][k], single fp16.
// ---------------------------------------------------------------------------
__global__ void convertW_kernel(const float* __restrict__ Wq,
                                const float* __restrict__ Wk,
                                const float* __restrict__ Wv)
{
    __shared__ float ts[32][33];
    int zn = blockIdx.z;
    int z = zn / 3, n = zn % 3;
    const float* W = ((z == 0) ? Wq : (z == 1) ? Wk : Wv) + (size_t)n * EDIM * EDIM;
    int e0 = blockIdx.y * 32, o0 = blockIdx.x * 32;
    int tx = threadIdx.x, ty = threadIdx.y;   // (32, 8)
    #pragma unroll
    for (int i = 0; i < 4; i++) {
        int e = e0 + ty + i * 8;
        ts[ty + i * 8][tx] = W[(size_t)e * EDIM + o0 + tx];
    }
    __syncthreads();
    #pragma unroll
    for (int i = 0; i < 4; i++) {
        int o = o0 + ty + i * 8;
        size_t idx = ((size_t)z * EDIM + o) * KDIM + n * EDIM + e0 + tx;
        g_Wf[idx] = __float2half(ts[tx][ty + i * 8]);
    }
}

// ---------------------------------------------------------------------------
// Kernel 3: fp16x2 MoE GEMM, BM=128 BN=128 BK=64, 2-stage cp.async,
// 2 CTAs/SM (4 warps/SMSP) to fill the tensor pipe.
// 8 warps (2x4), warp tile 64x32. Horner gate factorization.
// ---------------------------------------------------------------------------
#define GBN 128
#define GP 144                    // row pitch bytes (64 fp16 + 16 pad)
#define AXM (128 * GP)            // 18432 per matrix (A hi, A lo, B)
#define GSTG (3 * AXM)            // 55296 per stage
#define GNST (KDIM / 64)          // 48
#define SEGST 16                  // stages per gate segment

__global__ void __launch_bounds__(256, 2) moe_gemm_mma(
    const float* __restrict__ bq, const float* __restrict__ bk, const float* __restrict__ bv)
{
    extern __shared__ char smem[];
    const uint32_t sb = smem_u32(smem);
    const int tid = threadIdx.x;
    const int lane = tid & 31, wid = tid >> 5;
    const int warpM = wid >> 2, warpN = wid & 3;
    const int z  = blockIdx.z;
    const int n0 = blockIdx.x * GBN;
    const int t0 = blockIdx.y * 128;

    const __half* Xh = g_Xh + (size_t)t0 * EDIM;
    const __half* Xl = g_Xl + (size_t)t0 * EDIM;
    const __half* Wf = g_Wf + ((size_t)z * EDIM + n0) * KDIM;
    const float* gate = g_gate + (size_t)z * TOKENS * 3;

    const int lr = tid >> 1;          // 0..127
    const int lc = (tid & 1) * 4;     // chunk base 0 or 4

    float acc[4][4][4];
    #pragma unroll
    for (int mt = 0; mt < 4; mt++)
        #pragma unroll
        for (int nt = 0; nt < 4; nt++)
            #pragma unroll
            for (int q = 0; q < 4; q++) acc[mt][nt][q] = 0.f;

    #define GEMM_ISSUE(S) do {                                                  \
        int _k0 = (S) * 64;                                                     \
        int _e0 = _k0 & 1023;                                                   \
        uint32_t _st = sb + (uint32_t)((S) & 1) * GSTG;                         \
        _Pragma("unroll")                                                       \
        for (int j = 0; j < 4; j++) {                                           \
            int c = lc + j;                                                     \
            uint32_t d = _st + (uint32_t)lr * GP + c * 16;                      \
            size_t goA = (size_t)lr * EDIM + _e0 + c * 8;                       \
            size_t goB = (size_t)lr * KDIM + _k0 + c * 8;                       \
            cp_async16(d,           Xh + goA);                                  \
            cp_async16(d + AXM,     Xl + goA);                                  \
            cp_async16(d + 2 * AXM, Wf + goB);                                  \
        }                                                                       \
        cp_commit();                                                            \
    } while (0)

    GEMM_ISSUE(0);

    const uint32_t a_off = (uint32_t)(warpM * 64 + (lane & 15)) * GP + ((lane >> 4) << 4);
    const uint32_t b_off = (uint32_t)(warpN * 32 + (lane & 7) + ((lane >> 4) << 3)) * GP
                         + (((lane >> 3) & 1) << 4);

    for (int s = 0; s < GNST; s++) {
        cp_wait0();                         // stage s landed
        __syncthreads();
        if (s + 1 < GNST) GEMM_ISSUE(s + 1);
        uint32_t stg = sb + (uint32_t)(s & 1) * GSTG;
        #pragma unroll
        for (int kc = 0; kc < 4; kc++) {
            uint32_t ko = kc * 32;
            uint32_t xh[4][4], xl[4][4];
            #pragma unroll
            for (int mt = 0; mt < 4; mt++) {
                uint32_t ad = stg + a_off + (uint32_t)(mt * 16) * GP + ko;
                ldsm_x4(xh[mt][0], xh[mt][1], xh[mt][2], xh[mt][3], ad);
                ldsm_x4(xl[mt][0], xl[mt][1], xl[mt][2], xl[mt][3], ad + AXM);
            }
            uint32_t bb[4][2];
            #pragma unroll
            for (int p = 0; p < 2; p++) {
                uint32_t bd = stg + 2 * AXM + b_off + (uint32_t)(p * 16) * GP + ko;
                ldsm_x4(bb[2*p][0], bb[2*p][1], bb[2*p+1][0], bb[2*p+1][1], bd);
            }
            #pragma unroll
            for (int mt = 0; mt < 4; mt++)
                #pragma unroll
                for (int nt = 0; nt < 4; nt++)
                    mma_f16(acc[mt][nt], xh[mt], bb[nt]);
            #pragma unroll
            for (int mt = 0; mt < 4; mt++)
                #pragma unroll
                for (int nt = 0; nt < 4; nt++)
                    mma_f16(acc[mt][nt], xl[mt], bb[nt]);
        }
        // Horner gate-segment boundary: acc *= g[n]/g[n+1]
        if (s == SEGST - 1 || s == 2 * SEGST - 1) {
            int n = (s == SEGST - 1) ? 0 : 1;
            #pragma unroll
            for (int mt = 0; mt < 4; mt++) {
                #pragma unroll
                for (int half = 0; half < 2; half++) {
                    int t = t0 + warpM * 64 + mt * 16 + (lane >> 2) + half * 8;
                    float r = __ldg(&gate[t * 3 + n]) / __ldg(&gate[t * 3 + n + 1]);
                    #pragma unroll
                    for (int nt = 0; nt < 4; nt++) {
                        acc[mt][nt][half * 2 + 0] *= r;
                        acc[mt][nt][half * 2 + 1] *= r;
                    }
                }
            }
        }
    }

    // epilogue: v = acc*g2 + sum g_i b_i; Q split hi/lo fp16, K/V single fp16
    const float* bias = (z == 0) ? bq : (z == 1) ? bk : bv;
    #pragma unroll
    for (int mt = 0; mt < 4; mt++) {
        #pragma unroll
        for (int half = 0; half < 2; half++) {
            int t = t0 + warpM * 64 + mt * 16 + (lane >> 2) + half * 8;
            float g0 = gate[t * 3 + 0], g1 = gate[t * 3 + 1], g2 = gate[t * 3 + 2];
            int mb = t >> 11, sr = t & 2047;
            #pragma unroll
            for (int nt = 0; nt < 4; nt++) {
                int co = n0 + warpN * 32 + nt * 8 + 2 * (lane & 3);
                float2 b0 = *(const float2*)&bias[co];
                float2 b1 = *(const float2*)&bias[EDIM + co];
                float2 b2 = *(const float2*)&bias[2 * EDIM + co];
                float v0 = acc[mt][nt][half*2+0] * g2 + g0*b0.x + g1*b1.x + g2*b2.x;
                float v1 = acc[mt][nt][half*2+1] * g2 + g0*b0.y + g1*b1.y + g2*b2.y;
                int h = co >> 6, d = co & 63;
                size_t off = (((size_t)mb * NHEAD + h) * SEQ + sr) * HDIM + d;
                if (z == 0) {
                    __half h0 = __float2half(v0);
                    __half h1 = __float2half(v1);
                    __half2 hp; hp.x = h0; hp.y = h1;
                    __half2 lp;
                    lp.x = __float2half(v0 - __half2float(h0));
                    lp.y = __float2half(v1 - __half2float(h1));
                    *(__half2*)&g_Qh[off] = hp;
                    *(__half2*)&g_Ql[off] = lp;
                } else {
                    __half2 hp = __float22half2_rn(make_float2(v0, v1));
                    __half* dst = (z == 1) ? g_Kf : g_Vf;
                    *(__half2*)&dst[off] = hp;
                }
            }
        }
    }
    #undef GEMM_ISSUE
}

// ---------------------------------------------------------------------------
// Kernel 4: flash attention fp16x2, 2-stage KV ring, 3 CTAs/SM.
// ---------------------------------------------------------------------------
#define AP 144
#define AQMAT (128 * AP)          // 18432 per Q matrix
#define AKMAT (64 * AP)           // 9216 per K/V matrix
#define KVSTG (2 * AKMAT)         // 18432 per stage (K + V)
#define KVOFF (2 * AQMAT)         // 36864

__global__ void __launch_bounds__(128, 3) attn_mma(float* __restrict__ out)
{
    extern __shared__ char smem[];
    const uint32_t su = smem_u32(smem);
    const int tid = threadIdx.x;
    const int lane = tid & 31, wid = tid >> 5;
    const int bh = blockIdx.y;
    const int q0 = blockIdx.x * 128;

    const __half* Qh = g_Qh + ((size_t)bh * SEQ + q0) * HDIM;
    const __half* Ql = g_Ql + ((size_t)bh * SEQ + q0) * HDIM;
    const __half* Kb = g_Kf + (size_t)bh * SEQ * HDIM;
    const __half* Vb = g_Vf + (size_t)bh * SEQ * HDIM;

    const int lr = tid >> 1;          // 0..63
    const int lc = (tid & 1) * 4;

    // stage Q (hi/lo)
    #pragma unroll
    for (int rr = 0; rr < 2; rr++) {
        int r = lr + rr * 64;
        #pragma unroll
        for (int j = 0; j < 4; j++) {
            int c = lc + j;
            uint32_t d = su + (uint32_t)r * AP + c * 16;
            size_t go = (size_t)r * HDIM + c * 8;
            cp_async16(d,         Qh + go);
            cp_async16(d + AQMAT, Ql + go);
        }
    }
    cp_commit();

    #define ATTN_ISSUE(T) do {                                                  \
        uint32_t _st = su + KVOFF + (uint32_t)((T) & 1) * KVSTG;                \
        size_t _gb = (size_t)(T) * 64 * HDIM;                                   \
        _Pragma("unroll")                                                       \
        for (int j = 0; j < 4; j++) {                                           \
            int c = lc + j;                                                     \
            uint32_t d = _st + (uint32_t)lr * AP + c * 16;                      \
            size_t go = _gb + (size_t)lr * HDIM + c * 8;                        \
            cp_async16(d,         Kb + go);                                     \
            cp_async16(d + AKMAT, Vb + go);                                     \
        }                                                                       \
        cp_commit();                                                            \
    } while (0)

    ATTN_ISSUE(0);

    float o_[2][8][4];
    float mrow[2][2], lrow[2][2];
    #pragma unroll
    for (int mt = 0; mt < 2; mt++) {
        #pragma unroll
        for (int nt = 0; nt < 8; nt++)
            #pragma unroll
            for (int q = 0; q < 4; q++) o_[mt][nt][q] = 0.f;
        mrow[mt][0] = -1e30f; mrow[mt][1] = -1e30f;
        lrow[mt][0] = 0.f;    lrow[mt][1] = 0.f;
    }

    const float sc = 0.125f;
    const uint32_t qa_off = (uint32_t)(wid * 32 + (lane & 15)) * AP + ((lane >> 4) << 4);
    const uint32_t kb_off = (uint32_t)((lane & 7) + ((lane >> 4) << 3)) * AP
                          + (((lane >> 3) & 1) << 4);
    const uint32_t vb_off = (uint32_t)((lane & 7) + (((lane >> 3) & 1) << 3)) * AP
                          + ((lane >> 4) << 4);

    const int NT = SEQ / 64;
    for (int t = 0; t < NT; t++) {
        cp_wait0();                        // tile t (and Q) landed
        __syncthreads();
        if (t + 1 < NT) ATTN_ISSUE(t + 1);
        uint32_t stg = su + KVOFF + (uint32_t)(t & 1) * KVSTG;

        // S = (q_hi + q_lo) * k
        float s_[2][8][4];
        #pragma unroll
        for (int mt = 0; mt < 2; mt++)
            #pragma unroll
            for (int nt = 0; nt < 8; nt++)
                #pragma unroll
                for (int q = 0; q < 4; q++) s_[mt][nt][q] = 0.f;

        #pragma unroll
        for (int c = 0; c < 4; c++) {
            uint32_t qh[2][4], ql[2][4];
            #pragma unroll
            for (int mt = 0; mt < 2; mt++) {
                uint32_t ad = su + qa_off + (uint32_t)(mt * 16) * AP + c * 32;
                ldsm_x4(qh[mt][0], qh[mt][1], qh[mt][2], qh[mt][3], ad);
                ldsm_x4(ql[mt][0], ql[mt][1], ql[mt][2], ql[mt][3], ad + AQMAT);
            }
            uint32_t kk[8][2];
            #pragma unroll
            for (int p = 0; p < 4; p++) {
                uint32_t bd = stg + kb_off + (uint32_t)(p * 16) * AP + c * 32;
                ldsm_x4(kk[2*p][0], kk[2*p][1], kk[2*p+1][0], kk[2*p+1][1], bd);
            }
            #pragma unroll
            for (int mt = 0; mt < 2; mt++)
                #pragma unroll
                for (int nt = 0; nt < 8; nt++)
                    mma_f16(s_[mt][nt], qh[mt], kk[nt]);
            #pragma unroll
            for (int mt = 0; mt < 2; mt++)
                #pragma unroll
                for (int nt = 0; nt < 8; nt++)
                    mma_f16(s_[mt][nt], ql[mt], kk[nt]);
        }

        // online softmax + pack P hi/lo fp16
        uint32_t phi[2][8][2], plo[2][8][2];
        #pragma unroll
        for (int mt = 0; mt < 2; mt++) {
            float r0 = -1e30f, r1 = -1e30f;
            #pragma unroll
            for (int j = 0; j < 8; j++) {
                r0 = fmaxf(r0, fmaxf(s_[mt][j][0], s_[mt][j][1]));
                r1 = fmaxf(r1, fmaxf(s_[mt][j][2], s_[mt][j][3]));
            }
            r0 = fmaxf(r0, __shfl_xor_sync(0xffffffffu, r0, 1));
            r0 = fmaxf(r0, __shfl_xor_sync(0xffffffffu, r0, 2));
            r1 = fmaxf(r1, __shfl_xor_sync(0xffffffffu, r1, 1));
            r1 = fmaxf(r1, __shfl_xor_sync(0xffffffffu, r1, 2));
            float m0 = fmaxf(mrow[mt][0], r0 * sc);
            float m1 = fmaxf(mrow[mt][1], r1 * sc);
            float f0 = __expf(mrow[mt][0] - m0);
            float f1 = __expf(mrow[mt][1] - m1);
            mrow[mt][0] = m0; mrow[mt][1] = m1;
            float s0 = 0.f, s1 = 0.f;
            #pragma unroll
            for (int j = 0; j < 8; j++) {
                float p00 = __expf(__fmaf_rn(s_[mt][j][0], sc, -m0));
                float p01 = __expf(__fmaf_rn(s_[mt][j][1], sc, -m0));
                float p10 = __expf(__fmaf_rn(s_[mt][j][2], sc, -m1));
                float p11 = __expf(__fmaf_rn(s_[mt][j][3], sc, -m1));
                s0 += p00 + p01; s1 += p10 + p11;
                uint32_t h0 = pack_f16x2(p00, p01);
                uint32_t h1 = pack_f16x2(p10, p11);
                phi[mt][j][0] = h0; phi[mt][j][1] = h1;
                float2 hf0 = __half22float2(*(__half2*)&h0);
                float2 hf1 = __half22float2(*(__half2*)&h1);
                plo[mt][j][0] = pack_f16x2(p00 - hf0.x, p01 - hf0.y);
                plo[mt][j][1] = pack_f16x2(p10 - hf1.x, p11 - hf1.y);
            }
            s0 += __shfl_xor_sync(0xffffffffu, s0, 1);
            s0 += __shfl_xor_sync(0xffffffffu, s0, 2);
            s1 += __shfl_xor_sync(0xffffffffu, s1, 1);
            s1 += __shfl_xor_sync(0xffffffffu, s1, 2);
            lrow[mt][0] = lrow[mt][0] * f0 + s0;
            lrow[mt][1] = lrow[mt][1] * f1 + s1;
            #pragma unroll
            for (int j = 0; j < 8; j++) {
                o_[mt][j][0] *= f0; o_[mt][j][1] *= f0;
                o_[mt][j][2] *= f1; o_[mt][j][3] *= f1;
            }
        }

        // O += (p_hi + p_lo) * v
        #pragma unroll
        for (int kc = 0; kc < 4; kc++) {
            uint32_t vv[8][2];
            #pragma unroll
            for (int dj = 0; dj < 4; dj++) {
                uint32_t vd = stg + AKMAT + vb_off
                            + (uint32_t)(kc * 16) * AP + dj * 32;
                ldsm_x4t(vv[2*dj][0], vv[2*dj][1], vv[2*dj+1][0], vv[2*dj+1][1], vd);
            }
            uint32_t pa[2][4], pb[2][4];
            #pragma unroll
            for (int mt = 0; mt < 2; mt++) {
                pa[mt][0] = phi[mt][2*kc][0];   pa[mt][1] = phi[mt][2*kc][1];
                pa[mt][2] = phi[mt][2*kc+1][0]; pa[mt][3] = phi[mt][2*kc+1][1];
                pb[mt][0] = plo[mt][2*kc][0];   pb[mt][1] = plo[mt][2*kc][1];
                pb[mt][2] = plo[mt][2*kc+1][0]; pb[mt][3] = plo[mt][2*kc+1][1];
            }
            #pragma unroll
            for (int mt = 0; mt < 2; mt++)
                #pragma unroll
                for (int nt = 0; nt < 8; nt++)
                    mma_f16(o_[mt][nt], pa[mt], vv[nt]);
            #pragma unroll
            for (int mt = 0; mt < 2; mt++)
                #pragma unroll
                for (int nt = 0; nt < 8; nt++)
                    mma_f16(o_[mt][nt], pb[mt], vv[nt]);
        }
    }

    int m = bh >> 4, h = bh & 15;
    #pragma unroll
    for (int mt = 0; mt < 2; mt++) {
        float inv0 = 1.0f / lrow[mt][0];
        float inv1 = 1.0f / lrow[mt][1];
        int r0 = q0 + wid * 32 + mt * 16 + (lane >> 2);
        int r1 = r0 + 8;
        #pragma unroll
        for (int j = 0; j < 8; j++) {
            int col = h * HDIM + j * 8 + 2 * (lane & 3);
            *(float2*)&out[((size_t)m * SEQ + r0) * EDIM + col] =
                make_float2(o_[mt][j][0] * inv0, o_[mt][j][1] * inv0);
            *(float2*)&out[((size_t)m * SEQ + r1) * EDIM + col] =
                make_float2(o_[mt][j][2] * inv1, o_[mt][j][3] * inv1);
        }
    }
    #undef ATTN_ISSUE
}

// ---------------------------------------------------------------------------
extern "C" void kernel_launch(void* const* d_in, const int* in_sizes, int n_in,
                              void* d_out, int out_size)
{
    (void)in_sizes; (void)n_in; (void)out_size;
    const float* x   = (const float*)d_in[0];
    const float* Wq  = (const float*)d_in[1];
    const float* bq  = (const float*)d_in[2];
    const float* Wgq = (const float*)d_in[3];
    const float* bgq = (const float*)d_in[4];
    const float* Wk  = (const float*)d_in[5];
    const float* bk  = (const float*)d_in[6];
    const float* Wgk = (const float*)d_in[7];
    const float* bgk = (const float*)d_in[8];
    const float* Wv  = (const float*)d_in[9];
    const float* bv  = (const float*)d_in[10];
    const float* Wgv = (const float*)d_in[11];
    const float* bgv = (const float*)d_in[12];
    float* out = (float*)d_out;

    gates_kernel<<<TOKENS, 128>>>(x, Wgq, bgq, Wgk, bgk, Wgv, bgv);
    convertW_kernel<<<dim3(32, 32, 9), dim3(32, 8)>>>(Wq, Wk, Wv);
    convertX_kernel<<<TOKENS * EDIM / 1024, 256>>>(x);

    const int gemm_smem = 2 * GSTG;   // 110592 per CTA, 2 CTAs/SM
    cudaFuncSetAttribute(moe_gemm_mma, cudaFuncAttributeMaxDynamicSharedMemorySize, gemm_smem);
    moe_gemm_mma<<<dim3(EDIM / GBN, TOKENS / 128, 3), 256, gemm_smem>>>(bq, bk, bv);

    const int attn_smem = KVOFF + 2 * KVSTG;  // 73728 per CTA, 3 CTAs/SM
    cudaFuncSetAttribute(attn_mma, cudaFuncAttributeMaxDynamicSharedMemorySize, attn_smem);
    attn_mma<<<dim3(SEQ / 128, MBATCH * NHEAD), 128, attn_smem>>>(out);
}

// round 9
// speedup vs baseline: 3.1314x; 1.0024x over previous
#include <cuda_runtime.h>
#include <cuda_fp16.h>
#include <cstdint>

#define TOKENS 8192
#define EDIM 1024
#define NHEAD 16
#define HDIM 64
#define SEQ 2048
#define MBATCH 4
#define KDIM 3072

#define LOSCALE 1024.0f
#define INVLOSCALE 0.0009765625f

// scratch
__device__ float g_gate[3 * TOKENS * 3];
__device__ __half g_Xh[(size_t)TOKENS * EDIM];      // x split hi (fp16)
__device__ __half g_Xl[(size_t)TOKENS * EDIM];      // x split lo, scaled x1024
__device__ __half g_Wf[3ull * EDIM * KDIM];         // W^T single fp16 [z][o][k]
// QKV (m*h, s, d): Q split hi/lo, K/V single fp16
__device__ __half g_Qh[(size_t)TOKENS * EDIM];
__device__ __half g_Ql[(size_t)TOKENS * EDIM];      // unscaled (attention path)
__device__ __half g_Kf[(size_t)TOKENS * EDIM];
__device__ __half g_Vf[(size_t)TOKENS * EDIM];

// ---------------- helpers ----------------
__device__ __forceinline__ uint32_t smem_u32(const void* p) {
    uint32_t a;
    asm("{ .reg .u64 t; cvta.to.shared.u64 t, %1; cvt.u32.u64 %0, t; }" : "=r"(a) : "l"(p));
    return a;
}
__device__ __forceinline__ void cp_async16(uint32_t dst, const void* src) {
    asm volatile("cp.async.cg.shared.global [%0], [%1], 16;" :: "r"(dst), "l"(src) : "memory");
}
__device__ __forceinline__ void cp_commit() {
    asm volatile("cp.async.commit_group;" ::: "memory");
}
__device__ __forceinline__ void cp_wait0() {
    asm volatile("cp.async.wait_group 0;" ::: "memory");
}
__device__ __forceinline__ void cp_wait1() {
    asm volatile("cp.async.wait_group 1;" ::: "memory");
}
__device__ __forceinline__ void ldsm_x4(uint32_t& r0, uint32_t& r1, uint32_t& r2, uint32_t& r3,
                                        uint32_t addr) {
    asm volatile("ldmatrix.sync.aligned.m8n8.x4.shared.b16 {%0,%1,%2,%3}, [%4];"
                 : "=r"(r0), "=r"(r1), "=r"(r2), "=r"(r3) : "r"(addr));
}
__device__ __forceinline__ void ldsm_x4t(uint32_t& r0, uint32_t& r1, uint32_t& r2, uint32_t& r3,
                                         uint32_t addr) {
    asm volatile("ldmatrix.sync.aligned.m8n8.x4.trans.shared.b16 {%0,%1,%2,%3}, [%4];"
                 : "=r"(r0), "=r"(r1), "=r"(r2), "=r"(r3) : "r"(addr));
}
__device__ __forceinline__ void mma_f16(float* d, const uint32_t* a, const uint32_t* b) {
    asm volatile("mma.sync.aligned.m16n8k16.row.col.f32.f16.f16.f32 "
                 "{%0,%1,%2,%3},{%4,%5,%6,%7},{%8,%9},{%0,%1,%2,%3};"
                 : "+f"(d[0]), "+f"(d[1]), "+f"(d[2]), "+f"(d[3])
                 : "r"(a[0]), "r"(a[1]), "r"(a[2]), "r"(a[3]), "r"(b[0]), "r"(b[1]));
}
// fp16-accumulator MMA (expected 2x rate of f32-acc)
__device__ __forceinline__ void mma_f16acc(uint32_t* d, const uint32_t* a, const uint32_t* b) {
    asm volatile("mma.sync.aligned.m16n8k16.row.col.f16.f16.f16.f16 "
                 "{%0,%1},{%2,%3,%4,%5},{%6,%7},{%0,%1};"
                 : "+r"(d[0]), "+r"(d[1])
                 : "r"(a[0]), "r"(a[1]), "r"(a[2]), "r"(a[3]), "r"(b[0]), "r"(b[1]));
}
__device__ __forceinline__ uint32_t pack_f16x2(float a, float b) {
    __half2 h = __float22half2_rn(make_float2(a, b));
    return *(uint32_t*)&h;
}

// ---------------------------------------------------------------------------
// Kernel 1: gates
// ---------------------------------------------------------------------------
__global__ void gates_kernel(const float* __restrict__ x,
                             const float* __restrict__ Wg0, const float* __restrict__ bg0,
                             const float* __restrict__ Wg1, const float* __restrict__ bg1,
                             const float* __restrict__ Wg2, const float* __restrict__ bg2)
{
    __shared__ float xs[EDIM];
    int t = blockIdx.x;
    int tid = threadIdx.x;
    const float4* xrow = (const float4*)(x + (size_t)t * EDIM);
    ((float4*)xs)[tid]       = xrow[tid];
    ((float4*)xs)[tid + 128] = xrow[tid + 128];
    __syncthreads();

    int w = tid >> 5;
    if (w < 3) {
        const float* Wg = (w == 0) ? Wg0 : (w == 1) ? Wg1 : Wg2;
        const float* bg = (w == 0) ? bg0 : (w == 1) ? bg1 : bg2;
        int lane = tid & 31;
        float a0 = 0.f, a1 = 0.f, a2 = 0.f;
        for (int e = lane; e < EDIM; e += 32) {
            float xv = xs[e];
            a0 += xv * Wg[e * 3 + 0];
            a1 += xv * Wg[e * 3 + 1];
            a2 += xv * Wg[e * 3 + 2];
        }
        #pragma unroll
        for (int o = 16; o; o >>= 1) {
            a0 += __shfl_xor_sync(0xffffffffu, a0, o);
            a1 += __shfl_xor_sync(0xffffffffu, a1, o);
            a2 += __shfl_xor_sync(0xffffffffu, a2, o);
        }
        if (lane == 0) {
            a0 += bg[0]; a1 += bg[1]; a2 += bg[2];
            float mx = fmaxf(a0, fmaxf(a1, a2));
            float e0 = __expf(a0 - mx), e1 = __expf(a1 - mx), e2 = __expf(a2 - mx);
            float inv = 1.0f / (e0 + e1 + e2);
            float* gp = g_gate + ((size_t)w * TOKENS + t) * 3;
            gp[0] = e0 * inv; gp[1] = e1 * inv; gp[2] = e2 * inv;
        }
    }
}

// ---------------------------------------------------------------------------
// Kernel 2a: X conversion — split x into fp16 hi/lo; lo scaled x1024
// ---------------------------------------------------------------------------
__global__ void convertX_kernel(const float* __restrict__ x)
{
    size_t i = ((size_t)blockIdx.x * 256 + threadIdx.x) * 4;
    float4 v = *(const float4*)(x + i);
    float vv[4] = {v.x, v.y, v.z, v.w};
    #pragma unroll
    for (int j = 0; j < 4; j++) {
        __half hi = __float2half(vv[j]);
        g_Xh[i + j] = hi;
        g_Xl[i + j] = __float2half((vv[j] - __half2float(hi)) * LOSCALE);
    }
}

// ---------------------------------------------------------------------------
// Kernel 2b: W conversion — transpose to [z][o][k], single fp16.
// ---------------------------------------------------------------------------
__global__ void convertW_kernel(const float* __restrict__ Wq,
                                const float* __restrict__ Wk,
                                const float* __restrict__ Wv)
{
    __shared__ float ts[32][33];
    int zn = blockIdx.z;
    int z = zn / 3, n = zn % 3;
    const float* W = ((z == 0) ? Wq : (z == 1) ? Wk : Wv) + (size_t)n * EDIM * EDIM;
    int e0 = blockIdx.y * 32, o0 = blockIdx.x * 32;
    int tx = threadIdx.x, ty = threadIdx.y;   // (32, 8)
    #pragma unroll
    for (int i = 0; i < 4; i++) {
        int e = e0 + ty + i * 8;
        ts[ty + i * 8][tx] = W[(size_t)e * EDIM + o0 + tx];
    }
    __syncthreads();
    #pragma unroll
    for (int i = 0; i < 4; i++) {
        int o = o0 + ty + i * 8;
        size_t idx = ((size_t)z * EDIM + o) * KDIM + n * EDIM + e0 + tx;
        g_Wf[idx] = __float2half(ts[tx][ty + i * 8]);
    }
}

// ---------------------------------------------------------------------------
// Kernel 3: MoE GEMM. hi-pass f32-acc HMMA, lo-pass f16-acc HMMA (2x rate).
// BM=64 BN=128 BK=64, 3-stage cp.async, 2 CTAs/SM, warp tile 32x32.
// ---------------------------------------------------------------------------
#define GBN 128
#define GP 144                    // row pitch bytes (64 fp16 + 16 pad)
#define AXM2 (64 * GP)            // 9216 per A matrix
#define BXM2 (128 * GP)           // 18432 for B
#define GSTG (2 * AXM2 + BXM2)    // 36864 per stage
#define GNST (KDIM / 64)          // 48
#define SEGST 16                  // stages per gate segment

__global__ void __launch_bounds__(256, 2) moe_gemm_mma(
    const float* __restrict__ bq, const float* __restrict__ bk, const float* __restrict__ bv)
{
    extern __shared__ char smem[];
    const uint32_t sb = smem_u32(smem);
    const int tid = threadIdx.x;
    const int lane = tid & 31, wid = tid >> 5;
    const int warpM = wid >> 2, warpN = wid & 3;   // 2 x 4 warps, 32x32 tiles
    const int z  = blockIdx.z;
    const int n0 = blockIdx.x * GBN;
    const int t0 = blockIdx.y * 64;

    const __half* Xh = g_Xh + (size_t)t0 * EDIM;
    const __half* Xl = g_Xl + (size_t)t0 * EDIM;
    const __half* Wf = g_Wf + ((size_t)z * EDIM + n0) * KDIM;
    const float* gate = g_gate + (size_t)z * TOKENS * 3;

    // loaders: A rows 0..63 (2 chunks each of hi+lo), B rows 0..127 (4 chunks)
    const int ar = tid >> 2;
    const int ac = (tid & 3) * 2;
    const int br = tid >> 1;
    const int bc = (tid & 1) * 4;

    float acc[2][4][4];
    uint32_t acc16[2][4][2];
    #pragma unroll
    for (int mt = 0; mt < 2; mt++)
        #pragma unroll
        for (int nt = 0; nt < 4; nt++) {
            #pragma unroll
            for (int q = 0; q < 4; q++) acc[mt][nt][q] = 0.f;
            acc16[mt][nt][0] = 0u; acc16[mt][nt][1] = 0u;
        }

    #define GEMM_ISSUE(S) do {                                                  \
        int _k0 = (S) * 64;                                                     \
        int _e0 = _k0 & 1023;                                                   \
        uint32_t _st = sb + (uint32_t)((S) % 3) * GSTG;                         \
        _Pragma("unroll")                                                       \
        for (int j = 0; j < 2; j++) {                                           \
            int c = ac + j;                                                     \
            uint32_t d = _st + (uint32_t)ar * GP + c * 16;                      \
            size_t go = (size_t)ar * EDIM + _e0 + c * 8;                        \
            cp_async16(d,        Xh + go);                                      \
            cp_async16(d + AXM2, Xl + go);                                      \
        }                                                                       \
        _Pragma("unroll")                                                       \
        for (int j = 0; j < 4; j++) {                                           \
            int c = bc + j;                                                     \
            uint32_t d = _st + 2 * AXM2 + (uint32_t)br * GP + c * 16;           \
            size_t go = (size_t)br * KDIM + _k0 + c * 8;                        \
            cp_async16(d, Wf + go);                                             \
        }                                                                       \
        cp_commit();                                                            \
    } while (0)

    #define FOLD_LO() do {                                                      \
        _Pragma("unroll")                                                       \
        for (int mt = 0; mt < 2; mt++)                                          \
            _Pragma("unroll")                                                   \
            for (int nt = 0; nt < 4; nt++) {                                    \
                float2 f0 = __half22float2(*(__half2*)&acc16[mt][nt][0]);       \
                float2 f1 = __half22float2(*(__half2*)&acc16[mt][nt][1]);       \
                acc[mt][nt][0] += f0.x * INVLOSCALE;                            \
                acc[mt][nt][1] += f0.y * INVLOSCALE;                            \
                acc[mt][nt][2] += f1.x * INVLOSCALE;                            \
                acc[mt][nt][3] += f1.y * INVLOSCALE;                            \
                acc16[mt][nt][0] = 0u; acc16[mt][nt][1] = 0u;                   \
            }                                                                   \
    } while (0)

    GEMM_ISSUE(0);
    GEMM_ISSUE(1);

    const uint32_t a_off = (uint32_t)(warpM * 32 + (lane & 15)) * GP + ((lane >> 4) << 4);
    const uint32_t b_off = (uint32_t)(warpN * 32 + (lane & 7) + ((lane >> 4) << 3)) * GP
                         + (((lane >> 3) & 1) << 4);

    for (int s = 0; s < GNST; s++) {
        if (s + 1 < GNST) cp_wait1(); else cp_wait0();   // stage s landed
        __syncthreads();
        if (s + 2 < GNST) GEMM_ISSUE(s + 2);
        uint32_t stg = sb + (uint32_t)(s % 3) * GSTG;
        #pragma unroll
        for (int kc = 0; kc < 4; kc++) {
            uint32_t ko = kc * 32;
            uint32_t xh[2][4], xl[2][4];
            #pragma unroll
            for (int mt = 0; mt < 2; mt++) {
                uint32_t ad = stg + a_off + (uint32_t)(mt * 16) * GP + ko;
                ldsm_x4(xh[mt][0], xh[mt][1], xh[mt][2], xh[mt][3], ad);
                ldsm_x4(xl[mt][0], xl[mt][1], xl[mt][2], xl[mt][3], ad + AXM2);
            }
            uint32_t bb[4][2];
            #pragma unroll
            for (int p = 0; p < 2; p++) {
                uint32_t bd = stg + 2 * AXM2 + b_off + (uint32_t)(p * 16) * GP + ko;
                ldsm_x4(bb[2*p][0], bb[2*p][1], bb[2*p+1][0], bb[2*p+1][1], bd);
            }
            #pragma unroll
            for (int mt = 0; mt < 2; mt++)
                #pragma unroll
                for (int nt = 0; nt < 4; nt++)
                    mma_f16(acc[mt][nt], xh[mt], bb[nt]);
            #pragma unroll
            for (int mt = 0; mt < 2; mt++)
                #pragma unroll
                for (int nt = 0; nt < 4; nt++)
                    mma_f16acc(acc16[mt][nt], xl[mt], bb[nt]);
        }
        // Horner gate-segment boundary: fold lo, then acc *= g[n]/g[n+1]
        if (s == SEGST - 1 || s == 2 * SEGST - 1) {
            FOLD_LO();
            int n = (s == SEGST - 1) ? 0 : 1;
            #pragma unroll
            for (int mt = 0; mt < 2; mt++) {
                #pragma unroll
                for (int half = 0; half < 2; half++) {
                    int t = t0 + warpM * 32 + mt * 16 + (lane >> 2) + half * 8;
                    float r = __ldg(&gate[t * 3 + n]) / __ldg(&gate[t * 3 + n + 1]);
                    #pragma unroll
                    for (int nt = 0; nt < 4; nt++) {
                        acc[mt][nt][half * 2 + 0] *= r;
                        acc[mt][nt][half * 2 + 1] *= r;
                    }
                }
            }
        }
    }
    FOLD_LO();

    // epilogue: v = acc*g2 + sum g_i b_i; Q split hi/lo fp16, K/V single fp16
    const float* bias = (z == 0) ? bq : (z == 1) ? bk : bv;
    #pragma unroll
    for (int mt = 0; mt < 2; mt++) {
        #pragma unroll
        for (int half = 0; half < 2; half++) {
            int t = t0 + warpM * 32 + mt * 16 + (lane >> 2) + half * 8;
            float g0 = gate[t * 3 + 0], g1 = gate[t * 3 + 1], g2 = gate[t * 3 + 2];
            int mb = t >> 11, sr = t & 2047;
            #pragma unroll
            for (int nt = 0; nt < 4; nt++) {
                int co = n0 + warpN * 32 + nt * 8 + 2 * (lane & 3);
                float2 b0 = *(const float2*)&bias[co];
                float2 b1 = *(const float2*)&bias[EDIM + co];
                float2 b2 = *(const float2*)&bias[2 * EDIM + co];
                float v0 = acc[mt][nt][half*2+0] * g2 + g0*b0.x + g1*b1.x + g2*b2.x;
                float v1 = acc[mt][nt][half*2+1] * g2 + g0*b0.y + g1*b1.y + g2*b2.y;
                int h = co >> 6, d = co & 63;
                size_t off = (((size_t)mb * NHEAD + h) * SEQ + sr) * HDIM + d;
                if (z == 0) {
                    __half h0 = __float2half(v0);
                    __half h1 = __float2half(v1);
                    __half2 hp; hp.x = h0; hp.y = h1;
                    __half2 lp;
                    lp.x = __float2half(v0 - __half2float(h0));
                    lp.y = __float2half(v1 - __half2float(h1));
                    *(__half2*)&g_Qh[off] = hp;
                    *(__half2*)&g_Ql[off] = lp;
                } else {
                    __half2 hp = __float22half2_rn(make_float2(v0, v1));
                    __half* dst = (z == 1) ? g_Kf : g_Vf;
                    *(__half2*)&dst[off] = hp;
                }
            }
        }
    }
    #undef GEMM_ISSUE
    #undef FOLD_LO
}

// ---------------------------------------------------------------------------
// Kernel 4: flash attention fp16x2, 2-stage KV ring, 3 CTAs/SM (unchanged R8).
// ---------------------------------------------------------------------------
#define AP 144
#define AQMAT (128 * AP)          // 18432 per Q matrix
#define AKMAT (64 * AP)           // 9216 per K/V matrix
#define KVSTG (2 * AKMAT)         // 18432 per stage (K + V)
#define KVOFF (2 * AQMAT)         // 36864

__global__ void __launch_bounds__(128, 3) attn_mma(float* __restrict__ out)
{
    extern __shared__ char smem[];
    const uint32_t su = smem_u32(smem);
    const int tid = threadIdx.x;
    const int lane = tid & 31, wid = tid >> 5;
    const int bh = blockIdx.y;
    const int q0 = blockIdx.x * 128;

    const __half* Qh = g_Qh + ((size_t)bh * SEQ + q0) * HDIM;
    const __half* Ql = g_Ql + ((size_t)bh * SEQ + q0) * HDIM;
    const __half* Kb = g_Kf + (size_t)bh * SEQ * HDIM;
    const __half* Vb = g_Vf + (size_t)bh * SEQ * HDIM;

    const int lr = tid >> 1;          // 0..63
    const int lc = (tid & 1) * 4;

    // stage Q (hi/lo)
    #pragma unroll
    for (int rr = 0; rr < 2; rr++) {
        int r = lr + rr * 64;
        #pragma unroll
        for (int j = 0; j < 4; j++) {
            int c = lc + j;
            uint32_t d = su + (uint32_t)r * AP + c * 16;
            size_t go = (size_t)r * HDIM + c * 8;
            cp_async16(d,         Qh + go);
            cp_async16(d + AQMAT, Ql + go);
        }
    }
    cp_commit();

    #define ATTN_ISSUE(T) do {                                                  \
        uint32_t _st = su + KVOFF + (uint32_t)((T) & 1) * KVSTG;                \
        size_t _gb = (size_t)(T) * 64 * HDIM;                                   \
        _Pragma("unroll")                                                       \
        for (int j = 0; j < 4; j++) {                                           \
            int c = lc + j;                                                     \
            uint32_t d = _st + (uint32_t)lr * AP + c * 16;                      \
            size_t go = _gb + (size_t)lr * HDIM + c * 8;                        \
            cp_async16(d,         Kb + go);                                     \
            cp_async16(d + AKMAT, Vb + go);                                     \
        }                                                                       \
        cp_commit();                                                            \
    } while (0)

    ATTN_ISSUE(0);

    float o_[2][8][4];
    float mrow[2][2], lrow[2][2];
    #pragma unroll
    for (int mt = 0; mt < 2; mt++) {
        #pragma unroll
        for (int nt = 0; nt < 8; nt++)
            #pragma unroll
            for (int q = 0; q < 4; q++) o_[mt][nt][q] = 0.f;
        mrow[mt][0] = -1e30f; mrow[mt][1] = -1e30f;
        lrow[mt][0] = 0.f;    lrow[mt][1] = 0.f;
    }

    const float sc = 0.125f;
    const uint32_t qa_off = (uint32_t)(wid * 32 + (lane & 15)) * AP + ((lane >> 4) << 4);
    const uint32_t kb_off = (uint32_t)((lane & 7) + ((lane >> 4) << 3)) * AP
                          + (((lane >> 3) & 1) << 4);
    const uint32_t vb_off = (uint32_t)((lane & 7) + (((lane >> 3) & 1) << 3)) * AP
                          + ((lane >> 4) << 4);

    const int NT = SEQ / 64;
    for (int t = 0; t < NT; t++) {
        cp_wait0();
        __syncthreads();
        if (t + 1 < NT) ATTN_ISSUE(t + 1);
        uint32_t stg = su + KVOFF + (uint32_t)(t & 1) * KVSTG;

        float s_[2][8][4];
        #pragma unroll
        for (int mt = 0; mt < 2; mt++)
            #pragma unroll
            for (int nt = 0; nt < 8; nt++)
                #pragma unroll
                for (int q = 0; q < 4; q++) s_[mt][nt][q] = 0.f;

        #pragma unroll
        for (int c = 0; c < 4; c++) {
            uint32_t qh[2][4], ql[2][4];
            #pragma unroll
            for (int mt = 0; mt < 2; mt++) {
                uint32_t ad = su + qa_off + (uint32_t)(mt * 16) * AP + c * 32;
                ldsm_x4(qh[mt][0], qh[mt][1], qh[mt][2], qh[mt][3], ad);
                ldsm_x4(ql[mt][0], ql[mt][1], ql[mt][2], ql[mt][3], ad + AQMAT);
            }
            uint32_t kk[8][2];
            #pragma unroll
            for (int p = 0; p < 4; p++) {
                uint32_t bd = stg + kb_off + (uint32_t)(p * 16) * AP + c * 32;
                ldsm_x4(kk[2*p][0], kk[2*p][1], kk[2*p+1][0], kk[2*p+1][1], bd);
            }
            #pragma unroll
            for (int mt = 0; mt < 2; mt++)
                #pragma unroll
                for (int nt = 0; nt < 8; nt++)
                    mma_f16(s_[mt][nt], qh[mt], kk[nt]);
            #pragma unroll
            for (int mt = 0; mt < 2; mt++)
                #pragma unroll
                for (int nt = 0; nt < 8; nt++)
                    mma_f16(s_[mt][nt], ql[mt], kk[nt]);
        }

        uint32_t phi[2][8][2], plo[2][8][2];
        #pragma unroll
        for (int mt = 0; mt < 2; mt++) {
            float r0 = -1e30f, r1 = -1e30f;
            #pragma unroll
            for (int j = 0; j < 8; j++) {
                r0 = fmaxf(r0, fmaxf(s_[mt][j][0], s_[mt][j][1]));
                r1 = fmaxf(r1, fmaxf(s_[mt][j][2], s_[mt][j][3]));
            }
            r0 = fmaxf(r0, __shfl_xor_sync(0xffffffffu, r0, 1));
            r0 = fmaxf(r0, __shfl_xor_sync(0xffffffffu, r0, 2));
            r1 = fmaxf(r1, __shfl_xor_sync(0xffffffffu, r1, 1));
            r1 = fmaxf(r1, __shfl_xor_sync(0xffffffffu, r1, 2));
            float m0 = fmaxf(mrow[mt][0], r0 * sc);
            float m1 = fmaxf(mrow[mt][1], r1 * sc);
            float f0 = __expf(mrow[mt][0] - m0);
            float f1 = __expf(mrow[mt][1] - m1);
            mrow[mt][0] = m0; mrow[mt][1] = m1;
            float s0 = 0.f, s1 = 0.f;
            #pragma unroll
            for (int j = 0; j < 8; j++) {
                float p00 = __expf(__fmaf_rn(s_[mt][j][0], sc, -m0));
                float p01 = __expf(__fmaf_rn(s_[mt][j][1], sc, -m0));
                float p10 = __expf(__fmaf_rn(s_[mt][j][2], sc, -m1));
                float p11 = __expf(__fmaf_rn(s_[mt][j][3], sc, -m1));
                s0 += p00 + p01; s1 += p10 + p11;
                uint32_t h0 = pack_f16x2(p00, p01);
                uint32_t h1 = pack_f16x2(p10, p11);
                phi[mt][j][0] = h0; phi[mt][j][1] = h1;
                float2 hf0 = __half22float2(*(__half2*)&h0);
                float2 hf1 = __half22float2(*(__half2*)&h1);
                plo[mt][j][0] = pack_f16x2(p00 - hf0.x, p01 - hf0.y);
                plo[mt][j][1] = pack_f16x2(p10 - hf1.x, p11 - hf1.y);
            }
            s0 += __shfl_xor_sync(0xffffffffu, s0, 1);
            s0 += __shfl_xor_sync(0xffffffffu, s0, 2);
            s1 += __shfl_xor_sync(0xffffffffu, s1, 1);
            s1 += __shfl_xor_sync(0xffffffffu, s1, 2);
            lrow[mt][0] = lrow[mt][0] * f0 + s0;
            lrow[mt][1] = lrow[mt][1] * f1 + s1;
            #pragma unroll
            for (int j = 0; j < 8; j++) {
                o_[mt][j][0] *= f0; o_[mt][j][1] *= f0;
                o_[mt][j][2] *= f1; o_[mt][j][3] *= f1;
            }
        }

        #pragma unroll
        for (int kc = 0; kc < 4; kc++) {
            uint32_t vv[8][2];
            #pragma unroll
            for (int dj = 0; dj < 4; dj++) {
                uint32_t vd = stg + AKMAT + vb_off
                            + (uint32_t)(kc * 16) * AP + dj * 32;
                ldsm_x4t(vv[2*dj][0], vv[2*dj][1], vv[2*dj+1][0], vv[2*dj+1][1], vd);
            }
            uint32_t pa[2][4], pb[2][4];
            #pragma unroll
            for (int mt = 0; mt < 2; mt++) {
                pa[mt][0] = phi[mt][2*kc][0];   pa[mt][1] = phi[mt][2*kc][1];
                pa[mt][2] = phi[mt][2*kc+1][0]; pa[mt][3] = phi[mt][2*kc+1][1];
                pb[mt][0] = plo[mt][2*kc][0];   pb[mt][1] = plo[mt][2*kc][1];
                pb[mt][2] = plo[mt][2*kc+1][0]; pb[mt][3] = plo[mt][2*kc+1][1];
            }
            #pragma unroll
            for (int mt = 0; mt < 2; mt++)
                #pragma unroll
                for (int nt = 0; nt < 8; nt++)
                    mma_f16(o_[mt][nt], pa[mt], vv[nt]);
            #pragma unroll
            for (int mt = 0; mt < 2; mt++)
                #pragma unroll
                for (int nt = 0; nt < 8; nt++)
                    mma_f16(o_[mt][nt], pb[mt], vv[nt]);
        }
    }

    int m = bh >> 4, h = bh & 15;
    #pragma unroll
    for (int mt = 0; mt < 2; mt++) {
        float inv0 = 1.0f / lrow[mt][0];
        float inv1 = 1.0f / lrow[mt][1];
        int r0 = q0 + wid * 32 + mt * 16 + (lane >> 2);
        int r1 = r0 + 8;
        #pragma unroll
        for (int j = 0; j < 8; j++) {
            int col = h * HDIM + j * 8 + 2 * (lane & 3);
            *(float2*)&out[((size_t)m * SEQ + r0) * EDIM + col] =
                make_float2(o_[mt][j][0] * inv0, o_[mt][j][1] * inv0);
            *(float2*)&out[((size_t)m * SEQ + r1) * EDIM + col] =
                make_float2(o_[mt][j][2] * inv1, o_[mt][j][3] * inv1);
        }
    }
    #undef ATTN_ISSUE
}

// ---------------------------------------------------------------------------
extern "C" void kernel_launch(void* const* d_in, const int* in_sizes, int n_in,
                              void* d_out, int out_size)
{
    (void)in_sizes; (void)n_in; (void)out_size;
    const float* x   = (const float*)d_in[0];
    const float* Wq  = (const float*)d_in[1];
    const float* bq  = (const float*)d_in[2];
    const float* Wgq = (const float*)d_in[3];
    const float* bgq = (const float*)d_in[4];
    const float* Wk  = (const float*)d_in[5];
    const float* bk  = (const float*)d_in[6];
    const float* Wgk = (const float*)d_in[7];
    const float* bgk = (const float*)d_in[8];
    const float* Wv  = (const float*)d_in[9];
    const float* bv  = (const float*)d_in[10];
    const float* Wgv = (const float*)d_in[11];
    const float* bgv = (const float*)d_in[12];
    float* out = (float*)d_out;

    gates_kernel<<<TOKENS, 128>>>(x, Wgq, bgq, Wgk, bgk, Wgv, bgv);
    convertW_kernel<<<dim3(32, 32, 9), dim3(32, 8)>>>(Wq, Wk, Wv);
    convertX_kernel<<<TOKENS * EDIM / 1024, 256>>>(x);

    const int gemm_smem = 3 * GSTG;   // 110592 per CTA, 2 CTAs/SM
    cudaFuncSetAttribute(moe_gemm_mma, cudaFuncAttributeMaxDynamicSharedMemorySize, gemm_smem);
    moe_gemm_mma<<<dim3(EDIM / GBN, TOKENS / 64, 3), 256, gemm_smem>>>(bq, bk, bv);

    const int attn_smem = KVOFF + 2 * KVSTG;  // 73728 per CTA, 3 CTAs/SM
    cudaFuncSetAttribute(attn_mma, cudaFuncAttributeMaxDynamicSharedMemorySize, attn_smem);
    attn_mma<<<dim3(SEQ / 128, MBATCH * NHEAD), 128, attn_smem>>>(out);
}

// round 10
// speedup vs baseline: 5.0234x; 1.6042x over previous
#include <cuda_runtime.h>
#include <cuda_fp16.h>
#include <cstdint>

#define TOKENS 8192
#define EDIM 1024
#define NHEAD 16
#define HDIM 64
#define SEQ 2048
#define MBATCH 4
#define KDIM 3072

// scratch
__device__ float g_gate[3 * TOKENS * 3];
__device__ __half g_Xf[(size_t)TOKENS * EDIM];      // x single fp16
__device__ __half g_Wf[3ull * EDIM * KDIM];         // W^T single fp16 [z][o][k]
// QKV (m*h, s, d) single fp16
__device__ __half g_Qf[(size_t)TOKENS * EDIM];
__device__ __half g_Kf[(size_t)TOKENS * EDIM];
__device__ __half g_Vf[(size_t)TOKENS * EDIM];

// ---------------- helpers ----------------
__device__ __forceinline__ uint32_t smem_u32(const void* p) {
    uint32_t a;
    asm("{ .reg .u64 t; cvta.to.shared.u64 t, %1; cvt.u32.u64 %0, t; }" : "=r"(a) : "l"(p));
    return a;
}
__device__ __forceinline__ void cp_async16(uint32_t dst, const void* src) {
    asm volatile("cp.async.cg.shared.global [%0], [%1], 16;" :: "r"(dst), "l"(src) : "memory");
}
__device__ __forceinline__ void cp_commit() {
    asm volatile("cp.async.commit_group;" ::: "memory");
}
__device__ __forceinline__ void cp_wait0() {
    asm volatile("cp.async.wait_group 0;" ::: "memory");
}
__device__ __forceinline__ void cp_wait1() {
    asm volatile("cp.async.wait_group 1;" ::: "memory");
}
__device__ __forceinline__ void ldsm_x4(uint32_t& r0, uint32_t& r1, uint32_t& r2, uint32_t& r3,
                                        uint32_t addr) {
    asm volatile("ldmatrix.sync.aligned.m8n8.x4.shared.b16 {%0,%1,%2,%3}, [%4];"
                 : "=r"(r0), "=r"(r1), "=r"(r2), "=r"(r3) : "r"(addr));
}
__device__ __forceinline__ void ldsm_x4t(uint32_t& r0, uint32_t& r1, uint32_t& r2, uint32_t& r3,
                                         uint32_t addr) {
    asm volatile("ldmatrix.sync.aligned.m8n8.x4.trans.shared.b16 {%0,%1,%2,%3}, [%4];"
                 : "=r"(r0), "=r"(r1), "=r"(r2), "=r"(r3) : "r"(addr));
}
__device__ __forceinline__ void mma_f16(float* d, const uint32_t* a, const uint32_t* b) {
    asm volatile("mma.sync.aligned.m16n8k16.row.col.f32.f16.f16.f32 "
                 "{%0,%1,%2,%3},{%4,%5,%6,%7},{%8,%9},{%0,%1,%2,%3};"
                 : "+f"(d[0]), "+f"(d[1]), "+f"(d[2]), "+f"(d[3])
                 : "r"(a[0]), "r"(a[1]), "r"(a[2]), "r"(a[3]), "r"(b[0]), "r"(b[1]));
}
__device__ __forceinline__ uint32_t pack_f16x2(float a, float b) {
    __half2 h = __float22half2_rn(make_float2(a, b));
    return *(uint32_t*)&h;
}

// ---------------------------------------------------------------------------
// Kernel 1: gates
// ---------------------------------------------------------------------------
__global__ void gates_kernel(const float* __restrict__ x,
                             const float* __restrict__ Wg0, const float* __restrict__ bg0,
                             const float* __restrict__ Wg1, const float* __restrict__ bg1,
                             const float* __restrict__ Wg2, const float* __restrict__ bg2)
{
    __shared__ float xs[EDIM];
    int t = blockIdx.x;
    int tid = threadIdx.x;
    const float4* xrow = (const float4*)(x + (size_t)t * EDIM);
    ((float4*)xs)[tid]       = xrow[tid];
    ((float4*)xs)[tid + 128] = xrow[tid + 128];
    __syncthreads();

    int w = tid >> 5;
    if (w < 3) {
        const float* Wg = (w == 0) ? Wg0 : (w == 1) ? Wg1 : Wg2;
        const float* bg = (w == 0) ? bg0 : (w == 1) ? bg1 : bg2;
        int lane = tid & 31;
        float a0 = 0.f, a1 = 0.f, a2 = 0.f;
        for (int e = lane; e < EDIM; e += 32) {
            float xv = xs[e];
            a0 += xv * Wg[e * 3 + 0];
            a1 += xv * Wg[e * 3 + 1];
            a2 += xv * Wg[e * 3 + 2];
        }
        #pragma unroll
        for (int o = 16; o; o >>= 1) {
            a0 += __shfl_xor_sync(0xffffffffu, a0, o);
            a1 += __shfl_xor_sync(0xffffffffu, a1, o);
            a2 += __shfl_xor_sync(0xffffffffu, a2, o);
        }
        if (lane == 0) {
            a0 += bg[0]; a1 += bg[1]; a2 += bg[2];
            float mx = fmaxf(a0, fmaxf(a1, a2));
            float e0 = __expf(a0 - mx), e1 = __expf(a1 - mx), e2 = __expf(a2 - mx);
            float inv = 1.0f / (e0 + e1 + e2);
            float* gp = g_gate + ((size_t)w * TOKENS + t) * 3;
            gp[0] = e0 * inv; gp[1] = e1 * inv; gp[2] = e2 * inv;
        }
    }
}

// ---------------------------------------------------------------------------
// Kernel 2a: X conversion — single fp16
// ---------------------------------------------------------------------------
__global__ void convertX_kernel(const float* __restrict__ x)
{
    size_t i = ((size_t)blockIdx.x * 256 + threadIdx.x) * 4;
    float4 v = *(const float4*)(x + i);
    __half2 h0 = __float22half2_rn(make_float2(v.x, v.y));
    __half2 h1 = __float22half2_rn(make_float2(v.z, v.w));
    *(__half2*)&g_Xf[i]     = h0;
    *(__half2*)&g_Xf[i + 2] = h1;
}

// ---------------------------------------------------------------------------
// Kernel 2b: W conversion — transpose to [z][o][k], single fp16.
// ---------------------------------------------------------------------------
__global__ void convertW_kernel(const float* __restrict__ Wq,
                                const float* __restrict__ Wk,
                                const float* __restrict__ Wv)
{
    __shared__ float ts[32][33];
    int zn = blockIdx.z;
    int z = zn / 3, n = zn % 3;
    const float* W = ((z == 0) ? Wq : (z == 1) ? Wk : Wv) + (size_t)n * EDIM * EDIM;
    int e0 = blockIdx.y * 32, o0 = blockIdx.x * 32;
    int tx = threadIdx.x, ty = threadIdx.y;   // (32, 8)
    #pragma unroll
    for (int i = 0; i < 4; i++) {
        int e = e0 + ty + i * 8;
        ts[ty + i * 8][tx] = W[(size_t)e * EDIM + o0 + tx];
    }
    __syncthreads();
    #pragma unroll
    for (int i = 0; i < 4; i++) {
        int o = o0 + ty + i * 8;
        size_t idx = ((size_t)z * EDIM + o) * KDIM + n * EDIM + e0 + tx;
        g_Wf[idx] = __float2half(ts[tx][ty + i * 8]);
    }
}

// ---------------------------------------------------------------------------
// Kernel 3: fp16 single-pass MoE GEMM, BM=128 BN=128 BK=64, 3-stage,
// 2 CTAs/SM, 8 warps (2x4), warp tile 64x32. Horner gate factorization.
// ---------------------------------------------------------------------------
#define GBN 128
#define GP 144                    // row pitch bytes (64 fp16 + 16 pad)
#define AXM (128 * GP)            // 18432 per matrix (A or B)
#define GSTG (2 * AXM)            // 36864 per stage
#define GNST (KDIM / 64)          // 48
#define SEGST 16                  // stages per gate segment

__global__ void __launch_bounds__(256, 2) moe_gemm_mma(
    const float* __restrict__ bq, const float* __restrict__ bk, const float* __restrict__ bv)
{
    extern __shared__ char smem[];
    const uint32_t sb = smem_u32(smem);
    const int tid = threadIdx.x;
    const int lane = tid & 31, wid = tid >> 5;
    const int warpM = wid >> 2, warpN = wid & 3;   // 2x4 warps, 64x32 tiles
    const int z  = blockIdx.z;
    const int n0 = blockIdx.x * GBN;
    const int t0 = blockIdx.y * 128;

    const __half* Xf = g_Xf + (size_t)t0 * EDIM;
    const __half* Wf = g_Wf + ((size_t)z * EDIM + n0) * KDIM;
    const float* gate = g_gate + (size_t)z * TOKENS * 3;

    const int lr = tid >> 1;          // 0..127
    const int lc = (tid & 1) * 4;     // chunk base 0 or 4

    float acc[4][4][4];
    #pragma unroll
    for (int mt = 0; mt < 4; mt++)
        #pragma unroll
        for (int nt = 0; nt < 4; nt++)
            #pragma unroll
            for (int q = 0; q < 4; q++) acc[mt][nt][q] = 0.f;

    #define GEMM_ISSUE(S) do {                                                  \
        int _k0 = (S) * 64;                                                     \
        int _e0 = _k0 & 1023;                                                   \
        uint32_t _st = sb + (uint32_t)((S) % 3) * GSTG;                         \
        _Pragma("unroll")                                                       \
        for (int j = 0; j < 4; j++) {                                           \
            int c = lc + j;                                                     \
            uint32_t d = _st + (uint32_t)lr * GP + c * 16;                      \
            size_t goA = (size_t)lr * EDIM + _e0 + c * 8;                       \
            size_t goB = (size_t)lr * KDIM + _k0 + c * 8;                       \
            cp_async16(d,       Xf + goA);                                      \
            cp_async16(d + AXM, Wf + goB);                                      \
        }                                                                       \
        cp_commit();                                                            \
    } while (0)

    GEMM_ISSUE(0);
    GEMM_ISSUE(1);

    const uint32_t a_off = (uint32_t)(warpM * 64 + (lane & 15)) * GP + ((lane >> 4) << 4);
    const uint32_t b_off = (uint32_t)(warpN * 32 + (lane & 7) + ((lane >> 4) << 3)) * GP
                         + (((lane >> 3) & 1) << 4);

    for (int s = 0; s < GNST; s++) {
        if (s + 1 < GNST) cp_wait1(); else cp_wait0();   // stage s landed
        __syncthreads();
        if (s + 2 < GNST) GEMM_ISSUE(s + 2);
        uint32_t stg = sb + (uint32_t)(s % 3) * GSTG;
        #pragma unroll
        for (int kc = 0; kc < 4; kc++) {
            uint32_t ko = kc * 32;
            uint32_t xa[4][4];
            #pragma unroll
            for (int mt = 0; mt < 4; mt++) {
                uint32_t ad = stg + a_off + (uint32_t)(mt * 16) * GP + ko;
                ldsm_x4(xa[mt][0], xa[mt][1], xa[mt][2], xa[mt][3], ad);
            }
            uint32_t bb[4][2];
            #pragma unroll
            for (int p = 0; p < 2; p++) {
                uint32_t bd = stg + AXM + b_off + (uint32_t)(p * 16) * GP + ko;
                ldsm_x4(bb[2*p][0], bb[2*p][1], bb[2*p+1][0], bb[2*p+1][1], bd);
            }
            #pragma unroll
            for (int mt = 0; mt < 4; mt++)
                #pragma unroll
                for (int nt = 0; nt < 4; nt++)
                    mma_f16(acc[mt][nt], xa[mt], bb[nt]);
        }
        // Horner gate-segment boundary: acc *= g[n]/g[n+1]
        if (s == SEGST - 1 || s == 2 * SEGST - 1) {
            int n = (s == SEGST - 1) ? 0 : 1;
            #pragma unroll
            for (int mt = 0; mt < 4; mt++) {
                #pragma unroll
                for (int half = 0; half < 2; half++) {
                    int t = t0 + warpM * 64 + mt * 16 + (lane >> 2) + half * 8;
                    float r = __ldg(&gate[t * 3 + n]) / __ldg(&gate[t * 3 + n + 1]);
                    #pragma unroll
                    for (int nt = 0; nt < 4; nt++) {
                        acc[mt][nt][half * 2 + 0] *= r;
                        acc[mt][nt][half * 2 + 1] *= r;
                    }
                }
            }
        }
    }

    // epilogue: v = acc*g2 + sum g_i b_i; QKV single fp16, scatter (m,h,s,d)
    const float* bias = (z == 0) ? bq : (z == 1) ? bk : bv;
    __half* dst = (z == 0) ? g_Qf : (z == 1) ? g_Kf : g_Vf;
    #pragma unroll
    for (int mt = 0; mt < 4; mt++) {
        #pragma unroll
        for (int half = 0; half < 2; half++) {
            int t = t0 + warpM * 64 + mt * 16 + (lane >> 2) + half * 8;
            float g0 = gate[t * 3 + 0], g1 = gate[t * 3 + 1], g2 = gate[t * 3 + 2];
            int mb = t >> 11, sr = t & 2047;
            #pragma unroll
            for (int nt = 0; nt < 4; nt++) {
                int co = n0 + warpN * 32 + nt * 8 + 2 * (lane & 3);
                float2 b0 = *(const float2*)&bias[co];
                float2 b1 = *(const float2*)&bias[EDIM + co];
                float2 b2 = *(const float2*)&bias[2 * EDIM + co];
                float v0 = acc[mt][nt][half*2+0] * g2 + g0*b0.x + g1*b1.x + g2*b2.x;
                float v1 = acc[mt][nt][half*2+1] * g2 + g0*b0.y + g1*b1.y + g2*b2.y;
                int h = co >> 6, d = co & 63;
                size_t off = (((size_t)mb * NHEAD + h) * SEQ + sr) * HDIM + d;
                *(__half2*)&dst[off] = __float22half2_rn(make_float2(v0, v1));
            }
        }
    }
    #undef GEMM_ISSUE
}

// ---------------------------------------------------------------------------
// Kernel 4: flash attention, single fp16 QK and PV, 2-stage KV ring, 3 CTA/SM.
// ---------------------------------------------------------------------------
#define AP 144
#define AQMAT (128 * AP)          // 18432 Q matrix
#define AKMAT (64 * AP)           // 9216 per K/V matrix
#define KVSTG (2 * AKMAT)         // 18432 per stage (K + V)
#define KVOFF AQMAT               // 18432

__global__ void __launch_bounds__(128, 3) attn_mma(float* __restrict__ out)
{
    extern __shared__ char smem[];
    const uint32_t su = smem_u32(smem);
    const int tid = threadIdx.x;
    const int lane = tid & 31, wid = tid >> 5;
    const int bh = blockIdx.y;
    const int q0 = blockIdx.x * 128;

    const __half* Qf = g_Qf + ((size_t)bh * SEQ + q0) * HDIM;
    const __half* Kb = g_Kf + (size_t)bh * SEQ * HDIM;
    const __half* Vb = g_Vf + (size_t)bh * SEQ * HDIM;

    const int lr = tid >> 1;          // 0..63
    const int lc = (tid & 1) * 4;

    // stage Q
    #pragma unroll
    for (int rr = 0; rr < 2; rr++) {
        int r = lr + rr * 64;
        #pragma unroll
        for (int j = 0; j < 4; j++) {
            int c = lc + j;
            cp_async16(su + (uint32_t)r * AP + c * 16, Qf + (size_t)r * HDIM + c * 8);
        }
    }
    cp_commit();

    #define ATTN_ISSUE(T) do {                                                  \
        uint32_t _st = su + KVOFF + (uint32_t)((T) & 1) * KVSTG;                \
        size_t _gb = (size_t)(T) * 64 * HDIM;                                   \
        _Pragma("unroll")                                                       \
        for (int j = 0; j < 4; j++) {                                           \
            int c = lc + j;                                                     \
            uint32_t d = _st + (uint32_t)lr * AP + c * 16;                      \
            size_t go = _gb + (size_t)lr * HDIM + c * 8;                        \
            cp_async16(d,         Kb + go);                                     \
            cp_async16(d + AKMAT, Vb + go);                                     \
        }                                                                       \
        cp_commit();                                                            \
    } while (0)

    ATTN_ISSUE(0);

    float o_[2][8][4];
    float mrow[2][2], lrow[2][2];
    #pragma unroll
    for (int mt = 0; mt < 2; mt++) {
        #pragma unroll
        for (int nt = 0; nt < 8; nt++)
            #pragma unroll
            for (int q = 0; q < 4; q++) o_[mt][nt][q] = 0.f;
        mrow[mt][0] = -1e30f; mrow[mt][1] = -1e30f;
        lrow[mt][0] = 0.f;    lrow[mt][1] = 0.f;
    }

    const float sc = 0.125f;
    const uint32_t qa_off = (uint32_t)(wid * 32 + (lane & 15)) * AP + ((lane >> 4) << 4);
    const uint32_t kb_off = (uint32_t)((lane & 7) + ((lane >> 4) << 3)) * AP
                          + (((lane >> 3) & 1) << 4);
    const uint32_t vb_off = (uint32_t)((lane & 7) + (((lane >> 3) & 1) << 3)) * AP
                          + ((lane >> 4) << 4);

    const int NT = SEQ / 64;
    for (int t = 0; t < NT; t++) {
        cp_wait0();
        __syncthreads();
        if (t + 1 < NT) ATTN_ISSUE(t + 1);
        uint32_t stg = su + KVOFF + (uint32_t)(t & 1) * KVSTG;

        // S = q * k (single pass)
        float s_[2][8][4];
        #pragma unroll
        for (int mt = 0; mt < 2; mt++)
            #pragma unroll
            for (int nt = 0; nt < 8; nt++)
                #pragma unroll
                for (int q = 0; q < 4; q++) s_[mt][nt][q] = 0.f;

        #pragma unroll
        for (int c = 0; c < 4; c++) {
            uint32_t qq[2][4];
            #pragma unroll
            for (int mt = 0; mt < 2; mt++) {
                uint32_t ad = su + qa_off + (uint32_t)(mt * 16) * AP + c * 32;
                ldsm_x4(qq[mt][0], qq[mt][1], qq[mt][2], qq[mt][3], ad);
            }
            uint32_t kk[8][2];
            #pragma unroll
            for (int p = 0; p < 4; p++) {
                uint32_t bd = stg + kb_off + (uint32_t)(p * 16) * AP + c * 32;
                ldsm_x4(kk[2*p][0], kk[2*p][1], kk[2*p+1][0], kk[2*p+1][1], bd);
            }
            #pragma unroll
            for (int mt = 0; mt < 2; mt++)
                #pragma unroll
                for (int nt = 0; nt < 8; nt++)
                    mma_f16(s_[mt][nt], qq[mt], kk[nt]);
        }

        // online softmax + pack P fp16
        uint32_t phi[2][8][2];
        #pragma unroll
        for (int mt = 0; mt < 2; mt++) {
            float r0 = -1e30f, r1 = -1e30f;
            #pragma unroll
            for (int j = 0; j < 8; j++) {
                r0 = fmaxf(r0, fmaxf(s_[mt][j][0], s_[mt][j][1]));
                r1 = fmaxf(r1, fmaxf(s_[mt][j][2], s_[mt][j][3]));
            }
            r0 = fmaxf(r0, __shfl_xor_sync(0xffffffffu, r0, 1));
            r0 = fmaxf(r0, __shfl_xor_sync(0xffffffffu, r0, 2));
            r1 = fmaxf(r1, __shfl_xor_sync(0xffffffffu, r1, 1));
            r1 = fmaxf(r1, __shfl_xor_sync(0xffffffffu, r1, 2));
            float m0 = fmaxf(mrow[mt][0], r0 * sc);
            float m1 = fmaxf(mrow[mt][1], r1 * sc);
            float f0 = __expf(mrow[mt][0] - m0);
            float f1 = __expf(mrow[mt][1] - m1);
            mrow[mt][0] = m0; mrow[mt][1] = m1;
            float s0 = 0.f, s1 = 0.f;
            #pragma unroll
            for (int j = 0; j < 8; j++) {
                float p00 = __expf(__fmaf_rn(s_[mt][j][0], sc, -m0));
                float p01 = __expf(__fmaf_rn(s_[mt][j][1], sc, -m0));
                float p10 = __expf(__fmaf_rn(s_[mt][j][2], sc, -m1));
                float p11 = __expf(__fmaf_rn(s_[mt][j][3], sc, -m1));
                s0 += p00 + p01; s1 += p10 + p11;
                phi[mt][j][0] = pack_f16x2(p00, p01);
                phi[mt][j][1] = pack_f16x2(p10, p11);
            }
            s0 += __shfl_xor_sync(0xffffffffu, s0, 1);
            s0 += __shfl_xor_sync(0xffffffffu, s0, 2);
            s1 += __shfl_xor_sync(0xffffffffu, s1, 1);
            s1 += __shfl_xor_sync(0xffffffffu, s1, 2);
            lrow[mt][0] = lrow[mt][0] * f0 + s0;
            lrow[mt][1] = lrow[mt][1] * f1 + s1;
            #pragma unroll
            for (int j = 0; j < 8; j++) {
                o_[mt][j][0] *= f0; o_[mt][j][1] *= f0;
                o_[mt][j][2] *= f1; o_[mt][j][3] *= f1;
            }
        }

        // O += p * v (single pass)
        #pragma unroll
        for (int kc = 0; kc < 4; kc++) {
            uint32_t vv[8][2];
            #pragma unroll
            for (int dj = 0; dj < 4; dj++) {
                uint32_t vd = stg + AKMAT + vb_off
                            + (uint32_t)(kc * 16) * AP + dj * 32;
                ldsm_x4t(vv[2*dj][0], vv[2*dj][1], vv[2*dj+1][0], vv[2*dj+1][1], vd);
            }
            uint32_t pa[2][4];
            #pragma unroll
            for (int mt = 0; mt < 2; mt++) {
                pa[mt][0] = phi[mt][2*kc][0];   pa[mt][1] = phi[mt][2*kc][1];
                pa[mt][2] = phi[mt][2*kc+1][0]; pa[mt][3] = phi[mt][2*kc+1][1];
            }
            #pragma unroll
            for (int mt = 0; mt < 2; mt++)
                #pragma unroll
                for (int nt = 0; nt < 8; nt++)
                    mma_f16(o_[mt][nt], pa[mt], vv[nt]);
        }
    }

    int m = bh >> 4, h = bh & 15;
    #pragma unroll
    for (int mt = 0; mt < 2; mt++) {
        float inv0 = 1.0f / lrow[mt][0];
        float inv1 = 1.0f / lrow[mt][1];
        int r0 = q0 + wid * 32 + mt * 16 + (lane >> 2);
        int r1 = r0 + 8;
        #pragma unroll
        for (int j = 0; j < 8; j++) {
            int col = h * HDIM + j * 8 + 2 * (lane & 3);
            *(float2*)&out[((size_t)m * SEQ + r0) * EDIM + col] =
                make_float2(o_[mt][j][0] * inv0, o_[mt][j][1] * inv0);
            *(float2*)&out[((size_t)m * SEQ + r1) * EDIM + col] =
                make_float2(o_[mt][j][2] * inv1, o_[mt][j][3] * inv1);
        }
    }
    #undef ATTN_ISSUE
}

// ---------------------------------------------------------------------------
extern "C" void kernel_launch(void* const* d_in, const int* in_sizes, int n_in,
                              void* d_out, int out_size)
{
    (void)in_sizes; (void)n_in; (void)out_size;
    const float* x   = (const float*)d_in[0];
    const float* Wq  = (const float*)d_in[1];
    const float* bq  = (const float*)d_in[2];
    const float* Wgq = (const float*)d_in[3];
    const float* bgq = (const float*)d_in[4];
    const float* Wk  = (const float*)d_in[5];
    const float* bk  = (const float*)d_in[6];
    const float* Wgk = (const float*)d_in[7];
    const float* bgk = (const float*)d_in[8];
    const float* Wv  = (const float*)d_in[9];
    const float* bv  = (const float*)d_in[10];
    const float* Wgv = (const float*)d_in[11];
    const float* bgv = (const float*)d_in[12];
    float* out = (float*)d_out;

    gates_kernel<<<TOKENS, 128>>>(x, Wgq, bgq, Wgk, bgk, Wgv, bgv);
    convertW_kernel<<<dim3(32, 32, 9), dim3(32, 8)>>>(Wq, Wk, Wv);
    convertX_kernel<<<TOKENS * EDIM / 1024, 256>>>(x);

    const int gemm_smem = 3 * GSTG;   // 110592 per CTA, 2 CTAs/SM
    cudaFuncSetAttribute(moe_gemm_mma, cudaFuncAttributeMaxDynamicSharedMemorySize, gemm_smem);
    moe_gemm_mma<<<dim3(EDIM / GBN, TOKENS / 128, 3), 256, gemm_smem>>>(bq, bk, bv);

    const int attn_smem = KVOFF + 2 * KVSTG;  // 55296 per CTA, 3 CTAs/SM
    cudaFuncSetAttribute(attn_mma, cudaFuncAttributeMaxDynamicSharedMemorySize, attn_smem);
    attn_mma<<<dim3(SEQ / 128, MBATCH * NHEAD), 128, attn_smem>>>(out);
}